// round 1
// baseline (speedup 1.0000x reference)
#include <cuda_runtime.h>

#define N_NODES 4096
#define HDIM    128
#define N_EDGES 131072

// ---------------- scratch (static device arrays; no allocation) ----------------
__device__ float g_t[N_NODES * 256];     // RHS buffer (ld up to 256 for concat pass)
__device__ float g_t2[N_NODES * 128];
__device__ float g_h1[N_NODES * 128];
__device__ float g_h2[N_NODES * 128];
__device__ float g_h3c1[N_NODES * 128];
__device__ float g_a1[N_NODES * 128];
__device__ float g_a3[N_NODES * 128];
__device__ float g_m1[N_NODES * 128];
__device__ float g_m3[N_NODES * 128];
__device__ float g_qkv0[N_NODES * 384];
__device__ float g_qkv1[N_NODES * 384];
__device__ float g_om[N_NODES * 128];
__device__ float g_hmix[N_NODES * 128];
__device__ float g_h2m[N_NODES * 128];
__device__ float g_h3c2[N_NODES * 128];
__device__ float g_h3[N_NODES * 128];

// ---------------------------------------------------------------------------
// Generic tiled GEMM: C[M, 128] = epilogue( A[M,K] @ B[K, 128(+off)] )
// BM=32, BN=128, BK=32; 128 threads; per-thread 4x8 register tile.
// modes:
//  0: C = relu(z)
//  1: C = relu(z + res)
//  2: dual (grid.y=2): y==0 -> C = relu(z + res); y==1 -> C2 = z   (B has ldb=256)
//  3: C = z
//  4: C = relu(z + res) * (*scale_p)
//  5: C[row*ldc + coffc + col] = z + bias[col]     (small feature GEMMs)
// ---------------------------------------------------------------------------
__global__ __launch_bounds__(128, 1) void gemm_tiled(
    const float* __restrict__ A, int lda,
    const float* __restrict__ B, int ldb,
    int K,
    float* __restrict__ C, float* __restrict__ C2,
    const float* __restrict__ res,
    const float* __restrict__ bias,
    const float* __restrict__ scale_p,
    int ldc, int coffc, int mode)
{
    __shared__ float As[32 * 33];   // As[k*33 + m], padded: conflict-free
    __shared__ float Bs[32 * 128];  // Bs[k*128 + n]

    const int t  = threadIdx.x;
    const int m0 = blockIdx.x * 32;
    const int yb = blockIdx.y;
    const int boff = yb * 128;
    const int tr = t >> 4;          // 0..7  -> rows tr*4 .. tr*4+3
    const int tc = t & 15;          // 0..15 -> cols tc*8 .. tc*8+7

    const int am = t >> 2;          // 0..31 (A staging row)
    const int ak = (t & 3) * 8;     // A staging k-offset

    float acc[4][8];
#pragma unroll
    for (int r = 0; r < 4; r++)
#pragma unroll
        for (int c = 0; c < 8; c++) acc[r][c] = 0.0f;

    const float* Ap = A + (size_t)(m0 + am) * lda + ak;

    float4 a0, a1, bb[8];

    // prologue: load tile 0
    a0 = *(const float4*)(Ap);
    a1 = *(const float4*)(Ap + 4);
#pragma unroll
    for (int j = 0; j < 8; j++) {
        int f = t + j * 128;
        int kr = f >> 5, c4 = f & 31;
        bb[j] = *(const float4*)(B + (size_t)kr * ldb + boff + c4 * 4);
    }
    As[(ak + 0) * 33 + am] = a0.x; As[(ak + 1) * 33 + am] = a0.y;
    As[(ak + 2) * 33 + am] = a0.z; As[(ak + 3) * 33 + am] = a0.w;
    As[(ak + 4) * 33 + am] = a1.x; As[(ak + 5) * 33 + am] = a1.y;
    As[(ak + 6) * 33 + am] = a1.z; As[(ak + 7) * 33 + am] = a1.w;
#pragma unroll
    for (int j = 0; j < 8; j++) {
        int f = t + j * 128;
        int kr = f >> 5, c4 = f & 31;
        *(float4*)&Bs[kr * 128 + c4 * 4] = bb[j];
    }
    __syncthreads();

    const int nIt = K >> 5;
    for (int it = 1; it <= nIt; ++it) {
        if (it < nIt) {
            int k0 = it << 5;
            a0 = *(const float4*)(Ap + k0);
            a1 = *(const float4*)(Ap + k0 + 4);
#pragma unroll
            for (int j = 0; j < 8; j++) {
                int f = t + j * 128;
                int kr = f >> 5, c4 = f & 31;
                bb[j] = *(const float4*)(B + (size_t)(k0 + kr) * ldb + boff + c4 * 4);
            }
        }
#pragma unroll
        for (int k = 0; k < 32; ++k) {
            float av[4];
#pragma unroll
            for (int r = 0; r < 4; r++) av[r] = As[k * 33 + tr * 4 + r];
            float4 b0 = *(const float4*)&Bs[k * 128 + tc * 8];
            float4 b1 = *(const float4*)&Bs[k * 128 + tc * 8 + 4];
            float bv[8] = {b0.x, b0.y, b0.z, b0.w, b1.x, b1.y, b1.z, b1.w};
#pragma unroll
            for (int r = 0; r < 4; r++)
#pragma unroll
                for (int c = 0; c < 8; c++) acc[r][c] += av[r] * bv[c];
        }
        __syncthreads();
        if (it < nIt) {
            As[(ak + 0) * 33 + am] = a0.x; As[(ak + 1) * 33 + am] = a0.y;
            As[(ak + 2) * 33 + am] = a0.z; As[(ak + 3) * 33 + am] = a0.w;
            As[(ak + 4) * 33 + am] = a1.x; As[(ak + 5) * 33 + am] = a1.y;
            As[(ak + 6) * 33 + am] = a1.z; As[(ak + 7) * 33 + am] = a1.w;
#pragma unroll
            for (int j = 0; j < 8; j++) {
                int f = t + j * 128;
                int kr = f >> 5, c4 = f & 31;
                *(float4*)&Bs[kr * 128 + c4 * 4] = bb[j];
            }
            __syncthreads();
        }
    }

    const float sc = (mode == 4) ? *scale_p : 0.0f;

#pragma unroll
    for (int r = 0; r < 4; r++) {
        int row = m0 + tr * 4 + r;
#pragma unroll
        for (int c = 0; c < 8; c++) {
            int col = tc * 8 + c;
            float z = acc[r][c];
            int o = row * 128 + col;
            if (mode == 0) {
                C[o] = fmaxf(z, 0.0f);
            } else if (mode == 1) {
                C[o] = fmaxf(z + res[o], 0.0f);
            } else if (mode == 2) {
                if (yb == 0) C[o] = fmaxf(z + res[o], 0.0f);
                else         C2[o] = z;
            } else if (mode == 3) {
                C[o] = z;
            } else if (mode == 4) {
                C[o] = fmaxf(z + res[o], 0.0f) * sc;
            } else {
                C[(size_t)row * ldc + coffc + col] = z + bias[col];
            }
        }
    }
}

// ---------------------------------------------------------------------------
// NT GEMM: C[M, No] = A[M,128] @ W[No,128]^T + bias   (K = 128 fixed)
// Tile 32x32, 256 threads, 2x2 per thread. Optional duplicate write C2.
// ---------------------------------------------------------------------------
__global__ __launch_bounds__(256) void gemm_nt(
    const float* __restrict__ A, const float* __restrict__ W,
    const float* __restrict__ bias, float* __restrict__ C,
    float* __restrict__ C2, int No)
{
    __shared__ float As[32 * 129];
    __shared__ float Ws[32 * 129];
    const int t = threadIdx.x;
    const int m0 = blockIdx.x * 32, n0 = blockIdx.y * 32;

    for (int i = t; i < 32 * 128; i += 256) {
        int r = i >> 7, k = i & 127;
        As[r * 129 + k] = A[(m0 + r) * 128 + k];
        Ws[r * 129 + k] = W[(n0 + r) * 128 + k];
    }
    __syncthreads();

    const int tr = t >> 4, tc = t & 15;
    const float* a0p = &As[(tr * 2) * 129];
    const float* a1p = &As[(tr * 2 + 1) * 129];
    const float* w0p = &Ws[(tc * 2) * 129];
    const float* w1p = &Ws[(tc * 2 + 1) * 129];

    float acc00 = 0, acc01 = 0, acc10 = 0, acc11 = 0;
#pragma unroll 16
    for (int k = 0; k < 128; k++) {
        float a0 = a0p[k], a1 = a1p[k], w0 = w0p[k], w1 = w1p[k];
        acc00 += a0 * w0; acc01 += a0 * w1;
        acc10 += a1 * w0; acc11 += a1 * w1;
    }
    int row0 = m0 + tr * 2, col0 = n0 + tc * 2;
    float v00 = acc00 + bias[col0], v01 = acc01 + bias[col0 + 1];
    float v10 = acc10 + bias[col0], v11 = acc11 + bias[col0 + 1];
    C[(size_t)row0 * No + col0]           = v00;
    C[(size_t)row0 * No + col0 + 1]       = v01;
    C[(size_t)(row0 + 1) * No + col0]     = v10;
    C[(size_t)(row0 + 1) * No + col0 + 1] = v11;
    if (C2) {
        C2[(size_t)row0 * No + col0]           = v00;
        C2[(size_t)row0 * No + col0 + 1]       = v01;
        C2[(size_t)(row0 + 1) * No + col0]     = v10;
        C2[(size_t)(row0 + 1) * No + col0 + 1] = v11;
    }
}

// ---------------------------------------------------------------------------
// Mixup: m = lam*a + (1-lam)*a[perm]   for a1->m1 and a3->m3. One warp slot = 1 float4.
// ---------------------------------------------------------------------------
__global__ void mix_kernel(const float* __restrict__ a1, const float* __restrict__ a3,
                           const int* __restrict__ perm, const float* __restrict__ lam,
                           float* __restrict__ m1, float* __restrict__ m3)
{
    int i = blockIdx.x * blockDim.x + threadIdx.x;   // over N_NODES*32 float4 slots
    int row = i >> 5, q = i & 31;
    float l = lam[0], il = 1.0f - l;
    int pr = perm[row];
    float4 x = ((const float4*)a1)[row * 32 + q];
    float4 y = ((const float4*)a1)[pr * 32 + q];
    float4 o;
    o.x = l * x.x + il * y.x; o.y = l * x.y + il * y.y;
    o.z = l * x.z + il * y.z; o.w = l * x.w + il * y.w;
    ((float4*)m1)[row * 32 + q] = o;
    x = ((const float4*)a3)[row * 32 + q];
    y = ((const float4*)a3)[pr * 32 + q];
    o.x = l * x.x + il * y.x; o.y = l * x.y + il * y.y;
    o.z = l * x.z + il * y.z; o.w = l * x.w + il * y.w;
    ((float4*)m3)[row * 32 + q] = o;
}

// ---------------------------------------------------------------------------
// Per-node L=2 multi-head attention + mean over L.
// qkv0/qkv1: [N,384] (= q|k|v for L=0 / L=1). One warp per node; lane owns 4 dims.
// o_mean = 0.5*((a00+a10)*v0 + (a01+a11)*v1) per head.
// ---------------------------------------------------------------------------
__global__ void attn_kernel(const float* __restrict__ qkv0, const float* __restrict__ qkv1,
                            float* __restrict__ om, int nh)
{
    int gt = blockIdx.x * blockDim.x + threadIdx.x;
    int node = gt >> 5;
    int lane = gt & 31;
    const float4* p0 = (const float4*)(qkv0 + (size_t)node * 384);
    const float4* p1 = (const float4*)(qkv1 + (size_t)node * 384);
    float4 q0 = p0[lane], k0 = p0[32 + lane], v0 = p0[64 + lane];
    float4 q1 = p1[lane], k1 = p1[32 + lane], v1 = p1[64 + lane];

    float p00 = q0.x * k0.x + q0.y * k0.y + q0.z * k0.z + q0.w * k0.w;
    float p01 = q0.x * k1.x + q0.y * k1.y + q0.z * k1.z + q0.w * k1.w;
    float p10 = q1.x * k0.x + q1.y * k0.y + q1.z * k0.z + q1.w * k0.w;
    float p11 = q1.x * k1.x + q1.y * k1.y + q1.z * k1.z + q1.w * k1.w;

    int hd = 128 / nh;
    int Wd = hd >> 2;                 // lanes per head (16 or 8)
    for (int off = Wd >> 1; off; off >>= 1) {
        p00 += __shfl_xor_sync(0xffffffffu, p00, off);
        p01 += __shfl_xor_sync(0xffffffffu, p01, off);
        p10 += __shfl_xor_sync(0xffffffffu, p10, off);
        p11 += __shfl_xor_sync(0xffffffffu, p11, off);
    }
    float scl = rsqrtf((float)hd);
    float s00 = p00 * scl, s01 = p01 * scl, s10 = p10 * scl, s11 = p11 * scl;

    float mx0 = fmaxf(s00, s01);
    float e00 = expf(s00 - mx0), e01 = expf(s01 - mx0);
    float r0 = 1.0f / (e00 + e01);
    float mx1 = fmaxf(s10, s11);
    float e10 = expf(s10 - mx1), e11 = expf(s11 - mx1);
    float r1 = 1.0f / (e10 + e11);

    float c0 = 0.5f * (e00 * r0 + e10 * r1);
    float c1 = 0.5f * (e01 * r0 + e11 * r1);

    float4 o;
    o.x = c0 * v0.x + c1 * v1.x;
    o.y = c0 * v0.y + c1 * v1.y;
    o.z = c0 * v0.z + c1 * v1.z;
    o.w = c0 * v0.w + c1 * v1.w;
    ((float4*)(om + (size_t)node * 128))[lane] = o;
}

// ---------------------------------------------------------------------------
// Edge classifier: out[e,:2] = [h3[i0]|h3[i1]] @ Wc[256,2] + bc
// ---------------------------------------------------------------------------
__global__ __launch_bounds__(256) void edge_kernel(
    const float* __restrict__ h3, const int* __restrict__ ei,
    const float* __restrict__ Wc, const float* __restrict__ bc,
    float* __restrict__ out)
{
    __shared__ float wcs[512];
    __shared__ float bcs[2];
    int t = threadIdx.x;
    for (int i = t; i < 512; i += 256) wcs[i] = Wc[i];
    if (t < 2) bcs[t] = bc[t];
    __syncthreads();

    int e = blockIdx.x * 256 + t;
    int i0 = ei[e], i1 = ei[N_EDGES + e];
    const float4* r0 = (const float4*)(h3 + (size_t)i0 * 128);
    const float4* r1 = (const float4*)(h3 + (size_t)i1 * 128);
    float acc0 = bcs[0], acc1 = bcs[1];
#pragma unroll 8
    for (int q = 0; q < 32; q++) {
        float4 f = r0[q];
        int d = q * 4;
        acc0 += f.x * wcs[2 * d] + f.y * wcs[2 * (d + 1)] + f.z * wcs[2 * (d + 2)] + f.w * wcs[2 * (d + 3)];
        acc1 += f.x * wcs[2 * d + 1] + f.y * wcs[2 * (d + 1) + 1] + f.z * wcs[2 * (d + 2) + 1] + f.w * wcs[2 * (d + 3) + 1];
    }
#pragma unroll 8
    for (int q = 0; q < 32; q++) {
        float4 f = r1[q];
        int d = 128 + q * 4;
        acc0 += f.x * wcs[2 * d] + f.y * wcs[2 * (d + 1)] + f.z * wcs[2 * (d + 2)] + f.w * wcs[2 * (d + 3)];
        acc1 += f.x * wcs[2 * d + 1] + f.y * wcs[2 * (d + 1) + 1] + f.z * wcs[2 * (d + 2) + 1] + f.w * wcs[2 * (d + 3) + 1];
    }
    out[(size_t)e * 2]     = acc0;
    out[(size_t)e * 2 + 1] = acc1;
}

// ---------------------------------------------------------------------------
extern "C" void kernel_launch(void* const* d_in, const int* in_sizes, int n_in,
                              void* d_out, int out_size)
{
    const float* x    = (const float*)d_in[0];
    const float* G1   = (const float*)d_in[1];
    const float* G3   = (const float*)d_in[2];
    const int*   ei   = (const int*)d_in[3];
    const int*   perm = (const int*)d_in[4];
    const float* lam  = (const float*)d_in[5];
    const float* beta = (const float*)d_in[6];
    const float* W1 = (const float*)d_in[7];   const float* b1 = (const float*)d_in[8];
    const float* W2 = (const float*)d_in[9];   const float* b2 = (const float*)d_in[10];
    const float* W3 = (const float*)d_in[11];  const float* b3 = (const float*)d_in[12];
    const float* W1h = (const float*)d_in[13]; const float* b1h = (const float*)d_in[14];
    const float* W3h = (const float*)d_in[15]; const float* b3h = (const float*)d_in[16];
    const float* W2m = (const float*)d_in[17]; const float* b2m = (const float*)d_in[18];
    const float* W3m = (const float*)d_in[19]; const float* b3m = (const float*)d_in[20];
    const float* Wqkv_mix = (const float*)d_in[21]; const float* bqkv_mix = (const float*)d_in[22];
    const float* Wo_mix   = (const float*)d_in[23]; const float* bo_mix   = (const float*)d_in[24];
    const float* Wqkv_fus = (const float*)d_in[25]; const float* bqkv_fus = (const float*)d_in[26];
    const float* Wo_fus   = (const float*)d_in[27]; const float* bo_fus   = (const float*)d_in[28];
    const float* Wc = (const float*)d_in[29];  const float* bc = (const float*)d_in[30];

    float *t, *t2, *h1, *h2, *h3c1, *a1, *a3, *m1, *m3, *qkv0, *qkv1, *om, *hmix, *h2m, *h3c2, *h3;
    cudaGetSymbolAddress((void**)&t, g_t);
    cudaGetSymbolAddress((void**)&t2, g_t2);
    cudaGetSymbolAddress((void**)&h1, g_h1);
    cudaGetSymbolAddress((void**)&h2, g_h2);
    cudaGetSymbolAddress((void**)&h3c1, g_h3c1);
    cudaGetSymbolAddress((void**)&a1, g_a1);
    cudaGetSymbolAddress((void**)&a3, g_a3);
    cudaGetSymbolAddress((void**)&m1, g_m1);
    cudaGetSymbolAddress((void**)&m3, g_m3);
    cudaGetSymbolAddress((void**)&qkv0, g_qkv0);
    cudaGetSymbolAddress((void**)&qkv1, g_qkv1);
    cudaGetSymbolAddress((void**)&om, g_om);
    cudaGetSymbolAddress((void**)&hmix, g_hmix);
    cudaGetSymbolAddress((void**)&h2m, g_h2m);
    cudaGetSymbolAddress((void**)&h3c2, g_h3c2);
    cudaGetSymbolAddress((void**)&h3, g_h3);

    float* out_edge = (float*)d_out;
    float* out_h3   = out_edge + (size_t)N_EDGES * 2;

    dim3 blk(128);

    // t1 = x@W1 + b1
    gemm_tiled<<<dim3(128, 1), blk>>>(x, 128, W1, 128, 128, t, nullptr, nullptr, b1, nullptr, 128, 0, 5);
    // h1 = relu(G1 @ t1)
    gemm_tiled<<<dim3(128, 1), blk>>>(G1, 4096, t, 128, 4096, h1, nullptr, nullptr, nullptr, nullptr, 128, 0, 0);
    // t2 = h1@W2 + b2
    gemm_tiled<<<dim3(128, 1), blk>>>(h1, 128, W2, 128, 128, t, nullptr, nullptr, b2, nullptr, 128, 0, 5);
    // h2 = relu(G1 @ t2 + h1)
    gemm_tiled<<<dim3(128, 1), blk>>>(G1, 4096, t, 128, 4096, h2, nullptr, h1, nullptr, nullptr, 128, 0, 1);
    // t3 -> g_t cols 0..127 (ld 256); u1h -> cols 128..255; u3h -> t2buf
    gemm_tiled<<<dim3(128, 1), blk>>>(h2, 128, W3, 128, 128, t, nullptr, nullptr, b3, nullptr, 256, 0, 5);
    gemm_tiled<<<dim3(128, 1), blk>>>(h1, 128, W1h, 128, 128, t, nullptr, nullptr, b1h, nullptr, 256, 128, 5);
    gemm_tiled<<<dim3(128, 1), blk>>>(h1, 128, W3h, 128, 128, t2, nullptr, nullptr, b3h, nullptr, 128, 0, 5);
    // fused pass over G1: h3_c1 = relu(G1@t3 + h2); a1 = G1@u1h (raw)
    gemm_tiled<<<dim3(128, 2), blk>>>(G1, 4096, t, 256, 4096, h3c1, a1, h2, nullptr, nullptr, 128, 0, 2);
    // a3 = G3 @ u3h
    gemm_tiled<<<dim3(128, 1), blk>>>(G3, 4096, t2, 128, 4096, a3, nullptr, nullptr, nullptr, nullptr, 128, 0, 3);
    // mixup (permuted-graph branch == row permutation of a1/a3)
    mix_kernel<<<512, 256>>>(a1, a3, perm, lam, m1, m3);
    // MHA mix (nh=2)
    gemm_nt<<<dim3(128, 12), 256>>>(m1, Wqkv_mix, bqkv_mix, qkv0, nullptr, 384);
    gemm_nt<<<dim3(128, 12), 256>>>(m3, Wqkv_mix, bqkv_mix, qkv1, nullptr, 384);
    attn_kernel<<<512, 256>>>(qkv0, qkv1, om, 2);
    gemm_nt<<<dim3(128, 4), 256>>>(om, Wo_mix, bo_mix, hmix, nullptr, 128);
    // t2m, h2_mix
    gemm_tiled<<<dim3(128, 1), blk>>>(hmix, 128, W2m, 128, 128, t, nullptr, nullptr, b2m, nullptr, 128, 0, 5);
    gemm_tiled<<<dim3(128, 1), blk>>>(G1, 4096, t, 128, 4096, h2m, nullptr, hmix, nullptr, nullptr, 128, 0, 1);
    // t3m, h3_c2 = relu(G1@t3m + h2_mix)*beta
    gemm_tiled<<<dim3(128, 1), blk>>>(h2m, 128, W3m, 128, 128, t, nullptr, nullptr, b3m, nullptr, 128, 0, 5);
    gemm_tiled<<<dim3(128, 1), blk>>>(G1, 4096, t, 128, 4096, h3c2, nullptr, h2m, nullptr, beta, 128, 0, 4);
    // MHA fus (nh=4)
    gemm_nt<<<dim3(128, 12), 256>>>(h3c1, Wqkv_fus, bqkv_fus, qkv0, nullptr, 384);
    gemm_nt<<<dim3(128, 12), 256>>>(h3c2, Wqkv_fus, bqkv_fus, qkv1, nullptr, 384);
    attn_kernel<<<512, 256>>>(qkv0, qkv1, om, 4);
    // h3 (write scratch + second output region)
    gemm_nt<<<dim3(128, 4), 256>>>(om, Wo_fus, bo_fus, h3, out_h3, 128);
    // edge predictions (first output region)
    edge_kernel<<<512, 256>>>(h3, ei, Wc, bc, out_edge);
}

// round 4
// speedup vs baseline: 4.2056x; 4.2056x over previous
#include <cuda_runtime.h>
#include <cuda_bf16.h>
#include <cstdint>

#define N_NODES 4096
#define HDIM    128
#define N_EDGES 131072
#define KTOT    4096
#define SPLITK  8
#define KCTA    (KTOT / SPLITK)     // 512
#define BK      32
#define NCH     (KCTA / BK)         // 16

// ---------------- scratch (static device arrays; no allocation) ----------------
__device__ float g_t[N_NODES * 256];
__device__ float g_t2[N_NODES * 128];
__device__ float g_h1[N_NODES * 128];
__device__ float g_h2[N_NODES * 128];
__device__ float g_h3c1[N_NODES * 128];
__device__ float g_a1[N_NODES * 128];
__device__ float g_a3[N_NODES * 128];
__device__ float g_m1[N_NODES * 128];
__device__ float g_m3[N_NODES * 128];
__device__ float g_qkv0[N_NODES * 384];
__device__ float g_qkv1[N_NODES * 384];
__device__ float g_om[N_NODES * 128];
__device__ float g_hmix[N_NODES * 128];
__device__ float g_h2m[N_NODES * 128];
__device__ float g_h3c2[N_NODES * 128];
__device__ float g_h3[N_NODES * 128];
// bf16 split of the dense propagation matrices
__device__ __nv_bfloat16 g_G1h[(size_t)KTOT * KTOT];
__device__ __nv_bfloat16 g_G1l[(size_t)KTOT * KTOT];
__device__ __nv_bfloat16 g_G3h[(size_t)KTOT * KTOT];
__device__ __nv_bfloat16 g_G3l[(size_t)KTOT * KTOT];
// transposed bf16 split of RHS (up to 256 rows x 4096 cols, row = output col)
__device__ __nv_bfloat16 g_Bth[256 * KTOT];
__device__ __nv_bfloat16 g_Btl[256 * KTOT];
// split-K partials [2][SPLITK][4096][128]
__device__ float g_part[(size_t)2 * SPLITK * N_NODES * 128];

// ============================ asm helpers =================================
__device__ __forceinline__ uint32_t smem_to_u32(const void* p) {
    uint32_t a;
    asm("{ .reg .u64 t; cvta.to.shared.u64 t, %1; cvt.u32.u64 %0, t; }" : "=r"(a) : "l"(p));
    return a;
}
__device__ __forceinline__ void cp16(uint32_t s, const void* g) {
    asm volatile("cp.async.cg.shared.global [%0], [%1], 16;" :: "r"(s), "l"(g));
}
__device__ __forceinline__ void cp_commit() {
    asm volatile("cp.async.commit_group;" ::: "memory");
}
template <int Ng>
__device__ __forceinline__ void cp_wait() {
    asm volatile("cp.async.wait_group %0;" :: "n"(Ng) : "memory");
}
__device__ __forceinline__ void ldsm4(uint32_t* r, uint32_t addr) {
    asm volatile("ldmatrix.sync.aligned.m8n8.x4.shared.b16 {%0,%1,%2,%3}, [%4];"
        : "=r"(r[0]), "=r"(r[1]), "=r"(r[2]), "=r"(r[3]) : "r"(addr));
}
__device__ __forceinline__ void mma16816(float* d, const uint32_t* a, uint32_t b0, uint32_t b1) {
    asm volatile(
        "mma.sync.aligned.m16n8k16.row.col.f32.bf16.bf16.f32 "
        "{%0,%1,%2,%3}, {%4,%5,%6,%7}, {%8,%9}, {%0,%1,%2,%3};"
        : "+f"(d[0]), "+f"(d[1]), "+f"(d[2]), "+f"(d[3])
        : "r"(a[0]), "r"(a[1]), "r"(a[2]), "r"(a[3]), "r"(b0), "r"(b1));
}

// ===========================================================================
// Big tensor-core GEMM via mma.sync (HMMA, portable to plain sm_103 target):
// Part[nt][ks][4096][128] = Ah@Bh^T + Ah@Bl^T + Al@Bh^T over K range of ks.
// CTA tile 128x128, BK=32, 8 warps (4x2), warp tile 32x64, 2-stage cp.async.
// A: [4096][4096] row-major bf16. B: [n][4096] row-major bf16 (n = out col).
// ===========================================================================
#define TSTRIDE 80                    // bytes per smem row (32 bf16 + 8 pad)
#define TILE_B  (128 * TSTRIDE)       // 10240 B per operand tile
#define STAGE   (4 * TILE_B)          // Ah | Al | Bh | Bl
#define GEMM_SMEM (2 * STAGE)         // 81920 B

__global__ __launch_bounds__(256, 2) void gemm_mma(
    const __nv_bfloat16* __restrict__ Ah, const __nv_bfloat16* __restrict__ Al,
    const __nv_bfloat16* __restrict__ Bh, const __nv_bfloat16* __restrict__ Bl,
    float* __restrict__ Part)
{
    extern __shared__ char smraw[];
    const uint32_t sm0 = smem_to_u32(smraw);

    const int tid = threadIdx.x;
    const int lane = tid & 31, wid = tid >> 5;
    const int wm = wid >> 1, wn = wid & 1;
    const int m0 = blockIdx.x * 128;
    const int ks = blockIdx.y;
    const int nt = blockIdx.z;
    const int kb = ks * KCTA;

    const __nv_bfloat16* gAh = Ah + (size_t)m0 * KTOT + kb;
    const __nv_bfloat16* gAl = Al + (size_t)m0 * KTOT + kb;
    const __nv_bfloat16* gBh = Bh + (size_t)(nt * 128) * KTOT + kb;
    const __nv_bfloat16* gBl = Bl + (size_t)(nt * 128) * KTOT + kb;

    // per-thread staging slots: idx 0..511 -> row=idx>>2, 16B chunk c=idx&3
    const int r0i = tid >> 2, c0i = tid & 3;
    const int r1i = (tid + 256) >> 2, c1i = tid & 3;   // (tid+256)&3 == tid&3
    const uint32_t so0 = (uint32_t)r0i * TSTRIDE + c0i * 16;
    const uint32_t so1 = (uint32_t)r1i * TSTRIDE + c1i * 16;

    // ldmatrix lane addressing
    const uint32_t aO = (uint32_t)(wm * 32 + (lane & 15)) * TSTRIDE + (lane >> 4) * 16;
    const uint32_t bO = (uint32_t)(wn * 64 + (lane & 7) + ((lane >> 4) & 1) * 8) * TSTRIDE
                      + ((lane >> 3) & 1) * 16;

    float acc[2][8][4];
#pragma unroll
    for (int i = 0; i < 2; i++)
#pragma unroll
        for (int j = 0; j < 8; j++)
#pragma unroll
            for (int q = 0; q < 4; q++) acc[i][j][q] = 0.0f;

#define LOAD_CHUNK(ci, s) do { \
    uint32_t sbase = sm0 + (s) * STAGE; \
    size_t g0 = (size_t)r0i * KTOT + (ci) * BK + c0i * 8; \
    size_t g1 = (size_t)r1i * KTOT + (ci) * BK + c1i * 8; \
    cp16(sbase + so0,              gAh + g0); \
    cp16(sbase + so1,              gAh + g1); \
    cp16(sbase + TILE_B + so0,     gAl + g0); \
    cp16(sbase + TILE_B + so1,     gAl + g1); \
    cp16(sbase + 2 * TILE_B + so0, gBh + g0); \
    cp16(sbase + 2 * TILE_B + so1, gBh + g1); \
    cp16(sbase + 3 * TILE_B + so0, gBl + g0); \
    cp16(sbase + 3 * TILE_B + so1, gBl + g1); \
} while (0)

    LOAD_CHUNK(0, 0);
    cp_commit();

    for (int ci = 0; ci < NCH; ++ci) {
        if (ci + 1 < NCH) { LOAD_CHUNK(ci + 1, (ci + 1) & 1); cp_commit(); }
        if (ci + 1 < NCH) cp_wait<1>(); else cp_wait<0>();
        __syncthreads();

        const uint32_t sb = sm0 + (ci & 1) * STAGE;
#pragma unroll
        for (int kk = 0; kk < 2; ++kk) {
            const uint32_t ko = kk * 32;    // 16 bf16 = 32 B
            uint32_t ah[2][4], al[2][4], bf[4][4];
            ldsm4(ah[0], sb + aO + ko);
            ldsm4(ah[1], sb + aO + 16 * TSTRIDE + ko);
            ldsm4(al[0], sb + TILE_B + aO + ko);
            ldsm4(al[1], sb + TILE_B + aO + 16 * TSTRIDE + ko);
#pragma unroll
            for (int j = 0; j < 4; j++)
                ldsm4(bf[j], sb + 2 * TILE_B + bO + j * 16 * TSTRIDE + ko);
#pragma unroll
            for (int i = 0; i < 2; i++)
#pragma unroll
                for (int j = 0; j < 4; j++) {
                    mma16816(acc[i][2 * j],     ah[i], bf[j][0], bf[j][1]);
                    mma16816(acc[i][2 * j + 1], ah[i], bf[j][2], bf[j][3]);
                }
#pragma unroll
            for (int i = 0; i < 2; i++)
#pragma unroll
                for (int j = 0; j < 4; j++) {
                    mma16816(acc[i][2 * j],     al[i], bf[j][0], bf[j][1]);
                    mma16816(acc[i][2 * j + 1], al[i], bf[j][2], bf[j][3]);
                }
#pragma unroll
            for (int j = 0; j < 4; j++)
                ldsm4(bf[j], sb + 3 * TILE_B + bO + j * 16 * TSTRIDE + ko);
#pragma unroll
            for (int i = 0; i < 2; i++)
#pragma unroll
                for (int j = 0; j < 4; j++) {
                    mma16816(acc[i][2 * j],     ah[i], bf[j][0], bf[j][1]);
                    mma16816(acc[i][2 * j + 1], ah[i], bf[j][2], bf[j][3]);
                }
        }
        __syncthreads();
    }

    // epilogue: write fp32 partial tile
    float* outp = Part + ((size_t)(nt * SPLITK + ks) * N_NODES + m0) * 128;
    const int rr = lane >> 2, c2 = (lane & 3) * 2;
#pragma unroll
    for (int i = 0; i < 2; i++) {
        const int row0 = wm * 32 + i * 16 + rr;
#pragma unroll
        for (int j = 0; j < 8; j++) {
            const int col = wn * 64 + j * 8 + c2;
            *(float2*)(outp + (size_t)row0 * 128 + col)       = make_float2(acc[i][j][0], acc[i][j][1]);
            *(float2*)(outp + (size_t)(row0 + 8) * 128 + col) = make_float2(acc[i][j][2], acc[i][j][3]);
        }
    }
#undef LOAD_CHUNK
}

// ---------------------------------------------------------------------------
// reduce SPLITK partials + epilogue.
// mode 0: relu(z); 1: relu(z+res); 3: z; 4: relu(z+res)*scale
// ---------------------------------------------------------------------------
__global__ __launch_bounds__(256) void reduce_ep(
    const float* __restrict__ P, const float* __restrict__ res,
    const float* __restrict__ scale_p, float* __restrict__ C, int mode)
{
    int i = blockIdx.x * 256 + threadIdx.x;       // float4 index, 131072 total
    const float4* p = (const float4*)P;
    float4 z = p[i];
#pragma unroll
    for (int s = 1; s < SPLITK; s++) {
        float4 a = p[i + (size_t)s * 131072];
        z.x += a.x; z.y += a.y; z.z += a.z; z.w += a.w;
    }
    if (mode == 1 || mode == 4) {
        float4 r = ((const float4*)res)[i];
        z.x += r.x; z.y += r.y; z.z += r.z; z.w += r.w;
    }
    if (mode != 3) {
        z.x = fmaxf(z.x, 0.0f); z.y = fmaxf(z.y, 0.0f);
        z.z = fmaxf(z.z, 0.0f); z.w = fmaxf(z.w, 0.0f);
    }
    if (mode == 4) {
        float s = *scale_p;
        z.x *= s; z.y *= s; z.z *= s; z.w *= s;
    }
    ((float4*)C)[i] = z;
}

// ---------------------------------------------------------------------------
// Split fp32 -> bf16 hi/lo (elementwise, float4 granularity)
// ---------------------------------------------------------------------------
__global__ __launch_bounds__(256) void conv_split(
    const float* __restrict__ X, __nv_bfloat16* __restrict__ Xh,
    __nv_bfloat16* __restrict__ Xl)
{
    size_t i = (size_t)blockIdx.x * 256 + threadIdx.x;
    float4 v = ((const float4*)X)[i];
    __nv_bfloat16 hx = __float2bfloat16(v.x);
    __nv_bfloat16 hy = __float2bfloat16(v.y);
    __nv_bfloat16 hz = __float2bfloat16(v.z);
    __nv_bfloat16 hw = __float2bfloat16(v.w);
    __nv_bfloat16 lx = __float2bfloat16(v.x - __bfloat162float(hx));
    __nv_bfloat16 ly = __float2bfloat16(v.y - __bfloat162float(hy));
    __nv_bfloat16 lz = __float2bfloat16(v.z - __bfloat162float(hz));
    __nv_bfloat16 lw = __float2bfloat16(v.w - __bfloat162float(hw));
    union { __nv_bfloat16 b[4]; uint2 u; } H, L;
    H.b[0] = hx; H.b[1] = hy; H.b[2] = hz; H.b[3] = hw;
    L.b[0] = lx; L.b[1] = ly; L.b[2] = lz; L.b[3] = lw;
    ((uint2*)Xh)[i] = H.u;
    ((uint2*)Xl)[i] = L.u;
}

// ---------------------------------------------------------------------------
// Transpose + split: Bt[ro+n][k] = split(T[k][co+n]).  T is [4096][ldt].
// grid (KTOT/32, Ncols/32), block (32, 8)
// ---------------------------------------------------------------------------
__global__ void conv_trans(const float* __restrict__ T, int ldt, int co,
                           __nv_bfloat16* __restrict__ Bh, __nv_bfloat16* __restrict__ Bl,
                           int ro)
{
    __shared__ float tile[32][33];
    int k0 = blockIdx.x * 32, n0 = blockIdx.y * 32;
    int tx = threadIdx.x, ty = threadIdx.y;
#pragma unroll
    for (int j = 0; j < 32; j += 8)
        tile[ty + j][tx] = T[(size_t)(k0 + ty + j) * ldt + co + n0 + tx];
    __syncthreads();
#pragma unroll
    for (int j = 0; j < 32; j += 8) {
        int n = ty + j;
        float v = tile[tx][n];
        __nv_bfloat16 h = __float2bfloat16(v);
        __nv_bfloat16 l = __float2bfloat16(v - __bfloat162float(h));
        Bh[(size_t)(ro + n0 + n) * KTOT + k0 + tx] = h;
        Bl[(size_t)(ro + n0 + n) * KTOT + k0 + tx] = l;
    }
}

// ---------------------------------------------------------------------------
// Small NN GEMM (K=128): C[row*ldc + coffc + col] = A@B + bias
// ---------------------------------------------------------------------------
__global__ __launch_bounds__(128, 1) void gemm_small(
    const float* __restrict__ A,
    const float* __restrict__ B,
    const float* __restrict__ bias,
    float* __restrict__ C, int ldc, int coffc)
{
    __shared__ float As[32 * 33];
    __shared__ float Bs[32 * 128];
    const int t = threadIdx.x;
    const int m0 = blockIdx.x * 32;
    const int tr = t >> 4, tc = t & 15;
    const int am = t >> 2, ak = (t & 3) * 8;

    float acc[4][8];
#pragma unroll
    for (int r = 0; r < 4; r++)
#pragma unroll
        for (int c = 0; c < 8; c++) acc[r][c] = 0.0f;

    const float* Ap = A + (size_t)(m0 + am) * 128 + ak;
    float4 a0, a1, bb[8];

    a0 = *(const float4*)(Ap);
    a1 = *(const float4*)(Ap + 4);
#pragma unroll
    for (int j = 0; j < 8; j++) {
        int f = t + j * 128;
        bb[j] = *(const float4*)(B + (size_t)(f >> 5) * 128 + (f & 31) * 4);
    }
    As[(ak + 0) * 33 + am] = a0.x; As[(ak + 1) * 33 + am] = a0.y;
    As[(ak + 2) * 33 + am] = a0.z; As[(ak + 3) * 33 + am] = a0.w;
    As[(ak + 4) * 33 + am] = a1.x; As[(ak + 5) * 33 + am] = a1.y;
    As[(ak + 6) * 33 + am] = a1.z; As[(ak + 7) * 33 + am] = a1.w;
#pragma unroll
    for (int j = 0; j < 8; j++) {
        int f = t + j * 128;
        *(float4*)&Bs[(f >> 5) * 128 + (f & 31) * 4] = bb[j];
    }
    __syncthreads();

    for (int it = 1; it <= 4; ++it) {
        if (it < 4) {
            int k0 = it << 5;
            a0 = *(const float4*)(Ap + k0);
            a1 = *(const float4*)(Ap + k0 + 4);
#pragma unroll
            for (int j = 0; j < 8; j++) {
                int f = t + j * 128;
                bb[j] = *(const float4*)(B + (size_t)(k0 + (f >> 5)) * 128 + (f & 31) * 4);
            }
        }
#pragma unroll
        for (int k = 0; k < 32; ++k) {
            float av[4];
#pragma unroll
            for (int r = 0; r < 4; r++) av[r] = As[k * 33 + tr * 4 + r];
            float4 b0 = *(const float4*)&Bs[k * 128 + tc * 8];
            float4 b1 = *(const float4*)&Bs[k * 128 + tc * 8 + 4];
            float bv[8] = {b0.x, b0.y, b0.z, b0.w, b1.x, b1.y, b1.z, b1.w};
#pragma unroll
            for (int r = 0; r < 4; r++)
#pragma unroll
                for (int c = 0; c < 8; c++) acc[r][c] += av[r] * bv[c];
        }
        __syncthreads();
        if (it < 4) {
            As[(ak + 0) * 33 + am] = a0.x; As[(ak + 1) * 33 + am] = a0.y;
            As[(ak + 2) * 33 + am] = a0.z; As[(ak + 3) * 33 + am] = a0.w;
            As[(ak + 4) * 33 + am] = a1.x; As[(ak + 5) * 33 + am] = a1.y;
            As[(ak + 6) * 33 + am] = a1.z; As[(ak + 7) * 33 + am] = a1.w;
#pragma unroll
            for (int j = 0; j < 8; j++) {
                int f = t + j * 128;
                *(float4*)&Bs[(f >> 5) * 128 + (f & 31) * 4] = bb[j];
            }
            __syncthreads();
        }
    }

#pragma unroll
    for (int r = 0; r < 4; r++) {
        int row = m0 + tr * 4 + r;
#pragma unroll
        for (int c = 0; c < 8; c++) {
            int col = tc * 8 + c;
            C[(size_t)row * ldc + coffc + col] = acc[r][c] + bias[col];
        }
    }
}

// ---------------------------------------------------------------------------
// NT GEMM: C[M, No] = A[M,128] @ W[No,128]^T + bias
// ---------------------------------------------------------------------------
__global__ __launch_bounds__(256) void gemm_nt(
    const float* __restrict__ A, const float* __restrict__ W,
    const float* __restrict__ bias, float* __restrict__ C,
    float* __restrict__ C2, int No)
{
    __shared__ float As[32 * 129];
    __shared__ float Ws[32 * 129];
    const int t = threadIdx.x;
    const int m0 = blockIdx.x * 32, n0 = blockIdx.y * 32;

    for (int i = t; i < 32 * 128; i += 256) {
        int r = i >> 7, k = i & 127;
        As[r * 129 + k] = A[(m0 + r) * 128 + k];
        Ws[r * 129 + k] = W[(n0 + r) * 128 + k];
    }
    __syncthreads();

    const int tr = t >> 4, tc = t & 15;
    const float* a0p = &As[(tr * 2) * 129];
    const float* a1p = &As[(tr * 2 + 1) * 129];
    const float* w0p = &Ws[(tc * 2) * 129];
    const float* w1p = &Ws[(tc * 2 + 1) * 129];

    float acc00 = 0, acc01 = 0, acc10 = 0, acc11 = 0;
#pragma unroll 16
    for (int k = 0; k < 128; k++) {
        float a0 = a0p[k], a1 = a1p[k], w0 = w0p[k], w1 = w1p[k];
        acc00 += a0 * w0; acc01 += a0 * w1;
        acc10 += a1 * w0; acc11 += a1 * w1;
    }
    int row0 = m0 + tr * 2, col0 = n0 + tc * 2;
    float v00 = acc00 + bias[col0], v01 = acc01 + bias[col0 + 1];
    float v10 = acc10 + bias[col0], v11 = acc11 + bias[col0 + 1];
    C[(size_t)row0 * No + col0]           = v00;
    C[(size_t)row0 * No + col0 + 1]       = v01;
    C[(size_t)(row0 + 1) * No + col0]     = v10;
    C[(size_t)(row0 + 1) * No + col0 + 1] = v11;
    if (C2) {
        C2[(size_t)row0 * No + col0]           = v00;
        C2[(size_t)row0 * No + col0 + 1]       = v01;
        C2[(size_t)(row0 + 1) * No + col0]     = v10;
        C2[(size_t)(row0 + 1) * No + col0 + 1] = v11;
    }
}

// ---------------------------------------------------------------------------
__global__ void mix_kernel(const float* __restrict__ a1, const float* __restrict__ a3,
                           const int* __restrict__ perm, const float* __restrict__ lam,
                           float* __restrict__ m1, float* __restrict__ m3)
{
    int i = blockIdx.x * blockDim.x + threadIdx.x;
    int row = i >> 5, q = i & 31;
    float l = lam[0], il = 1.0f - l;
    int pr = perm[row];
    float4 x = ((const float4*)a1)[row * 32 + q];
    float4 y = ((const float4*)a1)[pr * 32 + q];
    float4 o;
    o.x = l * x.x + il * y.x; o.y = l * x.y + il * y.y;
    o.z = l * x.z + il * y.z; o.w = l * x.w + il * y.w;
    ((float4*)m1)[row * 32 + q] = o;
    x = ((const float4*)a3)[row * 32 + q];
    y = ((const float4*)a3)[pr * 32 + q];
    o.x = l * x.x + il * y.x; o.y = l * x.y + il * y.y;
    o.z = l * x.z + il * y.z; o.w = l * x.w + il * y.w;
    ((float4*)m3)[row * 32 + q] = o;
}

__global__ void attn_kernel(const float* __restrict__ qkv0, const float* __restrict__ qkv1,
                            float* __restrict__ om, int nh)
{
    int gt = blockIdx.x * blockDim.x + threadIdx.x;
    int node = gt >> 5;
    int lane = gt & 31;
    const float4* p0 = (const float4*)(qkv0 + (size_t)node * 384);
    const float4* p1 = (const float4*)(qkv1 + (size_t)node * 384);
    float4 q0 = p0[lane], k0 = p0[32 + lane], v0 = p0[64 + lane];
    float4 q1 = p1[lane], k1 = p1[32 + lane], v1 = p1[64 + lane];

    float p00 = q0.x * k0.x + q0.y * k0.y + q0.z * k0.z + q0.w * k0.w;
    float p01 = q0.x * k1.x + q0.y * k1.y + q0.z * k1.z + q0.w * k1.w;
    float p10 = q1.x * k0.x + q1.y * k0.y + q1.z * k0.z + q1.w * k0.w;
    float p11 = q1.x * k1.x + q1.y * k1.y + q1.z * k1.z + q1.w * k1.w;

    int hd = 128 / nh;
    int Wd = hd >> 2;
    for (int off = Wd >> 1; off; off >>= 1) {
        p00 += __shfl_xor_sync(0xffffffffu, p00, off);
        p01 += __shfl_xor_sync(0xffffffffu, p01, off);
        p10 += __shfl_xor_sync(0xffffffffu, p10, off);
        p11 += __shfl_xor_sync(0xffffffffu, p11, off);
    }
    float scl = rsqrtf((float)hd);
    float s00 = p00 * scl, s01 = p01 * scl, s10 = p10 * scl, s11 = p11 * scl;

    float mx0 = fmaxf(s00, s01);
    float e00 = expf(s00 - mx0), e01 = expf(s01 - mx0);
    float r0 = 1.0f / (e00 + e01);
    float mx1 = fmaxf(s10, s11);
    float e10 = expf(s10 - mx1), e11 = expf(s11 - mx1);
    float r1 = 1.0f / (e10 + e11);

    float c0 = 0.5f * (e00 * r0 + e10 * r1);
    float c1 = 0.5f * (e01 * r0 + e11 * r1);

    float4 o;
    o.x = c0 * v0.x + c1 * v1.x;
    o.y = c0 * v0.y + c1 * v1.y;
    o.z = c0 * v0.z + c1 * v1.z;
    o.w = c0 * v0.w + c1 * v1.w;
    ((float4*)(om + (size_t)node * 128))[lane] = o;
}

__global__ __launch_bounds__(256) void edge_kernel(
    const float* __restrict__ h3, const int* __restrict__ ei,
    const float* __restrict__ Wc, const float* __restrict__ bc,
    float* __restrict__ out)
{
    __shared__ float wcs[512];
    __shared__ float bcs[2];
    int t = threadIdx.x;
    for (int i = t; i < 512; i += 256) wcs[i] = Wc[i];
    if (t < 2) bcs[t] = bc[t];
    __syncthreads();

    int e = blockIdx.x * 256 + t;
    int i0 = ei[e], i1 = ei[N_EDGES + e];
    const float4* r0 = (const float4*)(h3 + (size_t)i0 * 128);
    const float4* r1 = (const float4*)(h3 + (size_t)i1 * 128);
    float acc0 = bcs[0], acc1 = bcs[1];
#pragma unroll 8
    for (int q = 0; q < 32; q++) {
        float4 f = r0[q];
        int d = q * 4;
        acc0 += f.x * wcs[2 * d] + f.y * wcs[2 * (d + 1)] + f.z * wcs[2 * (d + 2)] + f.w * wcs[2 * (d + 3)];
        acc1 += f.x * wcs[2 * d + 1] + f.y * wcs[2 * (d + 1) + 1] + f.z * wcs[2 * (d + 2) + 1] + f.w * wcs[2 * (d + 3) + 1];
    }
#pragma unroll 8
    for (int q = 0; q < 32; q++) {
        float4 f = r1[q];
        int d = 128 + q * 4;
        acc0 += f.x * wcs[2 * d] + f.y * wcs[2 * (d + 1)] + f.z * wcs[2 * (d + 2)] + f.w * wcs[2 * (d + 3)];
        acc1 += f.x * wcs[2 * d + 1] + f.y * wcs[2 * (d + 1) + 1] + f.z * wcs[2 * (d + 2) + 1] + f.w * wcs[2 * (d + 3) + 1];
    }
    out[(size_t)e * 2]     = acc0;
    out[(size_t)e * 2 + 1] = acc1;
}

// ---------------------------------------------------------------------------
extern "C" void kernel_launch(void* const* d_in, const int* in_sizes, int n_in,
                              void* d_out, int out_size)
{
    const float* x    = (const float*)d_in[0];
    const float* G1   = (const float*)d_in[1];
    const float* G3   = (const float*)d_in[2];
    const int*   ei   = (const int*)d_in[3];
    const int*   perm = (const int*)d_in[4];
    const float* lam  = (const float*)d_in[5];
    const float* beta = (const float*)d_in[6];
    const float* W1 = (const float*)d_in[7];   const float* b1 = (const float*)d_in[8];
    const float* W2 = (const float*)d_in[9];   const float* b2 = (const float*)d_in[10];
    const float* W3 = (const float*)d_in[11];  const float* b3 = (const float*)d_in[12];
    const float* W1h = (const float*)d_in[13]; const float* b1h = (const float*)d_in[14];
    const float* W3h = (const float*)d_in[15]; const float* b3h = (const float*)d_in[16];
    const float* W2m = (const float*)d_in[17]; const float* b2m = (const float*)d_in[18];
    const float* W3m = (const float*)d_in[19]; const float* b3m = (const float*)d_in[20];
    const float* Wqkv_mix = (const float*)d_in[21]; const float* bqkv_mix = (const float*)d_in[22];
    const float* Wo_mix   = (const float*)d_in[23]; const float* bo_mix   = (const float*)d_in[24];
    const float* Wqkv_fus = (const float*)d_in[25]; const float* bqkv_fus = (const float*)d_in[26];
    const float* Wo_fus   = (const float*)d_in[27]; const float* bo_fus   = (const float*)d_in[28];
    const float* Wc = (const float*)d_in[29];  const float* bc = (const float*)d_in[30];

    float *t, *t2, *h1, *h2, *h3c1, *a1, *a3, *m1, *m3, *qkv0, *qkv1, *om, *hmix, *h2m, *h3c2, *h3;
    float* part;
    __nv_bfloat16 *G1h, *G1l, *G3h, *G3l, *Bth, *Btl;
    cudaGetSymbolAddress((void**)&t, g_t);
    cudaGetSymbolAddress((void**)&t2, g_t2);
    cudaGetSymbolAddress((void**)&h1, g_h1);
    cudaGetSymbolAddress((void**)&h2, g_h2);
    cudaGetSymbolAddress((void**)&h3c1, g_h3c1);
    cudaGetSymbolAddress((void**)&a1, g_a1);
    cudaGetSymbolAddress((void**)&a3, g_a3);
    cudaGetSymbolAddress((void**)&m1, g_m1);
    cudaGetSymbolAddress((void**)&m3, g_m3);
    cudaGetSymbolAddress((void**)&qkv0, g_qkv0);
    cudaGetSymbolAddress((void**)&qkv1, g_qkv1);
    cudaGetSymbolAddress((void**)&om, g_om);
    cudaGetSymbolAddress((void**)&hmix, g_hmix);
    cudaGetSymbolAddress((void**)&h2m, g_h2m);
    cudaGetSymbolAddress((void**)&h3c2, g_h3c2);
    cudaGetSymbolAddress((void**)&h3, g_h3);
    cudaGetSymbolAddress((void**)&part, g_part);
    cudaGetSymbolAddress((void**)&G1h, g_G1h);
    cudaGetSymbolAddress((void**)&G1l, g_G1l);
    cudaGetSymbolAddress((void**)&G3h, g_G3h);
    cudaGetSymbolAddress((void**)&G3l, g_G3l);
    cudaGetSymbolAddress((void**)&Bth, g_Bth);
    cudaGetSymbolAddress((void**)&Btl, g_Btl);

    cudaFuncSetAttribute(gemm_mma, cudaFuncAttributeMaxDynamicSharedMemorySize, GEMM_SMEM);

    float* out_edge = (float*)d_out;
    float* out_h3   = out_edge + (size_t)N_EDGES * 2;

    const size_t partN = (size_t)SPLITK * N_NODES * 128;

    // split G matrices into bf16 hi/lo (once per call)
    conv_split<<<16384, 256>>>(G1, G1h, G1l);
    conv_split<<<16384, 256>>>(G3, G3h, G3l);

    // ---- h1 = relu(G1 @ (x@W1+b1)) ----
    gemm_small<<<128, 128>>>(x, W1, b1, t, 128, 0);
    conv_trans<<<dim3(128, 4), dim3(32, 8)>>>(t, 128, 0, Bth, Btl, 0);
    gemm_mma<<<dim3(32, SPLITK, 1), 256, GEMM_SMEM>>>(G1h, G1l, Bth, Btl, part);
    reduce_ep<<<512, 256>>>(part, nullptr, nullptr, h1, 0);

    // ---- h2 = relu(G1 @ (h1@W2+b2) + h1) ----
    gemm_small<<<128, 128>>>(h1, W2, b2, t, 128, 0);
    conv_trans<<<dim3(128, 4), dim3(32, 8)>>>(t, 128, 0, Bth, Btl, 0);
    gemm_mma<<<dim3(32, SPLITK, 1), 256, GEMM_SMEM>>>(G1h, G1l, Bth, Btl, part);
    reduce_ep<<<512, 256>>>(part, h1, nullptr, h2, 1);

    // ---- dual pass over G1: h3c1 = relu(G1@t3 + h2), a1 = G1@u1h ----
    gemm_small<<<128, 128>>>(h2, W3, b3, t, 256, 0);
    gemm_small<<<128, 128>>>(h1, W1h, b1h, t, 256, 128);
    gemm_small<<<128, 128>>>(h1, W3h, b3h, t2, 128, 0);
    conv_trans<<<dim3(128, 4), dim3(32, 8)>>>(t, 256, 0, Bth, Btl, 0);
    conv_trans<<<dim3(128, 4), dim3(32, 8)>>>(t, 256, 128, Bth, Btl, 128);
    gemm_mma<<<dim3(32, SPLITK, 2), 256, GEMM_SMEM>>>(G1h, G1l, Bth, Btl, part);
    reduce_ep<<<512, 256>>>(part, h2, nullptr, h3c1, 1);
    reduce_ep<<<512, 256>>>(part + partN, nullptr, nullptr, a1, 3);

    // ---- a3 = G3 @ u3h ----
    conv_trans<<<dim3(128, 4), dim3(32, 8)>>>(t2, 128, 0, Bth, Btl, 0);
    gemm_mma<<<dim3(32, SPLITK, 1), 256, GEMM_SMEM>>>(G3h, G3l, Bth, Btl, part);
    reduce_ep<<<512, 256>>>(part, nullptr, nullptr, a3, 3);

    // ---- mixup + MHA mix (nh=2) ----
    mix_kernel<<<512, 256>>>(a1, a3, perm, lam, m1, m3);
    gemm_nt<<<dim3(128, 12), 256>>>(m1, Wqkv_mix, bqkv_mix, qkv0, nullptr, 384);
    gemm_nt<<<dim3(128, 12), 256>>>(m3, Wqkv_mix, bqkv_mix, qkv1, nullptr, 384);
    attn_kernel<<<512, 256>>>(qkv0, qkv1, om, 2);
    gemm_nt<<<dim3(128, 4), 256>>>(om, Wo_mix, bo_mix, hmix, nullptr, 128);

    // ---- h2m = relu(G1 @ (hmix@W2m+b2m) + hmix) ----
    gemm_small<<<128, 128>>>(hmix, W2m, b2m, t, 128, 0);
    conv_trans<<<dim3(128, 4), dim3(32, 8)>>>(t, 128, 0, Bth, Btl, 0);
    gemm_mma<<<dim3(32, SPLITK, 1), 256, GEMM_SMEM>>>(G1h, G1l, Bth, Btl, part);
    reduce_ep<<<512, 256>>>(part, hmix, nullptr, h2m, 1);

    // ---- h3c2 = relu(G1 @ (h2m@W3m+b3m) + h2m) * beta ----
    gemm_small<<<128, 128>>>(h2m, W3m, b3m, t, 128, 0);
    conv_trans<<<dim3(128, 4), dim3(32, 8)>>>(t, 128, 0, Bth, Btl, 0);
    gemm_mma<<<dim3(32, SPLITK, 1), 256, GEMM_SMEM>>>(G1h, G1l, Bth, Btl, part);
    reduce_ep<<<512, 256>>>(part, h2m, beta, h3c2, 4);

    // ---- MHA fus (nh=4) ----
    gemm_nt<<<dim3(128, 12), 256>>>(h3c1, Wqkv_fus, bqkv_fus, qkv0, nullptr, 384);
    gemm_nt<<<dim3(128, 12), 256>>>(h3c2, Wqkv_fus, bqkv_fus, qkv1, nullptr, 384);
    attn_kernel<<<512, 256>>>(qkv0, qkv1, om, 4);
    gemm_nt<<<dim3(128, 4), 256>>>(om, Wo_fus, bo_fus, h3, out_h3, 128);

    // ---- edge classifier ----
    edge_kernel<<<512, 256>>>(h3, ei, Wc, bc, out_edge);
}

// round 8
// speedup vs baseline: 4.4638x; 1.0614x over previous
#include <cuda_runtime.h>
#include <cuda_bf16.h>
#include <cstdint>

#define N_NODES 4096
#define HDIM    128
#define N_EDGES 131072
#define KTOT    4096
#define SPLITK  8
#define KCTA    (KTOT / SPLITK)     // 512
#define BK      32
#define NCH     (KCTA / BK)         // 16

// ---------------- scratch (static device arrays; no allocation) ----------------
__device__ float g_h1[N_NODES * 128];
__device__ float g_h2[N_NODES * 128];
__device__ float g_h3c1[N_NODES * 128];
__device__ float g_a1[N_NODES * 128];
__device__ float g_a3[N_NODES * 128];
__device__ float g_m1[N_NODES * 128];
__device__ float g_m3[N_NODES * 128];
__device__ float g_qkv0[N_NODES * 384];
__device__ float g_qkv1[N_NODES * 384];
__device__ float g_om[N_NODES * 128];
__device__ float g_hmix[N_NODES * 128];
__device__ float g_h2m[N_NODES * 128];
__device__ float g_h3c2[N_NODES * 128];
__device__ float g_h3[N_NODES * 128];
// bf16 split of the dense propagation matrices
__device__ __nv_bfloat16 g_G1h[(size_t)KTOT * KTOT];
__device__ __nv_bfloat16 g_G1l[(size_t)KTOT * KTOT];
__device__ __nv_bfloat16 g_G3h[(size_t)KTOT * KTOT];
__device__ __nv_bfloat16 g_G3l[(size_t)KTOT * KTOT];
// transposed bf16 split of RHS (up to 384 rows x 4096 cols, row = output col)
__device__ __nv_bfloat16 g_Bth[384 * KTOT];
__device__ __nv_bfloat16 g_Btl[384 * KTOT];
// split-K partials [3][SPLITK][4096][128]
__device__ float g_part[(size_t)3 * SPLITK * N_NODES * 128];

// ============================ asm helpers =================================
__device__ __forceinline__ uint32_t smem_to_u32(const void* p) {
    uint32_t a;
    asm("{ .reg .u64 t; cvta.to.shared.u64 t, %1; cvt.u32.u64 %0, t; }" : "=r"(a) : "l"(p));
    return a;
}
__device__ __forceinline__ void cp16(uint32_t s, const void* g) {
    asm volatile("cp.async.cg.shared.global [%0], [%1], 16;" :: "r"(s), "l"(g));
}
__device__ __forceinline__ void cp_commit() {
    asm volatile("cp.async.commit_group;" ::: "memory");
}
template <int Ng>
__device__ __forceinline__ void cp_wait() {
    asm volatile("cp.async.wait_group %0;" :: "n"(Ng) : "memory");
}
__device__ __forceinline__ void ldsm4(uint32_t* r, uint32_t addr) {
    asm volatile("ldmatrix.sync.aligned.m8n8.x4.shared.b16 {%0,%1,%2,%3}, [%4];"
        : "=r"(r[0]), "=r"(r[1]), "=r"(r[2]), "=r"(r[3]) : "r"(addr));
}
__device__ __forceinline__ void mma16816(float* d, const uint32_t* a, uint32_t b0, uint32_t b1) {
    asm volatile(
        "mma.sync.aligned.m16n8k16.row.col.f32.bf16.bf16.f32 "
        "{%0,%1,%2,%3}, {%4,%5,%6,%7}, {%8,%9}, {%0,%1,%2,%3};"
        : "+f"(d[0]), "+f"(d[1]), "+f"(d[2]), "+f"(d[3])
        : "r"(a[0]), "r"(a[1]), "r"(a[2]), "r"(a[3]), "r"(b0), "r"(b1));
}

// ===========================================================================
// Big tensor-core GEMM via mma.sync:
// Part[z][ks][4096][128] = Ah@Bh^T + Ah@Bl^T + Al@Bh^T over K range of ks.
// z = blockIdx.z selects B rows z*128.. and (z==2 ? operand pair 1 : pair 0).
// CTA tile 128x128, BK=32, 8 warps (4x2), warp tile 32x64, 2-stage cp.async.
// ===========================================================================
#define TSTRIDE 80                    // bytes per smem row (32 bf16 + 8 pad)
#define TILE_B  (128 * TSTRIDE)       // 10240 B per operand tile
#define STAGE   (4 * TILE_B)          // Ah | Al | Bh | Bl
#define GEMM_SMEM (2 * STAGE)         // 81920 B

__global__ __launch_bounds__(256, 2) void gemm_mma(
    const __nv_bfloat16* __restrict__ Ah0, const __nv_bfloat16* __restrict__ Al0,
    const __nv_bfloat16* __restrict__ Ah1, const __nv_bfloat16* __restrict__ Al1,
    const __nv_bfloat16* __restrict__ Bh, const __nv_bfloat16* __restrict__ Bl,
    float* __restrict__ Part)
{
    extern __shared__ char smraw[];
    const uint32_t sm0 = smem_to_u32(smraw);

    const int tid = threadIdx.x;
    const int lane = tid & 31, wid = tid >> 5;
    const int wm = wid >> 1, wn = wid & 1;
    const int m0 = blockIdx.x * 128;
    const int ks = blockIdx.y;
    const int z  = blockIdx.z;
    const int kb = ks * KCTA;

    const __nv_bfloat16* Ah = (z == 2) ? Ah1 : Ah0;
    const __nv_bfloat16* Al = (z == 2) ? Al1 : Al0;

    const __nv_bfloat16* gAh = Ah + (size_t)m0 * KTOT + kb;
    const __nv_bfloat16* gAl = Al + (size_t)m0 * KTOT + kb;
    const __nv_bfloat16* gBh = Bh + (size_t)(z * 128) * KTOT + kb;
    const __nv_bfloat16* gBl = Bl + (size_t)(z * 128) * KTOT + kb;

    // per-thread staging slots: idx 0..511 -> row=idx>>2, 16B chunk c=idx&3
    const int r0i = tid >> 2, c0i = tid & 3;
    const int r1i = (tid + 256) >> 2, c1i = tid & 3;
    const uint32_t so0 = (uint32_t)r0i * TSTRIDE + c0i * 16;
    const uint32_t so1 = (uint32_t)r1i * TSTRIDE + c1i * 16;

    // ldmatrix lane addressing
    const uint32_t aO = (uint32_t)(wm * 32 + (lane & 15)) * TSTRIDE + (lane >> 4) * 16;
    const uint32_t bO = (uint32_t)(wn * 64 + (lane & 7) + ((lane >> 4) & 1) * 8) * TSTRIDE
                      + ((lane >> 3) & 1) * 16;

    float acc[2][8][4];
#pragma unroll
    for (int i = 0; i < 2; i++)
#pragma unroll
        for (int j = 0; j < 8; j++)
#pragma unroll
            for (int q = 0; q < 4; q++) acc[i][j][q] = 0.0f;

#define LOAD_CHUNK(ci, s) do { \
    uint32_t sbase = sm0 + (s) * STAGE; \
    size_t g0 = (size_t)r0i * KTOT + (ci) * BK + c0i * 8; \
    size_t g1 = (size_t)r1i * KTOT + (ci) * BK + c1i * 8; \
    cp16(sbase + so0,              gAh + g0); \
    cp16(sbase + so1,              gAh + g1); \
    cp16(sbase + TILE_B + so0,     gAl + g0); \
    cp16(sbase + TILE_B + so1,     gAl + g1); \
    cp16(sbase + 2 * TILE_B + so0, gBh + g0); \
    cp16(sbase + 2 * TILE_B + so1, gBh + g1); \
    cp16(sbase + 3 * TILE_B + so0, gBl + g0); \
    cp16(sbase + 3 * TILE_B + so1, gBl + g1); \
} while (0)

    LOAD_CHUNK(0, 0);
    cp_commit();

    for (int ci = 0; ci < NCH; ++ci) {
        if (ci + 1 < NCH) { LOAD_CHUNK(ci + 1, (ci + 1) & 1); cp_commit(); }
        if (ci + 1 < NCH) cp_wait<1>(); else cp_wait<0>();
        __syncthreads();

        const uint32_t sb = sm0 + (ci & 1) * STAGE;
#pragma unroll
        for (int kk = 0; kk < 2; ++kk) {
            const uint32_t ko = kk * 32;    // 16 bf16 = 32 B
            uint32_t ah[2][4], al[2][4], bf[4][4];
            ldsm4(ah[0], sb + aO + ko);
            ldsm4(ah[1], sb + aO + 16 * TSTRIDE + ko);
            ldsm4(al[0], sb + TILE_B + aO + ko);
            ldsm4(al[1], sb + TILE_B + aO + 16 * TSTRIDE + ko);
#pragma unroll
            for (int j = 0; j < 4; j++)
                ldsm4(bf[j], sb + 2 * TILE_B + bO + j * 16 * TSTRIDE + ko);
#pragma unroll
            for (int i = 0; i < 2; i++)
#pragma unroll
                for (int j = 0; j < 4; j++) {
                    mma16816(acc[i][2 * j],     ah[i], bf[j][0], bf[j][1]);
                    mma16816(acc[i][2 * j + 1], ah[i], bf[j][2], bf[j][3]);
                }
#pragma unroll
            for (int i = 0; i < 2; i++)
#pragma unroll
                for (int j = 0; j < 4; j++) {
                    mma16816(acc[i][2 * j],     al[i], bf[j][0], bf[j][1]);
                    mma16816(acc[i][2 * j + 1], al[i], bf[j][2], bf[j][3]);
                }
#pragma unroll
            for (int j = 0; j < 4; j++)
                ldsm4(bf[j], sb + 3 * TILE_B + bO + j * 16 * TSTRIDE + ko);
#pragma unroll
            for (int i = 0; i < 2; i++)
#pragma unroll
                for (int j = 0; j < 4; j++) {
                    mma16816(acc[i][2 * j],     ah[i], bf[j][0], bf[j][1]);
                    mma16816(acc[i][2 * j + 1], ah[i], bf[j][2], bf[j][3]);
                }
        }
        __syncthreads();
    }

    // epilogue: write fp32 partial tile
    float* outp = Part + ((size_t)(z * SPLITK + ks) * N_NODES + m0) * 128;
    const int rr = lane >> 2, c2 = (lane & 3) * 2;
#pragma unroll
    for (int i = 0; i < 2; i++) {
        const int row0 = wm * 32 + i * 16 + rr;
#pragma unroll
        for (int j = 0; j < 8; j++) {
            const int col = wn * 64 + j * 8 + c2;
            *(float2*)(outp + (size_t)row0 * 128 + col)       = make_float2(acc[i][j][0], acc[i][j][1]);
            *(float2*)(outp + (size_t)(row0 + 8) * 128 + col) = make_float2(acc[i][j][2], acc[i][j][3]);
        }
    }
#undef LOAD_CHUNK
}

// ---------------------------------------------------------------------------
// reduce SPLITK partials + epilogue; up to 3 outputs via grid.y.
// mode 0: relu(z); 1: relu(z+res); 3: z; 4: relu(z+res)*scale
// ---------------------------------------------------------------------------
__global__ __launch_bounds__(256) void reduce_ep(
    const float* __restrict__ P,
    const float* __restrict__ resA, const float* __restrict__ resB, const float* __restrict__ resC,
    const float* __restrict__ scale_p,
    float* __restrict__ CA, float* __restrict__ CB, float* __restrict__ CC,
    int mA, int mB, int mC)
{
    const int y = blockIdx.y;
    const float* res = (y == 0) ? resA : (y == 1) ? resB : resC;
    float* C         = (y == 0) ? CA   : (y == 1) ? CB   : CC;
    const int mode   = (y == 0) ? mA   : (y == 1) ? mB   : mC;

    int i = blockIdx.x * 256 + threadIdx.x;       // float4 index, 131072 per slot
    const float4* p = (const float4*)P + (size_t)y * SPLITK * 131072;
    float4 z = p[i];
#pragma unroll
    for (int s = 1; s < SPLITK; s++) {
        float4 a = p[i + (size_t)s * 131072];
        z.x += a.x; z.y += a.y; z.z += a.z; z.w += a.w;
    }
    if (mode == 1 || mode == 4) {
        float4 r = ((const float4*)res)[i];
        z.x += r.x; z.y += r.y; z.z += r.z; z.w += r.w;
    }
    if (mode != 3) {
        z.x = fmaxf(z.x, 0.0f); z.y = fmaxf(z.y, 0.0f);
        z.z = fmaxf(z.z, 0.0f); z.w = fmaxf(z.w, 0.0f);
    }
    if (mode == 4) {
        float s = *scale_p;
        z.x *= s; z.y *= s; z.z *= s; z.w *= s;
    }
    ((float4*)C)[i] = z;
}

// ---------------------------------------------------------------------------
// Split fp32 -> bf16 hi/lo (elementwise, float4 granularity)
// ---------------------------------------------------------------------------
__global__ __launch_bounds__(256) void conv_split(
    const float* __restrict__ X, __nv_bfloat16* __restrict__ Xh,
    __nv_bfloat16* __restrict__ Xl)
{
    size_t i = (size_t)blockIdx.x * 256 + threadIdx.x;
    float4 v = ((const float4*)X)[i];
    __nv_bfloat16 hx = __float2bfloat16(v.x);
    __nv_bfloat16 hy = __float2bfloat16(v.y);
    __nv_bfloat16 hz = __float2bfloat16(v.z);
    __nv_bfloat16 hw = __float2bfloat16(v.w);
    __nv_bfloat16 lx = __float2bfloat16(v.x - __bfloat162float(hx));
    __nv_bfloat16 ly = __float2bfloat16(v.y - __bfloat162float(hy));
    __nv_bfloat16 lz = __float2bfloat16(v.z - __bfloat162float(hz));
    __nv_bfloat16 lw = __float2bfloat16(v.w - __bfloat162float(hw));
    union { __nv_bfloat16 b[4]; uint2 u; } H, L;
    H.b[0] = hx; H.b[1] = hy; H.b[2] = hz; H.b[3] = hw;
    L.b[0] = lx; L.b[1] = ly; L.b[2] = lz; L.b[3] = lw;
    ((uint2*)Xh)[i] = H.u;
    ((uint2*)Xl)[i] = L.u;
}

// ---------------------------------------------------------------------------
// Small NN GEMM (K=128) + FUSED transpose/split epilogue:
// Z = A[4096,128] @ B[128,128] + bias;  Bt[ro+n][k] = split(Z[k][n])
// grid 128 (k-tiles of 32), block 128.
// ---------------------------------------------------------------------------
__global__ __launch_bounds__(128, 1) void gemm_smallT(
    const float* __restrict__ A,
    const float* __restrict__ B,
    const float* __restrict__ bias,
    __nv_bfloat16* __restrict__ Bth, __nv_bfloat16* __restrict__ Btl,
    int ro)
{
    __shared__ float As[32 * 33];
    __shared__ float Bs[32 * 128];
    __shared__ float Cs[128 * 33];   // [n][k_local]
    const int t = threadIdx.x;
    const int m0 = blockIdx.x * 32;
    const int tr = t >> 4, tc = t & 15;
    const int am = t >> 2, ak = (t & 3) * 8;

    float acc[4][8];
#pragma unroll
    for (int r = 0; r < 4; r++)
#pragma unroll
        for (int c = 0; c < 8; c++) acc[r][c] = 0.0f;

    const float* Ap = A + (size_t)(m0 + am) * 128 + ak;
    float4 a0, a1, bb[8];

    a0 = *(const float4*)(Ap);
    a1 = *(const float4*)(Ap + 4);
#pragma unroll
    for (int j = 0; j < 8; j++) {
        int f = t + j * 128;
        bb[j] = *(const float4*)(B + (size_t)(f >> 5) * 128 + (f & 31) * 4);
    }
    As[(ak + 0) * 33 + am] = a0.x; As[(ak + 1) * 33 + am] = a0.y;
    As[(ak + 2) * 33 + am] = a0.z; As[(ak + 3) * 33 + am] = a0.w;
    As[(ak + 4) * 33 + am] = a1.x; As[(ak + 5) * 33 + am] = a1.y;
    As[(ak + 6) * 33 + am] = a1.z; As[(ak + 7) * 33 + am] = a1.w;
#pragma unroll
    for (int j = 0; j < 8; j++) {
        int f = t + j * 128;
        *(float4*)&Bs[(f >> 5) * 128 + (f & 31) * 4] = bb[j];
    }
    __syncthreads();

    for (int it = 1; it <= 4; ++it) {
        if (it < 4) {
            int k0 = it << 5;
            a0 = *(const float4*)(Ap + k0);
            a1 = *(const float4*)(Ap + k0 + 4);
#pragma unroll
            for (int j = 0; j < 8; j++) {
                int f = t + j * 128;
                bb[j] = *(const float4*)(B + (size_t)(k0 + (f >> 5)) * 128 + (f & 31) * 4);
            }
        }
#pragma unroll
        for (int k = 0; k < 32; ++k) {
            float av[4];
#pragma unroll
            for (int r = 0; r < 4; r++) av[r] = As[k * 33 + tr * 4 + r];
            float4 b0 = *(const float4*)&Bs[k * 128 + tc * 8];
            float4 b1 = *(const float4*)&Bs[k * 128 + tc * 8 + 4];
            float bv[8] = {b0.x, b0.y, b0.z, b0.w, b1.x, b1.y, b1.z, b1.w};
#pragma unroll
            for (int r = 0; r < 4; r++)
#pragma unroll
                for (int c = 0; c < 8; c++) acc[r][c] += av[r] * bv[c];
        }
        __syncthreads();
        if (it < 4) {
            As[(ak + 0) * 33 + am] = a0.x; As[(ak + 1) * 33 + am] = a0.y;
            As[(ak + 2) * 33 + am] = a0.z; As[(ak + 3) * 33 + am] = a0.w;
            As[(ak + 4) * 33 + am] = a1.x; As[(ak + 5) * 33 + am] = a1.y;
            As[(ak + 6) * 33 + am] = a1.z; As[(ak + 7) * 33 + am] = a1.w;
#pragma unroll
            for (int j = 0; j < 8; j++) {
                int f = t + j * 128;
                *(float4*)&Bs[(f >> 5) * 128 + (f & 31) * 4] = bb[j];
            }
            __syncthreads();
        }
    }

    // stage transposed (+bias) into smem: Cs[n][k]
#pragma unroll
    for (int r = 0; r < 4; r++)
#pragma unroll
        for (int c = 0; c < 8; c++) {
            int n = tc * 8 + c;
            Cs[n * 33 + tr * 4 + r] = acc[r][c] + bias[n];
        }
    __syncthreads();

    // each thread owns one n-row: split 32 k-values, pack, write
    {
        const int n = t;
        union { __nv_bfloat16 b[8]; uint4 u; } Hp, Lp;
        __nv_bfloat16* oh = Bth + (size_t)(ro + n) * KTOT + m0;
        __nv_bfloat16* ol = Btl + (size_t)(ro + n) * KTOT + m0;
#pragma unroll
        for (int g = 0; g < 4; g++) {
#pragma unroll
            for (int q = 0; q < 8; q++) {
                float v = Cs[n * 33 + g * 8 + q];
                __nv_bfloat16 h = __float2bfloat16(v);
                Hp.b[q] = h;
                Lp.b[q] = __float2bfloat16(v - __bfloat162float(h));
            }
            *(uint4*)(oh + g * 8) = Hp.u;
            *(uint4*)(ol + g * 8) = Lp.u;
        }
    }
}

// ---------------------------------------------------------------------------
// NT GEMM: C[M, No] = A[M,128] @ W[No,128]^T + bias. grid.z selects (A,C) pair.
// ---------------------------------------------------------------------------
__global__ __launch_bounds__(256) void gemm_nt(
    const float* __restrict__ A0, const float* __restrict__ A1,
    const float* __restrict__ W,
    const float* __restrict__ bias, float* __restrict__ C0, float* __restrict__ C1,
    float* __restrict__ Cdup, int No)
{
    __shared__ float As[32 * 129];
    __shared__ float Ws[32 * 129];
    const int t = threadIdx.x;
    const int m0 = blockIdx.x * 32, n0 = blockIdx.y * 32;
    const float* A = blockIdx.z ? A1 : A0;
    float* C = blockIdx.z ? C1 : C0;

    for (int i = t; i < 32 * 128; i += 256) {
        int r = i >> 7, k = i & 127;
        As[r * 129 + k] = A[(size_t)(m0 + r) * 128 + k];
        Ws[r * 129 + k] = W[(size_t)(n0 + r) * 128 + k];
    }
    __syncthreads();

    const int tr = t >> 4, tc = t & 15;
    const float* a0p = &As[(tr * 2) * 129];
    const float* a1p = &As[(tr * 2 + 1) * 129];
    const float* w0p = &Ws[(tc * 2) * 129];
    const float* w1p = &Ws[(tc * 2 + 1) * 129];

    float acc00 = 0, acc01 = 0, acc10 = 0, acc11 = 0;
#pragma unroll 16
    for (int k = 0; k < 128; k++) {
        float a0 = a0p[k], a1 = a1p[k], w0 = w0p[k], w1 = w1p[k];
        acc00 += a0 * w0; acc01 += a0 * w1;
        acc10 += a1 * w0; acc11 += a1 * w1;
    }
    int row0 = m0 + tr * 2, col0 = n0 + tc * 2;
    float v00 = acc00 + bias[col0], v01 = acc01 + bias[col0 + 1];
    float v10 = acc10 + bias[col0], v11 = acc11 + bias[col0 + 1];
    C[(size_t)row0 * No + col0]           = v00;
    C[(size_t)row0 * No + col0 + 1]       = v01;
    C[(size_t)(row0 + 1) * No + col0]     = v10;
    C[(size_t)(row0 + 1) * No + col0 + 1] = v11;
    if (Cdup && blockIdx.z == 0) {
        Cdup[(size_t)row0 * No + col0]           = v00;
        Cdup[(size_t)row0 * No + col0 + 1]       = v01;
        Cdup[(size_t)(row0 + 1) * No + col0]     = v10;
        Cdup[(size_t)(row0 + 1) * No + col0 + 1] = v11;
    }
}

// ---------------------------------------------------------------------------
__global__ void mix_kernel(const float* __restrict__ a1, const float* __restrict__ a3,
                           const int* __restrict__ perm, const float* __restrict__ lam,
                           float* __restrict__ m1, float* __restrict__ m3)
{
    int i = blockIdx.x * blockDim.x + threadIdx.x;
    int row = i >> 5, q = i & 31;
    float l = lam[0], il = 1.0f - l;
    int pr = perm[row];
    float4 x = ((const float4*)a1)[row * 32 + q];
    float4 y = ((const float4*)a1)[pr * 32 + q];
    float4 o;
    o.x = l * x.x + il * y.x; o.y = l * x.y + il * y.y;
    o.z = l * x.z + il * y.z; o.w = l * x.w + il * y.w;
    ((float4*)m1)[row * 32 + q] = o;
    x = ((const float4*)a3)[row * 32 + q];
    y = ((const float4*)a3)[pr * 32 + q];
    o.x = l * x.x + il * y.x; o.y = l * x.y + il * y.y;
    o.z = l * x.z + il * y.z; o.w = l * x.w + il * y.w;
    ((float4*)m3)[row * 32 + q] = o;
}

__global__ void attn_kernel(const float* __restrict__ qkv0, const float* __restrict__ qkv1,
                            float* __restrict__ om, int nh)
{
    int gt = blockIdx.x * blockDim.x + threadIdx.x;
    int node = gt >> 5;
    int lane = gt & 31;
    const float4* p0 = (const float4*)(qkv0 + (size_t)node * 384);
    const float4* p1 = (const float4*)(qkv1 + (size_t)node * 384);
    float4 q0 = p0[lane], k0 = p0[32 + lane], v0 = p0[64 + lane];
    float4 q1 = p1[lane], k1 = p1[32 + lane], v1 = p1[64 + lane];

    float p00 = q0.x * k0.x + q0.y * k0.y + q0.z * k0.z + q0.w * k0.w;
    float p01 = q0.x * k1.x + q0.y * k1.y + q0.z * k1.z + q0.w * k1.w;
    float p10 = q1.x * k0.x + q1.y * k0.y + q1.z * k0.z + q1.w * k0.w;
    float p11 = q1.x * k1.x + q1.y * k1.y + q1.z * k1.z + q1.w * k1.w;

    int hd = 128 / nh;
    int Wd = hd >> 2;
    for (int off = Wd >> 1; off; off >>= 1) {
        p00 += __shfl_xor_sync(0xffffffffu, p00, off);
        p01 += __shfl_xor_sync(0xffffffffu, p01, off);
        p10 += __shfl_xor_sync(0xffffffffu, p10, off);
        p11 += __shfl_xor_sync(0xffffffffu, p11, off);
    }
    float scl = rsqrtf((float)hd);
    float s00 = p00 * scl, s01 = p01 * scl, s10 = p10 * scl, s11 = p11 * scl;

    float mx0 = fmaxf(s00, s01);
    float e00 = expf(s00 - mx0), e01 = expf(s01 - mx0);
    float r0 = 1.0f / (e00 + e01);
    float mx1 = fmaxf(s10, s11);
    float e10 = expf(s10 - mx1), e11 = expf(s11 - mx1);
    float r1 = 1.0f / (e10 + e11);

    float c0 = 0.5f * (e00 * r0 + e10 * r1);
    float c1 = 0.5f * (e01 * r0 + e11 * r1);

    float4 o;
    o.x = c0 * v0.x + c1 * v1.x;
    o.y = c0 * v0.y + c1 * v1.y;
    o.z = c0 * v0.z + c1 * v1.z;
    o.w = c0 * v0.w + c1 * v1.w;
    ((float4*)(om + (size_t)node * 128))[lane] = o;
}

__global__ __launch_bounds__(256) void edge_kernel(
    const float* __restrict__ h3, const int* __restrict__ ei,
    const float* __restrict__ Wc, const float* __restrict__ bc,
    float* __restrict__ out)
{
    __shared__ float wcs[512];
    __shared__ float bcs[2];
    int t = threadIdx.x;
    for (int i = t; i < 512; i += 256) wcs[i] = Wc[i];
    if (t < 2) bcs[t] = bc[t];
    __syncthreads();

    int e = blockIdx.x * 256 + t;
    int i0 = ei[e], i1 = ei[N_EDGES + e];
    const float4* r0 = (const float4*)(h3 + (size_t)i0 * 128);
    const float4* r1 = (const float4*)(h3 + (size_t)i1 * 128);
    float acc0 = bcs[0], acc1 = bcs[1];
#pragma unroll 8
    for (int q = 0; q < 32; q++) {
        float4 f = r0[q];
        int d = q * 4;
        acc0 += f.x * wcs[2 * d] + f.y * wcs[2 * (d + 1)] + f.z * wcs[2 * (d + 2)] + f.w * wcs[2 * (d + 3)];
        acc1 += f.x * wcs[2 * d + 1] + f.y * wcs[2 * (d + 1) + 1] + f.z * wcs[2 * (d + 2) + 1] + f.w * wcs[2 * (d + 3) + 1];
    }
#pragma unroll 8
    for (int q = 0; q < 32; q++) {
        float4 f = r1[q];
        int d = 128 + q * 4;
        acc0 += f.x * wcs[2 * d] + f.y * wcs[2 * (d + 1)] + f.z * wcs[2 * (d + 2)] + f.w * wcs[2 * (d + 3)];
        acc1 += f.x * wcs[2 * d + 1] + f.y * wcs[2 * (d + 1) + 1] + f.z * wcs[2 * (d + 2) + 1] + f.w * wcs[2 * (d + 3) + 1];
    }
    out[(size_t)e * 2]     = acc0;
    out[(size_t)e * 2 + 1] = acc1;
}

// ---------------------------------------------------------------------------
extern "C" void kernel_launch(void* const* d_in, const int* in_sizes, int n_in,
                              void* d_out, int out_size)
{
    const float* x    = (const float*)d_in[0];
    const float* G1   = (const float*)d_in[1];
    const float* G3   = (const float*)d_in[2];
    const int*   ei   = (const int*)d_in[3];
    const int*   perm = (const int*)d_in[4];
    const float* lam  = (const float*)d_in[5];
    const float* beta = (const float*)d_in[6];
    const float* W1 = (const float*)d_in[7];   const float* b1 = (const float*)d_in[8];
    const float* W2 = (const float*)d_in[9];   const float* b2 = (const float*)d_in[10];
    const float* W3 = (const float*)d_in[11];  const float* b3 = (const float*)d_in[12];
    const float* W1h = (const float*)d_in[13]; const float* b1h = (const float*)d_in[14];
    const float* W3h = (const float*)d_in[15]; const float* b3h = (const float*)d_in[16];
    const float* W2m = (const float*)d_in[17]; const float* b2m = (const float*)d_in[18];
    const float* W3m = (const float*)d_in[19]; const float* b3m = (const float*)d_in[20];
    const float* Wqkv_mix = (const float*)d_in[21]; const float* bqkv_mix = (const float*)d_in[22];
    const float* Wo_mix   = (const float*)d_in[23]; const float* bo_mix   = (const float*)d_in[24];
    const float* Wqkv_fus = (const float*)d_in[25]; const float* bqkv_fus = (const float*)d_in[26];
    const float* Wo_fus   = (const float*)d_in[27]; const float* bo_fus   = (const float*)d_in[28];
    const float* Wc = (const float*)d_in[29];  const float* bc = (const float*)d_in[30];

    float *h1, *h2, *h3c1, *a1, *a3, *m1, *m3, *qkv0, *qkv1, *om, *hmix, *h2m, *h3c2, *h3;
    float* part;
    __nv_bfloat16 *G1h, *G1l, *G3h, *G3l, *Bth, *Btl;
    cudaGetSymbolAddress((void**)&h1, g_h1);
    cudaGetSymbolAddress((void**)&h2, g_h2);
    cudaGetSymbolAddress((void**)&h3c1, g_h3c1);
    cudaGetSymbolAddress((void**)&a1, g_a1);
    cudaGetSymbolAddress((void**)&a3, g_a3);
    cudaGetSymbolAddress((void**)&m1, g_m1);
    cudaGetSymbolAddress((void**)&m3, g_m3);
    cudaGetSymbolAddress((void**)&qkv0, g_qkv0);
    cudaGetSymbolAddress((void**)&qkv1, g_qkv1);
    cudaGetSymbolAddress((void**)&om, g_om);
    cudaGetSymbolAddress((void**)&hmix, g_hmix);
    cudaGetSymbolAddress((void**)&h2m, g_h2m);
    cudaGetSymbolAddress((void**)&h3c2, g_h3c2);
    cudaGetSymbolAddress((void**)&h3, g_h3);
    cudaGetSymbolAddress((void**)&part, g_part);
    cudaGetSymbolAddress((void**)&G1h, g_G1h);
    cudaGetSymbolAddress((void**)&G1l, g_G1l);
    cudaGetSymbolAddress((void**)&G3h, g_G3h);
    cudaGetSymbolAddress((void**)&G3l, g_G3l);
    cudaGetSymbolAddress((void**)&Bth, g_Bth);
    cudaGetSymbolAddress((void**)&Btl, g_Btl);

    cudaFuncSetAttribute(gemm_mma, cudaFuncAttributeMaxDynamicSharedMemorySize, GEMM_SMEM);

    float* out_edge = (float*)d_out;
    float* out_h3   = out_edge + (size_t)N_EDGES * 2;

    // split G matrices into bf16 hi/lo (once per call)
    conv_split<<<16384, 256>>>(G1, G1h, G1l);
    conv_split<<<16384, 256>>>(G3, G3h, G3l);

    // ---- h1 = relu(G1 @ (x@W1+b1)) ----
    gemm_smallT<<<128, 128>>>(x, W1, b1, Bth, Btl, 0);
    gemm_mma<<<dim3(32, SPLITK, 1), 256, GEMM_SMEM>>>(G1h, G1l, G1h, G1l, Bth, Btl, part);
    reduce_ep<<<dim3(512, 1), 256>>>(part, nullptr, nullptr, nullptr, nullptr,
                                     h1, nullptr, nullptr, 0, 0, 0);

    // ---- h2 = relu(G1 @ (h1@W2+b2) + h1) ----
    gemm_smallT<<<128, 128>>>(h1, W2, b2, Bth, Btl, 0);
    gemm_mma<<<dim3(32, SPLITK, 1), 256, GEMM_SMEM>>>(G1h, G1l, G1h, G1l, Bth, Btl, part);
    reduce_ep<<<dim3(512, 1), 256>>>(part, h1, nullptr, nullptr, nullptr,
                                     h2, nullptr, nullptr, 1, 0, 0);

    // ---- merged pass: z0: G1@t3 (+h2, relu) -> h3c1; z1: G1@u1h -> a1; z2: G3@u3h -> a3 ----
    gemm_smallT<<<128, 128>>>(h2, W3, b3, Bth, Btl, 0);
    gemm_smallT<<<128, 128>>>(h1, W1h, b1h, Bth, Btl, 128);
    gemm_smallT<<<128, 128>>>(h1, W3h, b3h, Bth, Btl, 256);
    gemm_mma<<<dim3(32, SPLITK, 3), 256, GEMM_SMEM>>>(G1h, G1l, G3h, G3l, Bth, Btl, part);
    reduce_ep<<<dim3(512, 3), 256>>>(part, h2, nullptr, nullptr, nullptr,
                                     h3c1, a1, a3, 1, 3, 3);

    // ---- mixup + MHA mix (nh=2) ----
    mix_kernel<<<512, 256>>>(a1, a3, perm, lam, m1, m3);
    gemm_nt<<<dim3(128, 12, 2), 256>>>(m1, m3, Wqkv_mix, bqkv_mix, qkv0, qkv1, nullptr, 384);
    attn_kernel<<<512, 256>>>(qkv0, qkv1, om, 2);
    gemm_nt<<<dim3(128, 4, 1), 256>>>(om, nullptr, Wo_mix, bo_mix, hmix, nullptr, nullptr, 128);

    // ---- h2m = relu(G1 @ (hmix@W2m+b2m) + hmix) ----
    gemm_smallT<<<128, 128>>>(hmix, W2m, b2m, Bth, Btl, 0);
    gemm_mma<<<dim3(32, SPLITK, 1), 256, GEMM_SMEM>>>(G1h, G1l, G1h, G1l, Bth, Btl, part);
    reduce_ep<<<dim3(512, 1), 256>>>(part, hmix, nullptr, nullptr, nullptr,
                                     h2m, nullptr, nullptr, 1, 0, 0);

    // ---- h3c2 = relu(G1 @ (h2m@W3m+b3m) + h2m) * beta ----
    gemm_smallT<<<128, 128>>>(h2m, W3m, b3m, Bth, Btl, 0);
    gemm_mma<<<dim3(32, SPLITK, 1), 256, GEMM_SMEM>>>(G1h, G1l, G1h, G1l, Bth, Btl, part);
    reduce_ep<<<dim3(512, 1), 256>>>(part, h2m, nullptr, nullptr, beta,
                                     h3c2, nullptr, nullptr, 4, 0, 0);

    // ---- MHA fus (nh=4) ----
    gemm_nt<<<dim3(128, 12, 2), 256>>>(h3c1, h3c2, Wqkv_fus, bqkv_fus, qkv0, qkv1, nullptr, 384);
    attn_kernel<<<512, 256>>>(qkv0, qkv1, om, 4);
    gemm_nt<<<dim3(128, 4, 1), 256>>>(om, nullptr, Wo_fus, bo_fus, h3, nullptr, out_h3, 128);

    // ---- edge classifier ----
    edge_kernel<<<512, 256>>>(h3, ei, Wc, bc, out_edge);
}

// round 9
// speedup vs baseline: 5.2817x; 1.1832x over previous
#include <cuda_runtime.h>
#include <cuda_bf16.h>
#include <cstdint>

#define N_NODES 4096
#define HDIM    128
#define N_EDGES 131072
#define KTOT    4096
#define SPLITK  8
#define KCTA    (KTOT / SPLITK)     // 512
#define BK      32
#define NCH     (KCTA / BK)         // 16

// ---------------- scratch (static device arrays; no allocation) ----------------
__device__ float g_h1[N_NODES * 128];
__device__ float g_h2[N_NODES * 128];
__device__ float g_a1[N_NODES * 128];
__device__ float g_a3[N_NODES * 128];
__device__ float g_qkv0[N_NODES * 384];
__device__ float g_qkv1[N_NODES * 384];
__device__ float g_om[N_NODES * 128];
__device__ float g_hmix[N_NODES * 128];
__device__ float g_h2m[N_NODES * 128];
__device__ float g_h3[N_NODES * 128];
// bf16 split of the dense propagation matrices
__device__ __nv_bfloat16 g_G1h[(size_t)KTOT * KTOT];
__device__ __nv_bfloat16 g_G1l[(size_t)KTOT * KTOT];
__device__ __nv_bfloat16 g_G3h[(size_t)KTOT * KTOT];
__device__ __nv_bfloat16 g_G3l[(size_t)KTOT * KTOT];
// transposed bf16 split of RHS (up to 384 rows x 4096 cols, row = output col)
__device__ __nv_bfloat16 g_Bth[384 * KTOT];
__device__ __nv_bfloat16 g_Btl[384 * KTOT];
// bf16 hi/lo A-operands for the K=128 HMMA (qkv) kernels
__device__ __nv_bfloat16 g_p0h[N_NODES * 128];
__device__ __nv_bfloat16 g_p0l[N_NODES * 128];
__device__ __nv_bfloat16 g_p1h[N_NODES * 128];
__device__ __nv_bfloat16 g_p1l[N_NODES * 128];
// bf16 hi/lo of qkv weight [384,128]
__device__ __nv_bfloat16 g_wh[384 * 128];
__device__ __nv_bfloat16 g_wl[384 * 128];
// split-K partials [3][SPLITK][4096][128]
__device__ float g_part[(size_t)3 * SPLITK * N_NODES * 128];

// ============================ asm helpers =================================
__device__ __forceinline__ uint32_t smem_to_u32(const void* p) {
    uint32_t a;
    asm("{ .reg .u64 t; cvta.to.shared.u64 t, %1; cvt.u32.u64 %0, t; }" : "=r"(a) : "l"(p));
    return a;
}
__device__ __forceinline__ void cp16(uint32_t s, const void* g) {
    asm volatile("cp.async.cg.shared.global [%0], [%1], 16;" :: "r"(s), "l"(g));
}
__device__ __forceinline__ void cp_commit() {
    asm volatile("cp.async.commit_group;" ::: "memory");
}
template <int Ng>
__device__ __forceinline__ void cp_wait() {
    asm volatile("cp.async.wait_group %0;" :: "n"(Ng) : "memory");
}
__device__ __forceinline__ void ldsm4(uint32_t* r, uint32_t addr) {
    asm volatile("ldmatrix.sync.aligned.m8n8.x4.shared.b16 {%0,%1,%2,%3}, [%4];"
        : "=r"(r[0]), "=r"(r[1]), "=r"(r[2]), "=r"(r[3]) : "r"(addr));
}
__device__ __forceinline__ void mma16816(float* d, const uint32_t* a, uint32_t b0, uint32_t b1) {
    asm volatile(
        "mma.sync.aligned.m16n8k16.row.col.f32.bf16.bf16.f32 "
        "{%0,%1,%2,%3}, {%4,%5,%6,%7}, {%8,%9}, {%0,%1,%2,%3};"
        : "+f"(d[0]), "+f"(d[1]), "+f"(d[2]), "+f"(d[3])
        : "r"(a[0]), "r"(a[1]), "r"(a[2]), "r"(a[3]), "r"(b0), "r"(b1));
}
__device__ __forceinline__ void split2(float v, __nv_bfloat16& h, __nv_bfloat16& l) {
    h = __float2bfloat16(v);
    l = __float2bfloat16(v - __bfloat162float(h));
}

// ===========================================================================
// Big tensor-core GEMM via mma.sync:
// Part[z][ks][4096][128] = Ah@Bh^T + Ah@Bl^T + Al@Bh^T over K range of ks.
// ===========================================================================
#define TSTRIDE 80                    // bytes per smem row (32 bf16 + 8 pad)
#define TILE_B  (128 * TSTRIDE)       // 10240 B per operand tile
#define STAGE   (4 * TILE_B)          // Ah | Al | Bh | Bl
#define GEMM_SMEM (2 * STAGE)         // 81920 B

__global__ __launch_bounds__(256, 2) void gemm_mma(
    const __nv_bfloat16* __restrict__ Ah0, const __nv_bfloat16* __restrict__ Al0,
    const __nv_bfloat16* __restrict__ Ah1, const __nv_bfloat16* __restrict__ Al1,
    const __nv_bfloat16* __restrict__ Bh, const __nv_bfloat16* __restrict__ Bl,
    float* __restrict__ Part)
{
    extern __shared__ char smraw[];
    const uint32_t sm0 = smem_to_u32(smraw);

    const int tid = threadIdx.x;
    const int lane = tid & 31, wid = tid >> 5;
    const int wm = wid >> 1, wn = wid & 1;
    const int m0 = blockIdx.x * 128;
    const int ks = blockIdx.y;
    const int z  = blockIdx.z;
    const int kb = ks * KCTA;

    const __nv_bfloat16* Ah = (z == 2) ? Ah1 : Ah0;
    const __nv_bfloat16* Al = (z == 2) ? Al1 : Al0;

    const __nv_bfloat16* gAh = Ah + (size_t)m0 * KTOT + kb;
    const __nv_bfloat16* gAl = Al + (size_t)m0 * KTOT + kb;
    const __nv_bfloat16* gBh = Bh + (size_t)(z * 128) * KTOT + kb;
    const __nv_bfloat16* gBl = Bl + (size_t)(z * 128) * KTOT + kb;

    const int r0i = tid >> 2, c0i = tid & 3;
    const int r1i = (tid + 256) >> 2, c1i = tid & 3;
    const uint32_t so0 = (uint32_t)r0i * TSTRIDE + c0i * 16;
    const uint32_t so1 = (uint32_t)r1i * TSTRIDE + c1i * 16;

    const uint32_t aO = (uint32_t)(wm * 32 + (lane & 15)) * TSTRIDE + (lane >> 4) * 16;
    const uint32_t bO = (uint32_t)(wn * 64 + (lane & 7) + ((lane >> 4) & 1) * 8) * TSTRIDE
                      + ((lane >> 3) & 1) * 16;

    float acc[2][8][4];
#pragma unroll
    for (int i = 0; i < 2; i++)
#pragma unroll
        for (int j = 0; j < 8; j++)
#pragma unroll
            for (int q = 0; q < 4; q++) acc[i][j][q] = 0.0f;

#define LOAD_CHUNK(ci, s) do { \
    uint32_t sbase = sm0 + (s) * STAGE; \
    size_t g0 = (size_t)r0i * KTOT + (ci) * BK + c0i * 8; \
    size_t g1 = (size_t)r1i * KTOT + (ci) * BK + c1i * 8; \
    cp16(sbase + so0,              gAh + g0); \
    cp16(sbase + so1,              gAh + g1); \
    cp16(sbase + TILE_B + so0,     gAl + g0); \
    cp16(sbase + TILE_B + so1,     gAl + g1); \
    cp16(sbase + 2 * TILE_B + so0, gBh + g0); \
    cp16(sbase + 2 * TILE_B + so1, gBh + g1); \
    cp16(sbase + 3 * TILE_B + so0, gBl + g0); \
    cp16(sbase + 3 * TILE_B + so1, gBl + g1); \
} while (0)

    LOAD_CHUNK(0, 0);
    cp_commit();

    for (int ci = 0; ci < NCH; ++ci) {
        if (ci + 1 < NCH) { LOAD_CHUNK(ci + 1, (ci + 1) & 1); cp_commit(); }
        if (ci + 1 < NCH) cp_wait<1>(); else cp_wait<0>();
        __syncthreads();

        const uint32_t sb = sm0 + (ci & 1) * STAGE;
#pragma unroll
        for (int kk = 0; kk < 2; ++kk) {
            const uint32_t ko = kk * 32;
            uint32_t ah[2][4], al[2][4], bf[4][4];
            ldsm4(ah[0], sb + aO + ko);
            ldsm4(ah[1], sb + aO + 16 * TSTRIDE + ko);
            ldsm4(al[0], sb + TILE_B + aO + ko);
            ldsm4(al[1], sb + TILE_B + aO + 16 * TSTRIDE + ko);
#pragma unroll
            for (int j = 0; j < 4; j++)
                ldsm4(bf[j], sb + 2 * TILE_B + bO + j * 16 * TSTRIDE + ko);
#pragma unroll
            for (int i = 0; i < 2; i++)
#pragma unroll
                for (int j = 0; j < 4; j++) {
                    mma16816(acc[i][2 * j],     ah[i], bf[j][0], bf[j][1]);
                    mma16816(acc[i][2 * j + 1], ah[i], bf[j][2], bf[j][3]);
                }
#pragma unroll
            for (int i = 0; i < 2; i++)
#pragma unroll
                for (int j = 0; j < 4; j++) {
                    mma16816(acc[i][2 * j],     al[i], bf[j][0], bf[j][1]);
                    mma16816(acc[i][2 * j + 1], al[i], bf[j][2], bf[j][3]);
                }
#pragma unroll
            for (int j = 0; j < 4; j++)
                ldsm4(bf[j], sb + 3 * TILE_B + bO + j * 16 * TSTRIDE + ko);
#pragma unroll
            for (int i = 0; i < 2; i++)
#pragma unroll
                for (int j = 0; j < 4; j++) {
                    mma16816(acc[i][2 * j],     ah[i], bf[j][0], bf[j][1]);
                    mma16816(acc[i][2 * j + 1], ah[i], bf[j][2], bf[j][3]);
                }
        }
        __syncthreads();
    }

    float* outp = Part + ((size_t)(z * SPLITK + ks) * N_NODES + m0) * 128;
    const int rr = lane >> 2, c2 = (lane & 3) * 2;
#pragma unroll
    for (int i = 0; i < 2; i++) {
        const int row0 = wm * 32 + i * 16 + rr;
#pragma unroll
        for (int j = 0; j < 8; j++) {
            const int col = wn * 64 + j * 8 + c2;
            *(float2*)(outp + (size_t)row0 * 128 + col)       = make_float2(acc[i][j][0], acc[i][j][1]);
            *(float2*)(outp + (size_t)(row0 + 8) * 128 + col) = make_float2(acc[i][j][2], acc[i][j][3]);
        }
    }
#undef LOAD_CHUNK
}

// ===========================================================================
// K=128 HMMA NT GEMM: C[4096, No] = A@W^T + bias (3-term bf16 split).
// A given as h/l pairs [4096,128]; W as h/l [No,128]. grid (32, No/128, 2).
// ===========================================================================
__global__ __launch_bounds__(256, 2) void hmma_nt128(
    const __nv_bfloat16* __restrict__ Ah0, const __nv_bfloat16* __restrict__ Al0,
    const __nv_bfloat16* __restrict__ Ah1, const __nv_bfloat16* __restrict__ Al1,
    const __nv_bfloat16* __restrict__ Wh, const __nv_bfloat16* __restrict__ Wl,
    const float* __restrict__ bias,
    float* __restrict__ C0, float* __restrict__ C1, int No)
{
    extern __shared__ char smraw[];
    const uint32_t sm0 = smem_to_u32(smraw);

    const int tid = threadIdx.x;
    const int lane = tid & 31, wid = tid >> 5;
    const int wm = wid >> 1, wn = wid & 1;
    const int m0 = blockIdx.x * 128;
    const int n0 = blockIdx.y * 128;
    const int z  = blockIdx.z;

    const __nv_bfloat16* gAh = (z ? Ah1 : Ah0) + (size_t)m0 * 128;
    const __nv_bfloat16* gAl = (z ? Al1 : Al0) + (size_t)m0 * 128;
    const __nv_bfloat16* gBh = Wh + (size_t)n0 * 128;
    const __nv_bfloat16* gBl = Wl + (size_t)n0 * 128;
    float* C = z ? C1 : C0;

    const int r0i = tid >> 2, c0i = tid & 3;
    const int r1i = (tid + 256) >> 2, c1i = tid & 3;
    const uint32_t so0 = (uint32_t)r0i * TSTRIDE + c0i * 16;
    const uint32_t so1 = (uint32_t)r1i * TSTRIDE + c1i * 16;

    const uint32_t aO = (uint32_t)(wm * 32 + (lane & 15)) * TSTRIDE + (lane >> 4) * 16;
    const uint32_t bO = (uint32_t)(wn * 64 + (lane & 7) + ((lane >> 4) & 1) * 8) * TSTRIDE
                      + ((lane >> 3) & 1) * 16;

    float acc[2][8][4];
#pragma unroll
    for (int i = 0; i < 2; i++)
#pragma unroll
        for (int j = 0; j < 8; j++)
#pragma unroll
            for (int q = 0; q < 4; q++) acc[i][j][q] = 0.0f;

#define LOAD_CHUNK2(ci, s) do { \
    uint32_t sbase = sm0 + (s) * STAGE; \
    size_t g0 = (size_t)r0i * 128 + (ci) * BK + c0i * 8; \
    size_t g1 = (size_t)r1i * 128 + (ci) * BK + c1i * 8; \
    cp16(sbase + so0,              gAh + g0); \
    cp16(sbase + so1,              gAh + g1); \
    cp16(sbase + TILE_B + so0,     gAl + g0); \
    cp16(sbase + TILE_B + so1,     gAl + g1); \
    cp16(sbase + 2 * TILE_B + so0, gBh + g0); \
    cp16(sbase + 2 * TILE_B + so1, gBh + g1); \
    cp16(sbase + 3 * TILE_B + so0, gBl + g0); \
    cp16(sbase + 3 * TILE_B + so1, gBl + g1); \
} while (0)

    LOAD_CHUNK2(0, 0);
    cp_commit();

    for (int ci = 0; ci < 4; ++ci) {
        if (ci + 1 < 4) { LOAD_CHUNK2(ci + 1, (ci + 1) & 1); cp_commit(); }
        if (ci + 1 < 4) cp_wait<1>(); else cp_wait<0>();
        __syncthreads();

        const uint32_t sb = sm0 + (ci & 1) * STAGE;
#pragma unroll
        for (int kk = 0; kk < 2; ++kk) {
            const uint32_t ko = kk * 32;
            uint32_t ah[2][4], al[2][4], bf[4][4];
            ldsm4(ah[0], sb + aO + ko);
            ldsm4(ah[1], sb + aO + 16 * TSTRIDE + ko);
            ldsm4(al[0], sb + TILE_B + aO + ko);
            ldsm4(al[1], sb + TILE_B + aO + 16 * TSTRIDE + ko);
#pragma unroll
            for (int j = 0; j < 4; j++)
                ldsm4(bf[j], sb + 2 * TILE_B + bO + j * 16 * TSTRIDE + ko);
#pragma unroll
            for (int i = 0; i < 2; i++)
#pragma unroll
                for (int j = 0; j < 4; j++) {
                    mma16816(acc[i][2 * j],     ah[i], bf[j][0], bf[j][1]);
                    mma16816(acc[i][2 * j + 1], ah[i], bf[j][2], bf[j][3]);
                }
#pragma unroll
            for (int i = 0; i < 2; i++)
#pragma unroll
                for (int j = 0; j < 4; j++) {
                    mma16816(acc[i][2 * j],     al[i], bf[j][0], bf[j][1]);
                    mma16816(acc[i][2 * j + 1], al[i], bf[j][2], bf[j][3]);
                }
#pragma unroll
            for (int j = 0; j < 4; j++)
                ldsm4(bf[j], sb + 3 * TILE_B + bO + j * 16 * TSTRIDE + ko);
#pragma unroll
            for (int i = 0; i < 2; i++)
#pragma unroll
                for (int j = 0; j < 4; j++) {
                    mma16816(acc[i][2 * j],     ah[i], bf[j][0], bf[j][1]);
                    mma16816(acc[i][2 * j + 1], ah[i], bf[j][2], bf[j][3]);
                }
        }
        __syncthreads();
    }

    const int rr = lane >> 2, c2 = (lane & 3) * 2;
#pragma unroll
    for (int i = 0; i < 2; i++) {
        const int row0 = m0 + wm * 32 + i * 16 + rr;
#pragma unroll
        for (int j = 0; j < 8; j++) {
            const int col = n0 + wn * 64 + j * 8 + c2;
            const float b0 = bias[col], b1 = bias[col + 1];
            *(float2*)(C + (size_t)row0 * No + col)
                = make_float2(acc[i][j][0] + b0, acc[i][j][1] + b1);
            *(float2*)(C + (size_t)(row0 + 8) * No + col)
                = make_float2(acc[i][j][2] + b0, acc[i][j][3] + b1);
        }
    }
#undef LOAD_CHUNK2
}

// ---------------------------------------------------------------------------
// reduce SPLITK partials + epilogue; up to 3 outputs via grid.y.
// mode 0: relu(z); 1: relu(z+res); 3: z; 4: relu(z+res)*scale
// Optional bf16 hi/lo split outputs (Ch/Cl) instead of / besides fp32 C.
// ---------------------------------------------------------------------------
struct RedOut {
    float* C;
    __nv_bfloat16* Ch;
    __nv_bfloat16* Cl;
    const float* res;
    int mode;
};

__global__ __launch_bounds__(256) void reduce_ep(
    const float* __restrict__ P, const float* __restrict__ scale_p,
    RedOut o0, RedOut o1, RedOut o2)
{
    const int y = blockIdx.y;
    RedOut o = (y == 0) ? o0 : (y == 1) ? o1 : o2;

    int i = blockIdx.x * 256 + threadIdx.x;       // float4 index, 131072 per slot
    const float4* p = (const float4*)P + (size_t)y * SPLITK * 131072;
    float4 z = p[i];
#pragma unroll
    for (int s = 1; s < SPLITK; s++) {
        float4 a = p[i + (size_t)s * 131072];
        z.x += a.x; z.y += a.y; z.z += a.z; z.w += a.w;
    }
    if (o.mode == 1 || o.mode == 4) {
        float4 r = ((const float4*)o.res)[i];
        z.x += r.x; z.y += r.y; z.z += r.z; z.w += r.w;
    }
    if (o.mode != 3) {
        z.x = fmaxf(z.x, 0.0f); z.y = fmaxf(z.y, 0.0f);
        z.z = fmaxf(z.z, 0.0f); z.w = fmaxf(z.w, 0.0f);
    }
    if (o.mode == 4) {
        float s = *scale_p;
        z.x *= s; z.y *= s; z.z *= s; z.w *= s;
    }
    if (o.C) ((float4*)o.C)[i] = z;
    if (o.Ch) {
        union { __nv_bfloat16 b[4]; uint2 u; } H, L;
        split2(z.x, H.b[0], L.b[0]); split2(z.y, H.b[1], L.b[1]);
        split2(z.z, H.b[2], L.b[2]); split2(z.w, H.b[3], L.b[3]);
        ((uint2*)o.Ch)[i] = H.u;
        ((uint2*)o.Cl)[i] = L.u;
    }
}

// ---------------------------------------------------------------------------
// Split fp32 -> bf16 hi/lo (elementwise, float4 granularity)
// ---------------------------------------------------------------------------
__global__ __launch_bounds__(256) void conv_split(
    const float* __restrict__ X, __nv_bfloat16* __restrict__ Xh,
    __nv_bfloat16* __restrict__ Xl)
{
    size_t i = (size_t)blockIdx.x * 256 + threadIdx.x;
    float4 v = ((const float4*)X)[i];
    union { __nv_bfloat16 b[4]; uint2 u; } H, L;
    split2(v.x, H.b[0], L.b[0]); split2(v.y, H.b[1], L.b[1]);
    split2(v.z, H.b[2], L.b[2]); split2(v.w, H.b[3], L.b[3]);
    ((uint2*)Xh)[i] = H.u;
    ((uint2*)Xl)[i] = L.u;
}

// merged G1/G3 split: grid (16384, 2)
__global__ __launch_bounds__(256) void conv_splitG(
    const float* __restrict__ X0, __nv_bfloat16* __restrict__ X0h, __nv_bfloat16* __restrict__ X0l,
    const float* __restrict__ X1, __nv_bfloat16* __restrict__ X1h, __nv_bfloat16* __restrict__ X1l)
{
    const float* X = blockIdx.y ? X1 : X0;
    __nv_bfloat16* Xh = blockIdx.y ? X1h : X0h;
    __nv_bfloat16* Xl = blockIdx.y ? X1l : X0l;
    size_t i = (size_t)blockIdx.x * 256 + threadIdx.x;
    float4 v = ((const float4*)X)[i];
    union { __nv_bfloat16 b[4]; uint2 u; } H, L;
    split2(v.x, H.b[0], L.b[0]); split2(v.y, H.b[1], L.b[1]);
    split2(v.z, H.b[2], L.b[2]); split2(v.w, H.b[3], L.b[3]);
    ((uint2*)Xh)[i] = H.u;
    ((uint2*)Xl)[i] = L.u;
}

// ---------------------------------------------------------------------------
// Small NN GEMM (K=128) + FUSED transpose/split epilogue:
// Z = A[4096,128] @ B[128,128] + bias;  Bt[ro+n][k] = split(Z[k][n])
// grid (128 k-tiles of 32, 2 n-halves of 64), block 128.
// ---------------------------------------------------------------------------
__global__ __launch_bounds__(128, 4) void gemm_smallT(
    const float* __restrict__ A,
    const float* __restrict__ B,
    const float* __restrict__ bias,
    __nv_bfloat16* __restrict__ Bth, __nv_bfloat16* __restrict__ Btl,
    int ro)
{
    __shared__ float As[32 * 33];
    __shared__ float Bs[32 * 64];
    __shared__ float Cs[64 * 33];   // [n][k_local]
    const int t = threadIdx.x;
    const int m0 = blockIdx.x * 32;
    const int n0 = blockIdx.y * 64;
    const int tr = t >> 4, tc = t & 15;
    const int am = t >> 2, ak = (t & 3) * 8;

    float acc[4][4];
#pragma unroll
    for (int r = 0; r < 4; r++)
#pragma unroll
        for (int c = 0; c < 4; c++) acc[r][c] = 0.0f;

    const float* Ap = A + (size_t)(m0 + am) * 128 + ak;
    float4 a0, a1, bb[4];

    a0 = *(const float4*)(Ap);
    a1 = *(const float4*)(Ap + 4);
#pragma unroll
    for (int j = 0; j < 4; j++) {
        int f = t + j * 128;
        bb[j] = *(const float4*)(B + (size_t)(f >> 4) * 128 + n0 + (f & 15) * 4);
    }
    As[(ak + 0) * 33 + am] = a0.x; As[(ak + 1) * 33 + am] = a0.y;
    As[(ak + 2) * 33 + am] = a0.z; As[(ak + 3) * 33 + am] = a0.w;
    As[(ak + 4) * 33 + am] = a1.x; As[(ak + 5) * 33 + am] = a1.y;
    As[(ak + 6) * 33 + am] = a1.z; As[(ak + 7) * 33 + am] = a1.w;
#pragma unroll
    for (int j = 0; j < 4; j++) {
        int f = t + j * 128;
        *(float4*)&Bs[(f >> 4) * 64 + (f & 15) * 4] = bb[j];
    }
    __syncthreads();

    for (int it = 1; it <= 4; ++it) {
        if (it < 4) {
            int k0 = it << 5;
            a0 = *(const float4*)(Ap + k0);
            a1 = *(const float4*)(Ap + k0 + 4);
#pragma unroll
            for (int j = 0; j < 4; j++) {
                int f = t + j * 128;
                bb[j] = *(const float4*)(B + (size_t)(k0 + (f >> 4)) * 128 + n0 + (f & 15) * 4);
            }
        }
#pragma unroll
        for (int k = 0; k < 32; ++k) {
            float av[4];
#pragma unroll
            for (int r = 0; r < 4; r++) av[r] = As[k * 33 + tr * 4 + r];
            float4 b0 = *(const float4*)&Bs[k * 64 + tc * 4];
            float bv[4] = {b0.x, b0.y, b0.z, b0.w};
#pragma unroll
            for (int r = 0; r < 4; r++)
#pragma unroll
                for (int c = 0; c < 4; c++) acc[r][c] += av[r] * bv[c];
        }
        __syncthreads();
        if (it < 4) {
            As[(ak + 0) * 33 + am] = a0.x; As[(ak + 1) * 33 + am] = a0.y;
            As[(ak + 2) * 33 + am] = a0.z; As[(ak + 3) * 33 + am] = a0.w;
            As[(ak + 4) * 33 + am] = a1.x; As[(ak + 5) * 33 + am] = a1.y;
            As[(ak + 6) * 33 + am] = a1.z; As[(ak + 7) * 33 + am] = a1.w;
#pragma unroll
            for (int j = 0; j < 4; j++) {
                int f = t + j * 128;
                *(float4*)&Bs[(f >> 4) * 64 + (f & 15) * 4] = bb[j];
            }
            __syncthreads();
        }
    }

    // stage transposed (+bias) into smem: Cs[n][k]
#pragma unroll
    for (int r = 0; r < 4; r++)
#pragma unroll
        for (int c = 0; c < 4; c++) {
            int n = tc * 4 + c;
            Cs[n * 33 + tr * 4 + r] = acc[r][c] + bias[n0 + n];
        }
    __syncthreads();

    // thread t: n = t>>1 (0..63), k-half = (t&1)*16 -> 16 values
    {
        const int n = t >> 1;
        const int kh = (t & 1) * 16;
        union { __nv_bfloat16 b[8]; uint4 u; } Hp, Lp;
        __nv_bfloat16* oh = Bth + (size_t)(ro + n0 + n) * KTOT + m0 + kh;
        __nv_bfloat16* ol = Btl + (size_t)(ro + n0 + n) * KTOT + m0 + kh;
#pragma unroll
        for (int g = 0; g < 2; g++) {
#pragma unroll
            for (int q = 0; q < 8; q++)
                split2(Cs[n * 33 + kh + g * 8 + q], Hp.b[q], Lp.b[q]);
            *(uint4*)(oh + g * 8) = Hp.u;
            *(uint4*)(ol + g * 8) = Lp.u;
        }
    }
}

// ---------------------------------------------------------------------------
// NT GEMM (fp32 SIMT, kept for the small Wo projections):
// C[M, No] = A[M,128] @ W[No,128]^T + bias
// ---------------------------------------------------------------------------
__global__ __launch_bounds__(256) void gemm_nt(
    const float* __restrict__ A, const float* __restrict__ W,
    const float* __restrict__ bias, float* __restrict__ C,
    float* __restrict__ Cdup, int No)
{
    __shared__ float As[32 * 129];
    __shared__ float Ws[32 * 129];
    const int t = threadIdx.x;
    const int m0 = blockIdx.x * 32, n0 = blockIdx.y * 32;

    for (int i = t; i < 32 * 128; i += 256) {
        int r = i >> 7, k = i & 127;
        As[r * 129 + k] = A[(size_t)(m0 + r) * 128 + k];
        Ws[r * 129 + k] = W[(size_t)(n0 + r) * 128 + k];
    }
    __syncthreads();

    const int tr = t >> 4, tc = t & 15;
    const float* a0p = &As[(tr * 2) * 129];
    const float* a1p = &As[(tr * 2 + 1) * 129];
    const float* w0p = &Ws[(tc * 2) * 129];
    const float* w1p = &Ws[(tc * 2 + 1) * 129];

    float acc00 = 0, acc01 = 0, acc10 = 0, acc11 = 0;
#pragma unroll 16
    for (int k = 0; k < 128; k++) {
        float a0 = a0p[k], a1 = a1p[k], w0 = w0p[k], w1 = w1p[k];
        acc00 += a0 * w0; acc01 += a0 * w1;
        acc10 += a1 * w0; acc11 += a1 * w1;
    }
    int row0 = m0 + tr * 2, col0 = n0 + tc * 2;
    float v00 = acc00 + bias[col0], v01 = acc01 + bias[col0 + 1];
    float v10 = acc10 + bias[col0], v11 = acc11 + bias[col0 + 1];
    C[(size_t)row0 * No + col0]           = v00;
    C[(size_t)row0 * No + col0 + 1]       = v01;
    C[(size_t)(row0 + 1) * No + col0]     = v10;
    C[(size_t)(row0 + 1) * No + col0 + 1] = v11;
    if (Cdup) {
        Cdup[(size_t)row0 * No + col0]           = v00;
        Cdup[(size_t)row0 * No + col0 + 1]       = v01;
        Cdup[(size_t)(row0 + 1) * No + col0]     = v10;
        Cdup[(size_t)(row0 + 1) * No + col0 + 1] = v11;
    }
}

// ---------------------------------------------------------------------------
// Mixup, emitting bf16 hi/lo pairs directly (consumed by hmma_nt128).
// ---------------------------------------------------------------------------
__global__ void mix_kernel(const float* __restrict__ a1, const float* __restrict__ a3,
                           const int* __restrict__ perm, const float* __restrict__ lam,
                           __nv_bfloat16* __restrict__ m1h, __nv_bfloat16* __restrict__ m1l,
                           __nv_bfloat16* __restrict__ m3h, __nv_bfloat16* __restrict__ m3l)
{
    int i = blockIdx.x * blockDim.x + threadIdx.x;
    int row = i >> 5, q = i & 31;
    float l = lam[0], il = 1.0f - l;
    int pr = perm[row];
    union { __nv_bfloat16 b[4]; uint2 u; } H, L;

    float4 x = ((const float4*)a1)[row * 32 + q];
    float4 y = ((const float4*)a1)[pr * 32 + q];
    split2(l * x.x + il * y.x, H.b[0], L.b[0]);
    split2(l * x.y + il * y.y, H.b[1], L.b[1]);
    split2(l * x.z + il * y.z, H.b[2], L.b[2]);
    split2(l * x.w + il * y.w, H.b[3], L.b[3]);
    ((uint2*)m1h)[row * 32 + q] = H.u;
    ((uint2*)m1l)[row * 32 + q] = L.u;

    x = ((const float4*)a3)[row * 32 + q];
    y = ((const float4*)a3)[pr * 32 + q];
    split2(l * x.x + il * y.x, H.b[0], L.b[0]);
    split2(l * x.y + il * y.y, H.b[1], L.b[1]);
    split2(l * x.z + il * y.z, H.b[2], L.b[2]);
    split2(l * x.w + il * y.w, H.b[3], L.b[3]);
    ((uint2*)m3h)[row * 32 + q] = H.u;
    ((uint2*)m3l)[row * 32 + q] = L.u;
}

__global__ void attn_kernel(const float* __restrict__ qkv0, const float* __restrict__ qkv1,
                            float* __restrict__ om, int nh)
{
    int gt = blockIdx.x * blockDim.x + threadIdx.x;
    int node = gt >> 5;
    int lane = gt & 31;
    const float4* p0 = (const float4*)(qkv0 + (size_t)node * 384);
    const float4* p1 = (const float4*)(qkv1 + (size_t)node * 384);
    float4 q0 = p0[lane], k0 = p0[32 + lane], v0 = p0[64 + lane];
    float4 q1 = p1[lane], k1 = p1[32 + lane], v1 = p1[64 + lane];

    float p00 = q0.x * k0.x + q0.y * k0.y + q0.z * k0.z + q0.w * k0.w;
    float p01 = q0.x * k1.x + q0.y * k1.y + q0.z * k1.z + q0.w * k1.w;
    float p10 = q1.x * k0.x + q1.y * k0.y + q1.z * k0.z + q1.w * k0.w;
    float p11 = q1.x * k1.x + q1.y * k1.y + q1.z * k1.z + q1.w * k1.w;

    int hd = 128 / nh;
    int Wd = hd >> 2;
    for (int off = Wd >> 1; off; off >>= 1) {
        p00 += __shfl_xor_sync(0xffffffffu, p00, off);
        p01 += __shfl_xor_sync(0xffffffffu, p01, off);
        p10 += __shfl_xor_sync(0xffffffffu, p10, off);
        p11 += __shfl_xor_sync(0xffffffffu, p11, off);
    }
    float scl = rsqrtf((float)hd);
    float s00 = p00 * scl, s01 = p01 * scl, s10 = p10 * scl, s11 = p11 * scl;

    float mx0 = fmaxf(s00, s01);
    float e00 = expf(s00 - mx0), e01 = expf(s01 - mx0);
    float r0 = 1.0f / (e00 + e01);
    float mx1 = fmaxf(s10, s11);
    float e10 = expf(s10 - mx1), e11 = expf(s11 - mx1);
    float r1 = 1.0f / (e10 + e11);

    float c0 = 0.5f * (e00 * r0 + e10 * r1);
    float c1 = 0.5f * (e01 * r0 + e11 * r1);

    float4 o;
    o.x = c0 * v0.x + c1 * v1.x;
    o.y = c0 * v0.y + c1 * v1.y;
    o.z = c0 * v0.z + c1 * v1.z;
    o.w = c0 * v0.w + c1 * v1.w;
    ((float4*)(om + (size_t)node * 128))[lane] = o;
}

__global__ __launch_bounds__(256) void edge_kernel(
    const float* __restrict__ h3, const int* __restrict__ ei,
    const float* __restrict__ Wc, const float* __restrict__ bc,
    float* __restrict__ out)
{
    __shared__ float wcs[512];
    __shared__ float bcs[2];
    int t = threadIdx.x;
    for (int i = t; i < 512; i += 256) wcs[i] = Wc[i];
    if (t < 2) bcs[t] = bc[t];
    __syncthreads();

    int e = blockIdx.x * 256 + t;
    int i0 = ei[e], i1 = ei[N_EDGES + e];
    const float4* r0 = (const float4*)(h3 + (size_t)i0 * 128);
    const float4* r1 = (const float4*)(h3 + (size_t)i1 * 128);
    float acc0 = bcs[0], acc1 = bcs[1];
#pragma unroll 8
    for (int q = 0; q < 32; q++) {
        float4 f = r0[q];
        int d = q * 4;
        acc0 += f.x * wcs[2 * d] + f.y * wcs[2 * (d + 1)] + f.z * wcs[2 * (d + 2)] + f.w * wcs[2 * (d + 3)];
        acc1 += f.x * wcs[2 * d + 1] + f.y * wcs[2 * (d + 1) + 1] + f.z * wcs[2 * (d + 2) + 1] + f.w * wcs[2 * (d + 3) + 1];
    }
#pragma unroll 8
    for (int q = 0; q < 32; q++) {
        float4 f = r1[q];
        int d = 128 + q * 4;
        acc0 += f.x * wcs[2 * d] + f.y * wcs[2 * (d + 1)] + f.z * wcs[2 * (d + 2)] + f.w * wcs[2 * (d + 3)];
        acc1 += f.x * wcs[2 * d + 1] + f.y * wcs[2 * (d + 1) + 1] + f.z * wcs[2 * (d + 2) + 1] + f.w * wcs[2 * (d + 3) + 1];
    }
    out[(size_t)e * 2]     = acc0;
    out[(size_t)e * 2 + 1] = acc1;
}

// ---------------------------------------------------------------------------
extern "C" void kernel_launch(void* const* d_in, const int* in_sizes, int n_in,
                              void* d_out, int out_size)
{
    const float* x    = (const float*)d_in[0];
    const float* G1   = (const float*)d_in[1];
    const float* G3   = (const float*)d_in[2];
    const int*   ei   = (const int*)d_in[3];
    const int*   perm = (const int*)d_in[4];
    const float* lam  = (const float*)d_in[5];
    const float* beta = (const float*)d_in[6];
    const float* W1 = (const float*)d_in[7];   const float* b1 = (const float*)d_in[8];
    const float* W2 = (const float*)d_in[9];   const float* b2 = (const float*)d_in[10];
    const float* W3 = (const float*)d_in[11];  const float* b3 = (const float*)d_in[12];
    const float* W1h = (const float*)d_in[13]; const float* b1h = (const float*)d_in[14];
    const float* W3h = (const float*)d_in[15]; const float* b3h = (const float*)d_in[16];
    const float* W2m = (const float*)d_in[17]; const float* b2m = (const float*)d_in[18];
    const float* W3m = (const float*)d_in[19]; const float* b3m = (const float*)d_in[20];
    const float* Wqkv_mix = (const float*)d_in[21]; const float* bqkv_mix = (const float*)d_in[22];
    const float* Wo_mix   = (const float*)d_in[23]; const float* bo_mix   = (const float*)d_in[24];
    const float* Wqkv_fus = (const float*)d_in[25]; const float* bqkv_fus = (const float*)d_in[26];
    const float* Wo_fus   = (const float*)d_in[27]; const float* bo_fus   = (const float*)d_in[28];
    const float* Wc = (const float*)d_in[29];  const float* bc = (const float*)d_in[30];

    float *h1, *h2, *a1, *a3, *qkv0, *qkv1, *om, *hmix, *h2m, *h3;
    float* part;
    __nv_bfloat16 *G1h, *G1l, *G3h, *G3l, *Bth, *Btl;
    __nv_bfloat16 *p0h, *p0l, *p1h, *p1l, *wh, *wl;
    cudaGetSymbolAddress((void**)&h1, g_h1);
    cudaGetSymbolAddress((void**)&h2, g_h2);
    cudaGetSymbolAddress((void**)&a1, g_a1);
    cudaGetSymbolAddress((void**)&a3, g_a3);
    cudaGetSymbolAddress((void**)&qkv0, g_qkv0);
    cudaGetSymbolAddress((void**)&qkv1, g_qkv1);
    cudaGetSymbolAddress((void**)&om, g_om);
    cudaGetSymbolAddress((void**)&hmix, g_hmix);
    cudaGetSymbolAddress((void**)&h2m, g_h2m);
    cudaGetSymbolAddress((void**)&h3, g_h3);
    cudaGetSymbolAddress((void**)&part, g_part);
    cudaGetSymbolAddress((void**)&G1h, g_G1h);
    cudaGetSymbolAddress((void**)&G1l, g_G1l);
    cudaGetSymbolAddress((void**)&G3h, g_G3h);
    cudaGetSymbolAddress((void**)&G3l, g_G3l);
    cudaGetSymbolAddress((void**)&Bth, g_Bth);
    cudaGetSymbolAddress((void**)&Btl, g_Btl);
    cudaGetSymbolAddress((void**)&p0h, g_p0h);
    cudaGetSymbolAddress((void**)&p0l, g_p0l);
    cudaGetSymbolAddress((void**)&p1h, g_p1h);
    cudaGetSymbolAddress((void**)&p1l, g_p1l);
    cudaGetSymbolAddress((void**)&wh, g_wh);
    cudaGetSymbolAddress((void**)&wl, g_wl);

    cudaFuncSetAttribute(gemm_mma, cudaFuncAttributeMaxDynamicSharedMemorySize, GEMM_SMEM);
    cudaFuncSetAttribute(hmma_nt128, cudaFuncAttributeMaxDynamicSharedMemorySize, GEMM_SMEM);

    float* out_edge = (float*)d_out;
    float* out_h3   = out_edge + (size_t)N_EDGES * 2;

    const RedOut RO_NONE = {nullptr, nullptr, nullptr, nullptr, 3};

    // split G matrices into bf16 hi/lo (merged launch)
    conv_splitG<<<dim3(16384, 2), 256>>>(G1, G1h, G1l, G3, G3h, G3l);

    // ---- h1 = relu(G1 @ (x@W1+b1)) ----
    gemm_smallT<<<dim3(128, 2), 128>>>(x, W1, b1, Bth, Btl, 0);
    gemm_mma<<<dim3(32, SPLITK, 1), 256, GEMM_SMEM>>>(G1h, G1l, G1h, G1l, Bth, Btl, part);
    { RedOut o = {h1, nullptr, nullptr, nullptr, 0};
      reduce_ep<<<dim3(512, 1), 256>>>(part, nullptr, o, RO_NONE, RO_NONE); }

    // ---- h2 = relu(G1 @ (h1@W2+b2) + h1) ----
    gemm_smallT<<<dim3(128, 2), 128>>>(h1, W2, b2, Bth, Btl, 0);
    gemm_mma<<<dim3(32, SPLITK, 1), 256, GEMM_SMEM>>>(G1h, G1l, G1h, G1l, Bth, Btl, part);
    { RedOut o = {h2, nullptr, nullptr, h1, 1};
      reduce_ep<<<dim3(512, 1), 256>>>(part, nullptr, o, RO_NONE, RO_NONE); }

    // ---- merged pass: z0: G1@t3 (+h2, relu) -> h3c1(bf16); z1: G1@u1h -> a1; z2: G3@u3h -> a3 ----
    gemm_smallT<<<dim3(128, 2), 128>>>(h2, W3, b3, Bth, Btl, 0);
    gemm_smallT<<<dim3(128, 2), 128>>>(h1, W1h, b1h, Bth, Btl, 128);
    gemm_smallT<<<dim3(128, 2), 128>>>(h1, W3h, b3h, Bth, Btl, 256);
    gemm_mma<<<dim3(32, SPLITK, 3), 256, GEMM_SMEM>>>(G1h, G1l, G3h, G3l, Bth, Btl, part);
    { RedOut o0 = {nullptr, p0h, p0l, h2, 1};     // h3c1 as bf16 pair -> qkv_fus A0
      RedOut o1 = {a1, nullptr, nullptr, nullptr, 3};
      RedOut o2 = {a3, nullptr, nullptr, nullptr, 3};
      reduce_ep<<<dim3(512, 3), 256>>>(part, nullptr, o0, o1, o2); }

    // ---- mixup (emit bf16 pairs) + MHA mix (nh=2) on HMMA ----
    mix_kernel<<<512, 256>>>(a1, a3, perm, lam, p1h, p1l, /*m3*/ p1h + 0, p1l + 0);
    // NOTE: need two distinct pairs for m1/m3 -> use p1 for m1 and reuse a1/a3 slots? No:
    // m1 -> (p1h, p1l); m3 -> we re-purpose Bth/Btl head as a pair buffer (4096*128 elems each fits).
    // (see actual call below; this call above is replaced)

    // real sequence:
    mix_kernel<<<512, 256>>>(a1, a3, perm, lam, p1h, p1l,
                             (__nv_bfloat16*)Bth, (__nv_bfloat16*)Btl);
    conv_split<<<48, 256>>>(Wqkv_mix, wh, wl);
    hmma_nt128<<<dim3(32, 3, 2), 256, GEMM_SMEM>>>(p1h, p1l, Bth, Btl, wh, wl,
                                                   bqkv_mix, qkv0, qkv1, 384);
    attn_kernel<<<512, 256>>>(qkv0, qkv1, om, 2);
    gemm_nt<<<dim3(128, 4), 256>>>(om, Wo_mix, bo_mix, hmix, nullptr, 128);

    // ---- h2m = relu(G1 @ (hmix@W2m+b2m) + hmix) ----
    gemm_smallT<<<dim3(128, 2), 128>>>(hmix, W2m, b2m, Bth, Btl, 0);
    gemm_mma<<<dim3(32, SPLITK, 1), 256, GEMM_SMEM>>>(G1h, G1l, G1h, G1l, Bth, Btl, part);
    { RedOut o = {h2m, nullptr, nullptr, hmix, 1};
      reduce_ep<<<dim3(512, 1), 256>>>(part, nullptr, o, RO_NONE, RO_NONE); }

    // ---- h3c2 = relu(G1 @ (h2m@W3m+b3m) + h2m) * beta  -> bf16 pair ----
    gemm_smallT<<<dim3(128, 2), 128>>>(h2m, W3m, b3m, Bth, Btl, 0);
    gemm_mma<<<dim3(32, SPLITK, 1), 256, GEMM_SMEM>>>(G1h, G1l, G1h, G1l, Bth, Btl, part);
    { RedOut o = {nullptr, p1h, p1l, h2m, 4};     // h3c2 -> qkv_fus A1
      reduce_ep<<<dim3(512, 1), 256>>>(part, beta, o, RO_NONE, RO_NONE); }

    // ---- MHA fus (nh=4) on HMMA ----
    conv_split<<<48, 256>>>(Wqkv_fus, wh, wl);
    hmma_nt128<<<dim3(32, 3, 2), 256, GEMM_SMEM>>>(p0h, p0l, p1h, p1l, wh, wl,
                                                   bqkv_fus, qkv0, qkv1, 384);
    attn_kernel<<<512, 256>>>(qkv0, qkv1, om, 4);
    gemm_nt<<<dim3(128, 4), 256>>>(om, Wo_fus, bo_fus, h3, out_h3, 128);

    // ---- edge classifier ----
    edge_kernel<<<512, 256>>>(h3, ei, Wc, bc, out_edge);
}

// round 12
// speedup vs baseline: 6.7437x; 1.2768x over previous
#include <cuda_runtime.h>
#include <cuda_fp16.h>
#include <cstdint>

#define N_NODES 4096
#define HDIM    128
#define N_EDGES 131072
#define KTOT    4096
#define SPLITK  8
#define KCTA    (KTOT / SPLITK)     // 512
#define BK      32
#define NCH     (KCTA / BK)         // 16

// ---------------- scratch (static device arrays; no allocation) ----------------
__device__ float g_h1[N_NODES * 128];
__device__ float g_h2[N_NODES * 128];
__device__ float g_a1[N_NODES * 128];
__device__ float g_a3[N_NODES * 128];
__device__ float g_qkv0[N_NODES * 384];
__device__ float g_qkv1[N_NODES * 384];
__device__ float g_om[N_NODES * 128];
__device__ float g_hmix[N_NODES * 128];
__device__ float g_h2m[N_NODES * 128];
__device__ float g_h3[N_NODES * 128];
// fp16 (single) propagation matrices
__device__ __half g_G1h[(size_t)KTOT * KTOT];
__device__ __half g_G3h[(size_t)KTOT * KTOT];
// transposed fp16 hi/lo split of RHS (up to 384 rows x 4096 cols)
__device__ __half g_Bth[384 * KTOT];
__device__ __half g_Btl[384 * KTOT];
// fp16 single A-operands for the K=128 HMMA (qkv) kernels
__device__ __half g_fA[N_NODES * 128];
__device__ __half g_fB[N_NODES * 128];
__device__ __half g_fC[N_NODES * 128];
// fp16 hi/lo of qkv weights [384,128]
__device__ __half g_whm[384 * 128];
__device__ __half g_wlm[384 * 128];
__device__ __half g_whf[384 * 128];
__device__ __half g_wlf[384 * 128];
// split-K partials [3][SPLITK][4096][128]
__device__ float g_part[(size_t)3 * SPLITK * N_NODES * 128];

// ============================ asm helpers =================================
__device__ __forceinline__ uint32_t smem_to_u32(const void* p) {
    uint32_t a;
    asm("{ .reg .u64 t; cvta.to.shared.u64 t, %1; cvt.u32.u64 %0, t; }" : "=r"(a) : "l"(p));
    return a;
}
__device__ __forceinline__ void cp16(uint32_t s, const void* g) {
    asm volatile("cp.async.cg.shared.global [%0], [%1], 16;" :: "r"(s), "l"(g));
}
__device__ __forceinline__ void cp_commit() {
    asm volatile("cp.async.commit_group;" ::: "memory");
}
template <int Ng>
__device__ __forceinline__ void cp_wait() {
    asm volatile("cp.async.wait_group %0;" :: "n"(Ng) : "memory");
}
__device__ __forceinline__ void ldsm4(uint32_t* r, uint32_t addr) {
    asm volatile("ldmatrix.sync.aligned.m8n8.x4.shared.b16 {%0,%1,%2,%3}, [%4];"
        : "=r"(r[0]), "=r"(r[1]), "=r"(r[2]), "=r"(r[3]) : "r"(addr));
}
__device__ __forceinline__ void mma16816(float* d, const uint32_t* a, uint32_t b0, uint32_t b1) {
    asm volatile(
        "mma.sync.aligned.m16n8k16.row.col.f32.f16.f16.f32 "
        "{%0,%1,%2,%3}, {%4,%5,%6,%7}, {%8,%9}, {%0,%1,%2,%3};"
        : "+f"(d[0]), "+f"(d[1]), "+f"(d[2]), "+f"(d[3])
        : "r"(a[0]), "r"(a[1]), "r"(a[2]), "r"(a[3]), "r"(b0), "r"(b1));
}
__device__ __forceinline__ void split2h(float v, __half& h, __half& l) {
    h = __float2half_rn(v);
    l = __float2half_rn(v - __half2float(h));
}

// ===========================================================================
// Big tensor-core GEMM via mma.sync (fp16 2-term):
// Part[z][ks][4096][128] = A@Bh^T + A@Bl^T over K range of ks.
// z = blockIdx.z selects B rows z*128 and (z==2 ? A1 : A0) operand.
// CTA tile 128x128, BK=32, 8 warps (4x2), warp tile 32x64, 2-stage cp.async.
// ===========================================================================
#define TSTRIDE 80                    // bytes per smem row (32 fp16 = 64 B + 16 pad)
#define TILE_B  (128 * TSTRIDE)       // 10240 B per operand tile
#define STAGE   (3 * TILE_B)          // A | Bh | Bl
#define GEMM_SMEM (2 * STAGE)         // 61440 B

__global__ __launch_bounds__(256, 2) void gemm_mma(
    const __half* __restrict__ A0, const __half* __restrict__ A1,
    const __half* __restrict__ Bh, const __half* __restrict__ Bl,
    float* __restrict__ Part)
{
    extern __shared__ char smraw[];
    const uint32_t sm0 = smem_to_u32(smraw);

    const int tid = threadIdx.x;
    const int lane = tid & 31, wid = tid >> 5;
    const int wm = wid >> 1, wn = wid & 1;
    const int m0 = blockIdx.x * 128;
    const int ks = blockIdx.y;
    const int z  = blockIdx.z;
    const int kb = ks * KCTA;

    const __half* gA  = ((z == 2) ? A1 : A0) + (size_t)m0 * KTOT + kb;
    const __half* gBh = Bh + (size_t)(z * 128) * KTOT + kb;
    const __half* gBl = Bl + (size_t)(z * 128) * KTOT + kb;

    const int r0i = tid >> 2, c0i = tid & 3;
    const int r1i = (tid + 256) >> 2, c1i = tid & 3;
    const uint32_t so0 = (uint32_t)r0i * TSTRIDE + c0i * 16;
    const uint32_t so1 = (uint32_t)r1i * TSTRIDE + c1i * 16;

    const uint32_t aO = (uint32_t)(wm * 32 + (lane & 15)) * TSTRIDE + (lane >> 4) * 16;
    const uint32_t bO = (uint32_t)(wn * 64 + (lane & 7) + ((lane >> 4) & 1) * 8) * TSTRIDE
                      + ((lane >> 3) & 1) * 16;

    float acc[2][8][4];
#pragma unroll
    for (int i = 0; i < 2; i++)
#pragma unroll
        for (int j = 0; j < 8; j++)
#pragma unroll
            for (int q = 0; q < 4; q++) acc[i][j][q] = 0.0f;

#define LOAD_CHUNK(ci, s) do { \
    uint32_t sbase = sm0 + (s) * STAGE; \
    size_t g0 = (size_t)r0i * KTOT + (ci) * BK + c0i * 8; \
    size_t g1 = (size_t)r1i * KTOT + (ci) * BK + c1i * 8; \
    cp16(sbase + so0,              gA  + g0); \
    cp16(sbase + so1,              gA  + g1); \
    cp16(sbase + TILE_B + so0,     gBh + g0); \
    cp16(sbase + TILE_B + so1,     gBh + g1); \
    cp16(sbase + 2 * TILE_B + so0, gBl + g0); \
    cp16(sbase + 2 * TILE_B + so1, gBl + g1); \
} while (0)

    LOAD_CHUNK(0, 0);
    cp_commit();

    for (int ci = 0; ci < NCH; ++ci) {
        if (ci + 1 < NCH) { LOAD_CHUNK(ci + 1, (ci + 1) & 1); cp_commit(); }
        if (ci + 1 < NCH) cp_wait<1>(); else cp_wait<0>();
        __syncthreads();

        const uint32_t sb = sm0 + (ci & 1) * STAGE;
#pragma unroll
        for (int kk = 0; kk < 2; ++kk) {
            const uint32_t ko = kk * 32;    // 16 fp16 = 32 B
            uint32_t av[2][4], bf[4][4];
            ldsm4(av[0], sb + aO + ko);
            ldsm4(av[1], sb + aO + 16 * TSTRIDE + ko);
#pragma unroll
            for (int j = 0; j < 4; j++)
                ldsm4(bf[j], sb + TILE_B + bO + j * 16 * TSTRIDE + ko);
#pragma unroll
            for (int i = 0; i < 2; i++)
#pragma unroll
                for (int j = 0; j < 4; j++) {
                    mma16816(acc[i][2 * j],     av[i], bf[j][0], bf[j][1]);
                    mma16816(acc[i][2 * j + 1], av[i], bf[j][2], bf[j][3]);
                }
#pragma unroll
            for (int j = 0; j < 4; j++)
                ldsm4(bf[j], sb + 2 * TILE_B + bO + j * 16 * TSTRIDE + ko);
#pragma unroll
            for (int i = 0; i < 2; i++)
#pragma unroll
                for (int j = 0; j < 4; j++) {
                    mma16816(acc[i][2 * j],     av[i], bf[j][0], bf[j][1]);
                    mma16816(acc[i][2 * j + 1], av[i], bf[j][2], bf[j][3]);
                }
        }
        __syncthreads();
    }

    float* outp = Part + ((size_t)(z * SPLITK + ks) * N_NODES + m0) * 128;
    const int rr = lane >> 2, c2 = (lane & 3) * 2;
#pragma unroll
    for (int i = 0; i < 2; i++) {
        const int row0 = wm * 32 + i * 16 + rr;
#pragma unroll
        for (int j = 0; j < 8; j++) {
            const int col = wn * 64 + j * 8 + c2;
            *(float2*)(outp + (size_t)row0 * 128 + col)       = make_float2(acc[i][j][0], acc[i][j][1]);
            *(float2*)(outp + (size_t)(row0 + 8) * 128 + col) = make_float2(acc[i][j][2], acc[i][j][3]);
        }
    }
#undef LOAD_CHUNK
}

// ===========================================================================
// K=128 HMMA NT GEMM (fp16 2-term): C[4096, No] = A@W^T + bias.
// A fp16 single [4096,128]; W fp16 h/l [No,128]. grid (32, No/128, 2).
// ===========================================================================
__global__ __launch_bounds__(256, 2) void hmma_nt128(
    const __half* __restrict__ A0, const __half* __restrict__ A1,
    const __half* __restrict__ Wh, const __half* __restrict__ Wl,
    const float* __restrict__ bias,
    float* __restrict__ C0, float* __restrict__ C1, int No)
{
    extern __shared__ char smraw[];
    const uint32_t sm0 = smem_to_u32(smraw);

    const int tid = threadIdx.x;
    const int lane = tid & 31, wid = tid >> 5;
    const int wm = wid >> 1, wn = wid & 1;
    const int m0 = blockIdx.x * 128;
    const int n0 = blockIdx.y * 128;
    const int z  = blockIdx.z;

    const __half* gA  = (z ? A1 : A0) + (size_t)m0 * 128;
    const __half* gBh = Wh + (size_t)n0 * 128;
    const __half* gBl = Wl + (size_t)n0 * 128;
    float* C = z ? C1 : C0;

    const int r0i = tid >> 2, c0i = tid & 3;
    const int r1i = (tid + 256) >> 2, c1i = tid & 3;
    const uint32_t so0 = (uint32_t)r0i * TSTRIDE + c0i * 16;
    const uint32_t so1 = (uint32_t)r1i * TSTRIDE + c1i * 16;

    const uint32_t aO = (uint32_t)(wm * 32 + (lane & 15)) * TSTRIDE + (lane >> 4) * 16;
    const uint32_t bO = (uint32_t)(wn * 64 + (lane & 7) + ((lane >> 4) & 1) * 8) * TSTRIDE
                      + ((lane >> 3) & 1) * 16;

    float acc[2][8][4];
#pragma unroll
    for (int i = 0; i < 2; i++)
#pragma unroll
        for (int j = 0; j < 8; j++)
#pragma unroll
            for (int q = 0; q < 4; q++) acc[i][j][q] = 0.0f;

#define LOAD_CHUNK2(ci, s) do { \
    uint32_t sbase = sm0 + (s) * STAGE; \
    size_t g0 = (size_t)r0i * 128 + (ci) * BK + c0i * 8; \
    size_t g1 = (size_t)r1i * 128 + (ci) * BK + c1i * 8; \
    cp16(sbase + so0,              gA  + g0); \
    cp16(sbase + so1,              gA  + g1); \
    cp16(sbase + TILE_B + so0,     gBh + g0); \
    cp16(sbase + TILE_B + so1,     gBh + g1); \
    cp16(sbase + 2 * TILE_B + so0, gBl + g0); \
    cp16(sbase + 2 * TILE_B + so1, gBl + g1); \
} while (0)

    LOAD_CHUNK2(0, 0);
    cp_commit();

    for (int ci = 0; ci < 4; ++ci) {
        if (ci + 1 < 4) { LOAD_CHUNK2(ci + 1, (ci + 1) & 1); cp_commit(); }
        if (ci + 1 < 4) cp_wait<1>(); else cp_wait<0>();
        __syncthreads();

        const uint32_t sb = sm0 + (ci & 1) * STAGE;
#pragma unroll
        for (int kk = 0; kk < 2; ++kk) {
            const uint32_t ko = kk * 32;
            uint32_t av[2][4], bf[4][4];
            ldsm4(av[0], sb + aO + ko);
            ldsm4(av[1], sb + aO + 16 * TSTRIDE + ko);
#pragma unroll
            for (int j = 0; j < 4; j++)
                ldsm4(bf[j], sb + TILE_B + bO + j * 16 * TSTRIDE + ko);
#pragma unroll
            for (int i = 0; i < 2; i++)
#pragma unroll
                for (int j = 0; j < 4; j++) {
                    mma16816(acc[i][2 * j],     av[i], bf[j][0], bf[j][1]);
                    mma16816(acc[i][2 * j + 1], av[i], bf[j][2], bf[j][3]);
                }
#pragma unroll
            for (int j = 0; j < 4; j++)
                ldsm4(bf[j], sb + 2 * TILE_B + bO + j * 16 * TSTRIDE + ko);
#pragma unroll
            for (int i = 0; i < 2; i++)
#pragma unroll
                for (int j = 0; j < 4; j++) {
                    mma16816(acc[i][2 * j],     av[i], bf[j][0], bf[j][1]);
                    mma16816(acc[i][2 * j + 1], av[i], bf[j][2], bf[j][3]);
                }
        }
        __syncthreads();
    }

    const int rr = lane >> 2, c2 = (lane & 3) * 2;
#pragma unroll
    for (int i = 0; i < 2; i++) {
        const int row0 = m0 + wm * 32 + i * 16 + rr;
#pragma unroll
        for (int j = 0; j < 8; j++) {
            const int col = n0 + wn * 64 + j * 8 + c2;
            const float b0 = bias[col], b1 = bias[col + 1];
            *(float2*)(C + (size_t)row0 * No + col)
                = make_float2(acc[i][j][0] + b0, acc[i][j][1] + b1);
            *(float2*)(C + (size_t)(row0 + 8) * No + col)
                = make_float2(acc[i][j][2] + b0, acc[i][j][3] + b1);
        }
    }
#undef LOAD_CHUNK2
}

// ---------------------------------------------------------------------------
// reduce SPLITK partials + epilogue; up to 3 outputs via grid.y.
// mode 0: relu(z); 1: relu(z+res); 3: z; 4: relu(z+res)*scale
// Optional fp16 single output Ch besides/instead of fp32 C.
// ---------------------------------------------------------------------------
struct RedOut {
    float* C;
    __half* Ch;
    const float* res;
    int mode;
};

__global__ __launch_bounds__(256) void reduce_ep(
    const float* __restrict__ P, const float* __restrict__ scale_p,
    RedOut o0, RedOut o1, RedOut o2)
{
    const int y = blockIdx.y;
    RedOut o = (y == 0) ? o0 : (y == 1) ? o1 : o2;

    int i = blockIdx.x * 256 + threadIdx.x;       // float4 index, 131072 per slot
    const float4* p = (const float4*)P + (size_t)y * SPLITK * 131072;
    float4 z = p[i];
#pragma unroll
    for (int s = 1; s < SPLITK; s++) {
        float4 a = p[i + (size_t)s * 131072];
        z.x += a.x; z.y += a.y; z.z += a.z; z.w += a.w;
    }
    if (o.mode == 1 || o.mode == 4) {
        float4 r = ((const float4*)o.res)[i];
        z.x += r.x; z.y += r.y; z.z += r.z; z.w += r.w;
    }
    if (o.mode != 3) {
        z.x = fmaxf(z.x, 0.0f); z.y = fmaxf(z.y, 0.0f);
        z.z = fmaxf(z.z, 0.0f); z.w = fmaxf(z.w, 0.0f);
    }
    if (o.mode == 4) {
        float s = *scale_p;
        z.x *= s; z.y *= s; z.z *= s; z.w *= s;
    }
    if (o.C) ((float4*)o.C)[i] = z;
    if (o.Ch) {
        union { __half b[4]; uint2 u; } H;
        H.b[0] = __float2half_rn(z.x); H.b[1] = __float2half_rn(z.y);
        H.b[2] = __float2half_rn(z.z); H.b[3] = __float2half_rn(z.w);
        ((uint2*)o.Ch)[i] = H.u;
    }
}

// ---------------------------------------------------------------------------
// G matrices: fp32 -> fp16 single. grid (16384, 2)
// ---------------------------------------------------------------------------
__global__ __launch_bounds__(256) void conv_g(
    const float* __restrict__ X0, __half* __restrict__ Y0,
    const float* __restrict__ X1, __half* __restrict__ Y1)
{
    const float* X = blockIdx.y ? X1 : X0;
    __half* Y = blockIdx.y ? Y1 : Y0;
    size_t i = (size_t)blockIdx.x * 256 + threadIdx.x;
    float4 v = ((const float4*)X)[i];
    union { __half b[4]; uint2 u; } H;
    H.b[0] = __float2half_rn(v.x); H.b[1] = __float2half_rn(v.y);
    H.b[2] = __float2half_rn(v.z); H.b[3] = __float2half_rn(v.w);
    ((uint2*)Y)[i] = H.u;
}

// qkv weights: fp32 -> fp16 hi/lo pair. grid (48, 2)
__global__ __launch_bounds__(256) void conv_w(
    const float* __restrict__ X0, __half* __restrict__ H0, __half* __restrict__ L0,
    const float* __restrict__ X1, __half* __restrict__ H1, __half* __restrict__ L1)
{
    const float* X = blockIdx.y ? X1 : X0;
    __half* Xh = blockIdx.y ? H1 : H0;
    __half* Xl = blockIdx.y ? L1 : L0;
    size_t i = (size_t)blockIdx.x * 256 + threadIdx.x;
    float4 v = ((const float4*)X)[i];
    union { __half b[4]; uint2 u; } H, L;
    split2h(v.x, H.b[0], L.b[0]); split2h(v.y, H.b[1], L.b[1]);
    split2h(v.z, H.b[2], L.b[2]); split2h(v.w, H.b[3], L.b[3]);
    ((uint2*)Xh)[i] = H.u;
    ((uint2*)Xl)[i] = L.u;
}

// ---------------------------------------------------------------------------
// Small NN GEMM (K=128) + FUSED transpose/split(fp16) epilogue:
// Z = A[4096,128] @ B[128,128] + bias;  Bt[ro+n][k] = split_h/l(Z[k][n])
// grid (128 k-tiles of 32, 2 n-halves of 64), block 128.
// ---------------------------------------------------------------------------
__global__ __launch_bounds__(128, 4) void gemm_smallT(
    const float* __restrict__ A,
    const float* __restrict__ B,
    const float* __restrict__ bias,
    __half* __restrict__ Bth, __half* __restrict__ Btl,
    int ro)
{
    __shared__ float As[32 * 33];
    __shared__ float Bs[32 * 64];
    __shared__ float Cs[64 * 33];   // [n][k_local]
    const int t = threadIdx.x;
    const int m0 = blockIdx.x * 32;
    const int n0 = blockIdx.y * 64;
    const int tr = t >> 4, tc = t & 15;
    const int am = t >> 2, ak = (t & 3) * 8;

    float acc[4][4];
#pragma unroll
    for (int r = 0; r < 4; r++)
#pragma unroll
        for (int c = 0; c < 4; c++) acc[r][c] = 0.0f;

    const float* Ap = A + (size_t)(m0 + am) * 128 + ak;
    float4 a0, a1, bb[4];

    a0 = *(const float4*)(Ap);
    a1 = *(const float4*)(Ap + 4);
#pragma unroll
    for (int j = 0; j < 4; j++) {
        int f = t + j * 128;
        bb[j] = *(const float4*)(B + (size_t)(f >> 4) * 128 + n0 + (f & 15) * 4);
    }
    As[(ak + 0) * 33 + am] = a0.x; As[(ak + 1) * 33 + am] = a0.y;
    As[(ak + 2) * 33 + am] = a0.z; As[(ak + 3) * 33 + am] = a0.w;
    As[(ak + 4) * 33 + am] = a1.x; As[(ak + 5) * 33 + am] = a1.y;
    As[(ak + 6) * 33 + am] = a1.z; As[(ak + 7) * 33 + am] = a1.w;
#pragma unroll
    for (int j = 0; j < 4; j++) {
        int f = t + j * 128;
        *(float4*)&Bs[(f >> 4) * 64 + (f & 15) * 4] = bb[j];
    }
    __syncthreads();

    for (int it = 1; it <= 4; ++it) {
        if (it < 4) {
            int k0 = it << 5;
            a0 = *(const float4*)(Ap + k0);
            a1 = *(const float4*)(Ap + k0 + 4);
#pragma unroll
            for (int j = 0; j < 4; j++) {
                int f = t + j * 128;
                bb[j] = *(const float4*)(B + (size_t)(k0 + (f >> 4)) * 128 + n0 + (f & 15) * 4);
            }
        }
#pragma unroll
        for (int k = 0; k < 32; ++k) {
            float av[4];
#pragma unroll
            for (int r = 0; r < 4; r++) av[r] = As[k * 33 + tr * 4 + r];
            float4 b0 = *(const float4*)&Bs[k * 64 + tc * 4];
            float bv[4] = {b0.x, b0.y, b0.z, b0.w};
#pragma unroll
            for (int r = 0; r < 4; r++)
#pragma unroll
                for (int c = 0; c < 4; c++) acc[r][c] += av[r] * bv[c];
        }
        __syncthreads();
        if (it < 4) {
            As[(ak + 0) * 33 + am] = a0.x; As[(ak + 1) * 33 + am] = a0.y;
            As[(ak + 2) * 33 + am] = a0.z; As[(ak + 3) * 33 + am] = a0.w;
            As[(ak + 4) * 33 + am] = a1.x; As[(ak + 5) * 33 + am] = a1.y;
            As[(ak + 6) * 33 + am] = a1.z; As[(ak + 7) * 33 + am] = a1.w;
#pragma unroll
            for (int j = 0; j < 4; j++) {
                int f = t + j * 128;
                *(float4*)&Bs[(f >> 4) * 64 + (f & 15) * 4] = bb[j];
            }
            __syncthreads();
        }
    }

    // stage transposed (+bias) into smem: Cs[n][k]
#pragma unroll
    for (int r = 0; r < 4; r++)
#pragma unroll
        for (int c = 0; c < 4; c++) {
            int n = tc * 4 + c;
            Cs[n * 33 + tr * 4 + r] = acc[r][c] + bias[n0 + n];
        }
    __syncthreads();

    // thread t: n = t>>1 (0..63), k-half = (t&1)*16 -> 16 values
    {
        const int n = t >> 1;
        const int kh = (t & 1) * 16;
        union { __half b[8]; uint4 u; } Hp, Lp;
        __half* oh = Bth + (size_t)(ro + n0 + n) * KTOT + m0 + kh;
        __half* ol = Btl + (size_t)(ro + n0 + n) * KTOT + m0 + kh;
#pragma unroll
        for (int g = 0; g < 2; g++) {
#pragma unroll
            for (int q = 0; q < 8; q++)
                split2h(Cs[n * 33 + kh + g * 8 + q], Hp.b[q], Lp.b[q]);
            *(uint4*)(oh + g * 8) = Hp.u;
            *(uint4*)(ol + g * 8) = Lp.u;
        }
    }
}

// ---------------------------------------------------------------------------
// NT GEMM (fp32 SIMT, kept for the small Wo projections):
// C[M, No] = A[M,128] @ W[No,128]^T + bias
// ---------------------------------------------------------------------------
__global__ __launch_bounds__(256) void gemm_nt(
    const float* __restrict__ A, const float* __restrict__ W,
    const float* __restrict__ bias, float* __restrict__ C,
    float* __restrict__ Cdup, int No)
{
    __shared__ float As[32 * 129];
    __shared__ float Ws[32 * 129];
    const int t = threadIdx.x;
    const int m0 = blockIdx.x * 32, n0 = blockIdx.y * 32;

    for (int i = t; i < 32 * 128; i += 256) {
        int r = i >> 7, k = i & 127;
        As[r * 129 + k] = A[(size_t)(m0 + r) * 128 + k];
        Ws[r * 129 + k] = W[(size_t)(n0 + r) * 128 + k];
    }
    __syncthreads();

    const int tr = t >> 4, tc = t & 15;
    const float* a0p = &As[(tr * 2) * 129];
    const float* a1p = &As[(tr * 2 + 1) * 129];
    const float* w0p = &Ws[(tc * 2) * 129];
    const float* w1p = &Ws[(tc * 2 + 1) * 129];

    float acc00 = 0, acc01 = 0, acc10 = 0, acc11 = 0;
#pragma unroll 16
    for (int k = 0; k < 128; k++) {
        float a0 = a0p[k], a1 = a1p[k], w0 = w0p[k], w1 = w1p[k];
        acc00 += a0 * w0; acc01 += a0 * w1;
        acc10 += a1 * w0; acc11 += a1 * w1;
    }
    int row0 = m0 + tr * 2, col0 = n0 + tc * 2;
    float v00 = acc00 + bias[col0], v01 = acc01 + bias[col0 + 1];
    float v10 = acc10 + bias[col0], v11 = acc11 + bias[col0 + 1];
    C[(size_t)row0 * No + col0]           = v00;
    C[(size_t)row0 * No + col0 + 1]       = v01;
    C[(size_t)(row0 + 1) * No + col0]     = v10;
    C[(size_t)(row0 + 1) * No + col0 + 1] = v11;
    if (Cdup) {
        Cdup[(size_t)row0 * No + col0]           = v00;
        Cdup[(size_t)row0 * No + col0 + 1]       = v01;
        Cdup[(size_t)(row0 + 1) * No + col0]     = v10;
        Cdup[(size_t)(row0 + 1) * No + col0 + 1] = v11;
    }
}

// ---------------------------------------------------------------------------
// Mixup, emitting fp16 single (consumed as A by hmma_nt128).
// ---------------------------------------------------------------------------
__global__ void mix_kernel(const float* __restrict__ a1, const float* __restrict__ a3,
                           const int* __restrict__ perm, const float* __restrict__ lam,
                           __half* __restrict__ m1h, __half* __restrict__ m3h)
{
    int i = blockIdx.x * blockDim.x + threadIdx.x;
    int row = i >> 5, q = i & 31;
    float l = lam[0], il = 1.0f - l;
    int pr = perm[row];
    union { __half b[4]; uint2 u; } H;

    float4 x = ((const float4*)a1)[row * 32 + q];
    float4 y = ((const float4*)a1)[pr * 32 + q];
    H.b[0] = __float2half_rn(l * x.x + il * y.x);
    H.b[1] = __float2half_rn(l * x.y + il * y.y);
    H.b[2] = __float2half_rn(l * x.z + il * y.z);
    H.b[3] = __float2half_rn(l * x.w + il * y.w);
    ((uint2*)m1h)[row * 32 + q] = H.u;

    x = ((const float4*)a3)[row * 32 + q];
    y = ((const float4*)a3)[pr * 32 + q];
    H.b[0] = __float2half_rn(l * x.x + il * y.x);
    H.b[1] = __float2half_rn(l * x.y + il * y.y);
    H.b[2] = __float2half_rn(l * x.z + il * y.z);
    H.b[3] = __float2half_rn(l * x.w + il * y.w);
    ((uint2*)m3h)[row * 32 + q] = H.u;
}

__global__ void attn_kernel(const float* __restrict__ qkv0, const float* __restrict__ qkv1,
                            float* __restrict__ om, int nh)
{
    int gt = blockIdx.x * blockDim.x + threadIdx.x;
    int node = gt >> 5;
    int lane = gt & 31;
    const float4* p0 = (const float4*)(qkv0 + (size_t)node * 384);
    const float4* p1 = (const float4*)(qkv1 + (size_t)node * 384);
    float4 q0 = p0[lane], k0 = p0[32 + lane], v0 = p0[64 + lane];
    float4 q1 = p1[lane], k1 = p1[32 + lane], v1 = p1[64 + lane];

    float p00 = q0.x * k0.x + q0.y * k0.y + q0.z * k0.z + q0.w * k0.w;
    float p01 = q0.x * k1.x + q0.y * k1.y + q0.z * k1.z + q0.w * k1.w;
    float p10 = q1.x * k0.x + q1.y * k0.y + q1.z * k0.z + q1.w * k0.w;
    float p11 = q1.x * k1.x + q1.y * k1.y + q1.z * k1.z + q1.w * k1.w;

    int hd = 128 / nh;
    int Wd = hd >> 2;
    for (int off = Wd >> 1; off; off >>= 1) {
        p00 += __shfl_xor_sync(0xffffffffu, p00, off);
        p01 += __shfl_xor_sync(0xffffffffu, p01, off);
        p10 += __shfl_xor_sync(0xffffffffu, p10, off);
        p11 += __shfl_xor_sync(0xffffffffu, p11, off);
    }
    float scl = rsqrtf((float)hd);
    float s00 = p00 * scl, s01 = p01 * scl, s10 = p10 * scl, s11 = p11 * scl;

    float mx0 = fmaxf(s00, s01);
    float e00 = expf(s00 - mx0), e01 = expf(s01 - mx0);
    float r0 = 1.0f / (e00 + e01);
    float mx1 = fmaxf(s10, s11);
    float e10 = expf(s10 - mx1), e11 = expf(s11 - mx1);
    float r1 = 1.0f / (e10 + e11);

    float c0 = 0.5f * (e00 * r0 + e10 * r1);
    float c1 = 0.5f * (e01 * r0 + e11 * r1);

    float4 o;
    o.x = c0 * v0.x + c1 * v1.x;
    o.y = c0 * v0.y + c1 * v1.y;
    o.z = c0 * v0.z + c1 * v1.z;
    o.w = c0 * v0.w + c1 * v1.w;
    ((float4*)(om + (size_t)node * 128))[lane] = o;
}

__global__ __launch_bounds__(256) void edge_kernel(
    const float* __restrict__ h3, const int* __restrict__ ei,
    const float* __restrict__ Wc, const float* __restrict__ bc,
    float* __restrict__ out)
{
    __shared__ float wcs[512];
    __shared__ float bcs[2];
    int t = threadIdx.x;
    for (int i = t; i < 512; i += 256) wcs[i] = Wc[i];
    if (t < 2) bcs[t] = bc[t];
    __syncthreads();

    int e = blockIdx.x * 256 + t;
    int i0 = ei[e], i1 = ei[N_EDGES + e];
    const float4* r0 = (const float4*)(h3 + (size_t)i0 * 128);
    const float4* r1 = (const float4*)(h3 + (size_t)i1 * 128);
    float acc0 = bcs[0], acc1 = bcs[1];
#pragma unroll 8
    for (int q = 0; q < 32; q++) {
        float4 f = r0[q];
        int d = q * 4;
        acc0 += f.x * wcs[2 * d] + f.y * wcs[2 * (d + 1)] + f.z * wcs[2 * (d + 2)] + f.w * wcs[2 * (d + 3)];
        acc1 += f.x * wcs[2 * d + 1] + f.y * wcs[2 * (d + 1) + 1] + f.z * wcs[2 * (d + 2) + 1] + f.w * wcs[2 * (d + 3) + 1];
    }
#pragma unroll 8
    for (int q = 0; q < 32; q++) {
        float4 f = r1[q];
        int d = 128 + q * 4;
        acc0 += f.x * wcs[2 * d] + f.y * wcs[2 * (d + 1)] + f.z * wcs[2 * (d + 2)] + f.w * wcs[2 * (d + 3)];
        acc1 += f.x * wcs[2 * d + 1] + f.y * wcs[2 * (d + 1) + 1] + f.z * wcs[2 * (d + 2) + 1] + f.w * wcs[2 * (d + 3) + 1];
    }
    out[(size_t)e * 2]     = acc0;
    out[(size_t)e * 2 + 1] = acc1;
}

// ---------------------------------------------------------------------------
extern "C" void kernel_launch(void* const* d_in, const int* in_sizes, int n_in,
                              void* d_out, int out_size)
{
    const float* x    = (const float*)d_in[0];
    const float* G1   = (const float*)d_in[1];
    const float* G3   = (const float*)d_in[2];
    const int*   ei   = (const int*)d_in[3];
    const int*   perm = (const int*)d_in[4];
    const float* lam  = (const float*)d_in[5];
    const float* beta = (const float*)d_in[6];
    const float* W1 = (const float*)d_in[7];   const float* b1 = (const float*)d_in[8];
    const float* W2 = (const float*)d_in[9];   const float* b2 = (const float*)d_in[10];
    const float* W3 = (const float*)d_in[11];  const float* b3 = (const float*)d_in[12];
    const float* W1h = (const float*)d_in[13]; const float* b1h = (const float*)d_in[14];
    const float* W3h = (const float*)d_in[15]; const float* b3h = (const float*)d_in[16];
    const float* W2m = (const float*)d_in[17]; const float* b2m = (const float*)d_in[18];
    const float* W3m = (const float*)d_in[19]; const float* b3m = (const float*)d_in[20];
    const float* Wqkv_mix = (const float*)d_in[21]; const float* bqkv_mix = (const float*)d_in[22];
    const float* Wo_mix   = (const float*)d_in[23]; const float* bo_mix   = (const float*)d_in[24];
    const float* Wqkv_fus = (const float*)d_in[25]; const float* bqkv_fus = (const float*)d_in[26];
    const float* Wo_fus   = (const float*)d_in[27]; const float* bo_fus   = (const float*)d_in[28];
    const float* Wc = (const float*)d_in[29];  const float* bc = (const float*)d_in[30];

    float *h1, *h2, *a1, *a3, *qkv0, *qkv1, *om, *hmix, *h2m, *h3;
    float* part;
    __half *G1h, *G3h, *Bth, *Btl, *fA, *fB, *fC, *whm, *wlm, *whf, *wlf;
    cudaGetSymbolAddress((void**)&h1, g_h1);
    cudaGetSymbolAddress((void**)&h2, g_h2);
    cudaGetSymbolAddress((void**)&a1, g_a1);
    cudaGetSymbolAddress((void**)&a3, g_a3);
    cudaGetSymbolAddress((void**)&qkv0, g_qkv0);
    cudaGetSymbolAddress((void**)&qkv1, g_qkv1);
    cudaGetSymbolAddress((void**)&om, g_om);
    cudaGetSymbolAddress((void**)&hmix, g_hmix);
    cudaGetSymbolAddress((void**)&h2m, g_h2m);
    cudaGetSymbolAddress((void**)&h3, g_h3);
    cudaGetSymbolAddress((void**)&part, g_part);
    cudaGetSymbolAddress((void**)&G1h, g_G1h);
    cudaGetSymbolAddress((void**)&G3h, g_G3h);
    cudaGetSymbolAddress((void**)&Bth, g_Bth);
    cudaGetSymbolAddress((void**)&Btl, g_Btl);
    cudaGetSymbolAddress((void**)&fA, g_fA);
    cudaGetSymbolAddress((void**)&fB, g_fB);
    cudaGetSymbolAddress((void**)&fC, g_fC);
    cudaGetSymbolAddress((void**)&whm, g_whm);
    cudaGetSymbolAddress((void**)&wlm, g_wlm);
    cudaGetSymbolAddress((void**)&whf, g_whf);
    cudaGetSymbolAddress((void**)&wlf, g_wlf);

    cudaFuncSetAttribute(gemm_mma, cudaFuncAttributeMaxDynamicSharedMemorySize, GEMM_SMEM);
    cudaFuncSetAttribute(hmma_nt128, cudaFuncAttributeMaxDynamicSharedMemorySize, GEMM_SMEM);

    float* out_edge = (float*)d_out;
    float* out_h3   = out_edge + (size_t)N_EDGES * 2;

    const RedOut RO_NONE = {nullptr, nullptr, nullptr, 3};

    // convert G matrices (fp16 single) and qkv weights (fp16 pair)
    conv_g<<<dim3(16384, 2), 256>>>(G1, G1h, G3, G3h);
    conv_w<<<dim3(48, 2), 256>>>(Wqkv_mix, whm, wlm, Wqkv_fus, whf, wlf);

    // ---- h1 = relu(G1 @ (x@W1+b1)) ----
    gemm_smallT<<<dim3(128, 2), 128>>>(x, W1, b1, Bth, Btl, 0);
    gemm_mma<<<dim3(32, SPLITK, 1), 256, GEMM_SMEM>>>(G1h, G3h, Bth, Btl, part);
    { RedOut o = {h1, nullptr, nullptr, 0};
      reduce_ep<<<dim3(512, 1), 256>>>(part, nullptr, o, RO_NONE, RO_NONE); }

    // ---- h2 = relu(G1 @ (h1@W2+b2) + h1) ----
    gemm_smallT<<<dim3(128, 2), 128>>>(h1, W2, b2, Bth, Btl, 0);
    gemm_mma<<<dim3(32, SPLITK, 1), 256, GEMM_SMEM>>>(G1h, G3h, Bth, Btl, part);
    { RedOut o = {h2, nullptr, h1, 1};
      reduce_ep<<<dim3(512, 1), 256>>>(part, nullptr, o, RO_NONE, RO_NONE); }

    // ---- merged pass: z0: G1@t3 (+h2, relu) -> h3c1(fp16 fA); z1: G1@u1h -> a1; z2: G3@u3h -> a3 ----
    gemm_smallT<<<dim3(128, 2), 128>>>(h2, W3, b3, Bth, Btl, 0);
    gemm_smallT<<<dim3(128, 2), 128>>>(h1, W1h, b1h, Bth, Btl, 128);
    gemm_smallT<<<dim3(128, 2), 128>>>(h1, W3h, b3h, Bth, Btl, 256);
    gemm_mma<<<dim3(32, SPLITK, 3), 256, GEMM_SMEM>>>(G1h, G3h, Bth, Btl, part);
    { RedOut o0 = {nullptr, fA, h2, 1};
      RedOut o1 = {a1, nullptr, nullptr, 3};
      RedOut o2 = {a3, nullptr, nullptr, 3};
      reduce_ep<<<dim3(512, 3), 256>>>(part, nullptr, o0, o1, o2); }

    // ---- mixup (fp16 out) + MHA mix (nh=2) on HMMA ----
    mix_kernel<<<512, 256>>>(a1, a3, perm, lam, fB, fC);
    hmma_nt128<<<dim3(32, 3, 2), 256, GEMM_SMEM>>>(fB, fC, whm, wlm,
                                                   bqkv_mix, qkv0, qkv1, 384);
    attn_kernel<<<512, 256>>>(qkv0, qkv1, om, 2);
    gemm_nt<<<dim3(128, 4), 256>>>(om, Wo_mix, bo_mix, hmix, nullptr, 128);

    // ---- h2m = relu(G1 @ (hmix@W2m+b2m) + hmix) ----
    gemm_smallT<<<dim3(128, 2), 128>>>(hmix, W2m, b2m, Bth, Btl, 0);
    gemm_mma<<<dim3(32, SPLITK, 1), 256, GEMM_SMEM>>>(G1h, G3h, Bth, Btl, part);
    { RedOut o = {h2m, nullptr, hmix, 1};
      reduce_ep<<<dim3(512, 1), 256>>>(part, nullptr, o, RO_NONE, RO_NONE); }

    // ---- h3c2 = relu(G1 @ (h2m@W3m+b3m) + h2m) * beta -> fp16 fB ----
    gemm_smallT<<<dim3(128, 2), 128>>>(h2m, W3m, b3m, Bth, Btl, 0);
    gemm_mma<<<dim3(32, SPLITK, 1), 256, GEMM_SMEM>>>(G1h, G3h, Bth, Btl, part);
    { RedOut o = {nullptr, fB, h2m, 4};
      reduce_ep<<<dim3(512, 1), 256>>>(part, beta, o, RO_NONE, RO_NONE); }

    // ---- MHA fus (nh=4) on HMMA ----
    hmma_nt128<<<dim3(32, 3, 2), 256, GEMM_SMEM>>>(fA, fB, whf, wlf,
                                                   bqkv_fus, qkv0, qkv1, 384);
    attn_kernel<<<512, 256>>>(qkv0, qkv1, om, 4);
    gemm_nt<<<dim3(128, 4), 256>>>(om, Wo_fus, bo_fus, h3, out_h3, 128);

    // ---- edge classifier ----
    edge_kernel<<<512, 256>>>(h3, ei, Wc, bc, out_edge);
}

// round 13
// speedup vs baseline: 7.0167x; 1.0405x over previous
#include <cuda_runtime.h>
#include <cuda_fp16.h>
#include <cstdint>

#define N_NODES 4096
#define HDIM    128
#define N_EDGES 131072
#define KTOT    4096
#define SPLITK  8
#define KCTA    (KTOT / SPLITK)     // 512
#define BK      32
#define NCH     (KCTA / BK)         // 16

// ---------------- scratch (static device arrays; no allocation) ----------------
__device__ float g_h1[N_NODES * 128];
__device__ float g_h2[N_NODES * 128];
__device__ float g_a1[N_NODES * 128];
__device__ float g_a3[N_NODES * 128];
__device__ float g_qkv0[N_NODES * 384];
__device__ float g_qkv1[N_NODES * 384];
__device__ float g_om[N_NODES * 128];
__device__ float g_hmix[N_NODES * 128];
__device__ float g_h2m[N_NODES * 128];
__device__ float g_h3[N_NODES * 128];
// fp16 (single) propagation matrices
__device__ __half g_G1h[(size_t)KTOT * KTOT];
__device__ __half g_G3h[(size_t)KTOT * KTOT];
// transposed fp16 hi/lo split of RHS (up to 384 rows x 4096 cols)
__device__ __half g_Bth[384 * KTOT];
__device__ __half g_Btl[384 * KTOT];
// fp16 single A-operands for the K=128 HMMA (qkv) kernels
__device__ __half g_fA[N_NODES * 128];
__device__ __half g_fB[N_NODES * 128];
__device__ __half g_fC[N_NODES * 128];
// fp16 hi/lo of qkv weights [384,128]
__device__ __half g_whm[384 * 128];
__device__ __half g_wlm[384 * 128];
__device__ __half g_whf[384 * 128];
__device__ __half g_wlf[384 * 128];
// split-K partials [3][SPLITK][4096][128]
__device__ float g_part[(size_t)3 * SPLITK * N_NODES * 128];

// ============================ asm helpers =================================
__device__ __forceinline__ uint32_t smem_to_u32(const void* p) {
    uint32_t a;
    asm("{ .reg .u64 t; cvta.to.shared.u64 t, %1; cvt.u32.u64 %0, t; }" : "=r"(a) : "l"(p));
    return a;
}
__device__ __forceinline__ void cp16(uint32_t s, const void* g) {
    asm volatile("cp.async.cg.shared.global [%0], [%1], 16;" :: "r"(s), "l"(g));
}
__device__ __forceinline__ void cp_commit() {
    asm volatile("cp.async.commit_group;" ::: "memory");
}
template <int Ng>
__device__ __forceinline__ void cp_wait() {
    asm volatile("cp.async.wait_group %0;" :: "n"(Ng) : "memory");
}
__device__ __forceinline__ void ldsm4(uint32_t* r, uint32_t addr) {
    asm volatile("ldmatrix.sync.aligned.m8n8.x4.shared.b16 {%0,%1,%2,%3}, [%4];"
        : "=r"(r[0]), "=r"(r[1]), "=r"(r[2]), "=r"(r[3]) : "r"(addr));
}
__device__ __forceinline__ void mma16816(float* d, const uint32_t* a, uint32_t b0, uint32_t b1) {
    asm volatile(
        "mma.sync.aligned.m16n8k16.row.col.f32.f16.f16.f32 "
        "{%0,%1,%2,%3}, {%4,%5,%6,%7}, {%8,%9}, {%0,%1,%2,%3};"
        : "+f"(d[0]), "+f"(d[1]), "+f"(d[2]), "+f"(d[3])
        : "r"(a[0]), "r"(a[1]), "r"(a[2]), "r"(a[3]), "r"(b0), "r"(b1));
}
__device__ __forceinline__ void split2h(float v, __half& h, __half& l) {
    h = __float2half_rn(v);
    l = __float2half_rn(v - __half2float(h));
}

// ===========================================================================
// Big tensor-core GEMM via mma.sync (fp16 2-term):
// Part[z][ks][4096][128] = A@Bh^T + A@Bl^T over K range of ks.
// z = blockIdx.z selects B rows z*128 and (z==2 ? A1 : A0) operand.
// CTA tile 128x128, BK=32, 8 warps (4x2), warp tile 32x64.
// 3-stage cp.async pipeline, ONE __syncthreads per chunk.
// ===========================================================================
#define TSTRIDE 80                    // bytes per smem row (32 fp16 = 64 B + 16 pad)
#define TILE_B  (128 * TSTRIDE)       // 10240 B per operand tile
#define STAGE   (3 * TILE_B)          // A | Bh | Bl   (30720 B)
#define GEMM_SMEM (3 * STAGE)         // 92160 B (3 stages)
#define NT_SMEM   (2 * STAGE)         // 61440 B (hmma_nt128, 2 stages)

__global__ __launch_bounds__(256, 2) void gemm_mma(
    const __half* __restrict__ A0, const __half* __restrict__ A1,
    const __half* __restrict__ Bh, const __half* __restrict__ Bl,
    float* __restrict__ Part)
{
    extern __shared__ char smraw[];
    const uint32_t sm0 = smem_to_u32(smraw);

    const int tid = threadIdx.x;
    const int lane = tid & 31, wid = tid >> 5;
    const int wm = wid >> 1, wn = wid & 1;
    const int m0 = blockIdx.x * 128;
    const int ks = blockIdx.y;
    const int z  = blockIdx.z;
    const int kb = ks * KCTA;

    const __half* gA  = ((z == 2) ? A1 : A0) + (size_t)m0 * KTOT + kb;
    const __half* gBh = Bh + (size_t)(z * 128) * KTOT + kb;
    const __half* gBl = Bl + (size_t)(z * 128) * KTOT + kb;

    const int r0i = tid >> 2, c0i = tid & 3;
    const int r1i = (tid + 256) >> 2, c1i = tid & 3;
    const uint32_t so0 = (uint32_t)r0i * TSTRIDE + c0i * 16;
    const uint32_t so1 = (uint32_t)r1i * TSTRIDE + c1i * 16;

    const uint32_t aO = (uint32_t)(wm * 32 + (lane & 15)) * TSTRIDE + (lane >> 4) * 16;
    const uint32_t bO = (uint32_t)(wn * 64 + (lane & 7) + ((lane >> 4) & 1) * 8) * TSTRIDE
                      + ((lane >> 3) & 1) * 16;

    float acc[2][8][4];
#pragma unroll
    for (int i = 0; i < 2; i++)
#pragma unroll
        for (int j = 0; j < 8; j++)
#pragma unroll
            for (int q = 0; q < 4; q++) acc[i][j][q] = 0.0f;

#define LOAD_CHUNK(ci, s) do { \
    uint32_t sbase = sm0 + (s) * STAGE; \
    size_t g0 = (size_t)r0i * KTOT + (ci) * BK + c0i * 8; \
    size_t g1 = (size_t)r1i * KTOT + (ci) * BK + c1i * 8; \
    cp16(sbase + so0,              gA  + g0); \
    cp16(sbase + so1,              gA  + g1); \
    cp16(sbase + TILE_B + so0,     gBh + g0); \
    cp16(sbase + TILE_B + so1,     gBh + g1); \
    cp16(sbase + 2 * TILE_B + so0, gBl + g0); \
    cp16(sbase + 2 * TILE_B + so1, gBl + g1); \
} while (0)

    // prologue: stages 0 and 1 in flight (one group each)
    LOAD_CHUNK(0, 0);
    cp_commit();
    LOAD_CHUNK(1, 1);
    cp_commit();

    int stage = 0;       // stage holding chunk ci
    int lstage = 2;      // stage to load chunk ci+2 into
    for (int ci = 0; ci < NCH; ++ci) {
        // chunk ci's group is complete once <=1 newer groups remain pending
        cp_wait<1>();
        __syncthreads();   // make all threads' copies visible + protect stage reuse

        // issue loads for chunk ci+2 into stage (ci+2)%3 == (ci-1)%3 (safe post-barrier)
        if (ci + 2 < NCH) LOAD_CHUNK(ci + 2, lstage);
        cp_commit();       // unconditional: empty groups keep the wait window uniform

        const uint32_t sb = sm0 + stage * STAGE;
#pragma unroll
        for (int kk = 0; kk < 2; ++kk) {
            const uint32_t ko = kk * 32;    // 16 fp16 = 32 B
            uint32_t av[2][4], bf[4][4];
            ldsm4(av[0], sb + aO + ko);
            ldsm4(av[1], sb + aO + 16 * TSTRIDE + ko);
#pragma unroll
            for (int j = 0; j < 4; j++)
                ldsm4(bf[j], sb + TILE_B + bO + j * 16 * TSTRIDE + ko);
#pragma unroll
            for (int i = 0; i < 2; i++)
#pragma unroll
                for (int j = 0; j < 4; j++) {
                    mma16816(acc[i][2 * j],     av[i], bf[j][0], bf[j][1]);
                    mma16816(acc[i][2 * j + 1], av[i], bf[j][2], bf[j][3]);
                }
#pragma unroll
            for (int j = 0; j < 4; j++)
                ldsm4(bf[j], sb + 2 * TILE_B + bO + j * 16 * TSTRIDE + ko);
#pragma unroll
            for (int i = 0; i < 2; i++)
#pragma unroll
                for (int j = 0; j < 4; j++) {
                    mma16816(acc[i][2 * j],     av[i], bf[j][0], bf[j][1]);
                    mma16816(acc[i][2 * j + 1], av[i], bf[j][2], bf[j][3]);
                }
        }
        stage = (stage == 2) ? 0 : stage + 1;
        lstage = (lstage == 2) ? 0 : lstage + 1;
    }

    float* outp = Part + ((size_t)(z * SPLITK + ks) * N_NODES + m0) * 128;
    const int rr = lane >> 2, c2 = (lane & 3) * 2;
#pragma unroll
    for (int i = 0; i < 2; i++) {
        const int row0 = wm * 32 + i * 16 + rr;
#pragma unroll
        for (int j = 0; j < 8; j++) {
            const int col = wn * 64 + j * 8 + c2;
            *(float2*)(outp + (size_t)row0 * 128 + col)       = make_float2(acc[i][j][0], acc[i][j][1]);
            *(float2*)(outp + (size_t)(row0 + 8) * 128 + col) = make_float2(acc[i][j][2], acc[i][j][3]);
        }
    }
#undef LOAD_CHUNK
}

// ===========================================================================
// K=128 HMMA NT GEMM (fp16 2-term): C[4096, No] = A@W^T + bias.
// A fp16 single [4096,128]; W fp16 h/l [No,128]. grid (32, No/128, 2).
// ===========================================================================
__global__ __launch_bounds__(256, 2) void hmma_nt128(
    const __half* __restrict__ A0, const __half* __restrict__ A1,
    const __half* __restrict__ Wh, const __half* __restrict__ Wl,
    const float* __restrict__ bias,
    float* __restrict__ C0, float* __restrict__ C1, int No)
{
    extern __shared__ char smraw[];
    const uint32_t sm0 = smem_to_u32(smraw);

    const int tid = threadIdx.x;
    const int lane = tid & 31, wid = tid >> 5;
    const int wm = wid >> 1, wn = wid & 1;
    const int m0 = blockIdx.x * 128;
    const int n0 = blockIdx.y * 128;
    const int z  = blockIdx.z;

    const __half* gA  = (z ? A1 : A0) + (size_t)m0 * 128;
    const __half* gBh = Wh + (size_t)n0 * 128;
    const __half* gBl = Wl + (size_t)n0 * 128;
    float* C = z ? C1 : C0;

    const int r0i = tid >> 2, c0i = tid & 3;
    const int r1i = (tid + 256) >> 2, c1i = tid & 3;
    const uint32_t so0 = (uint32_t)r0i * TSTRIDE + c0i * 16;
    const uint32_t so1 = (uint32_t)r1i * TSTRIDE + c1i * 16;

    const uint32_t aO = (uint32_t)(wm * 32 + (lane & 15)) * TSTRIDE + (lane >> 4) * 16;
    const uint32_t bO = (uint32_t)(wn * 64 + (lane & 7) + ((lane >> 4) & 1) * 8) * TSTRIDE
                      + ((lane >> 3) & 1) * 16;

    float acc[2][8][4];
#pragma unroll
    for (int i = 0; i < 2; i++)
#pragma unroll
        for (int j = 0; j < 8; j++)
#pragma unroll
            for (int q = 0; q < 4; q++) acc[i][j][q] = 0.0f;

#define LOAD_CHUNK2(ci, s) do { \
    uint32_t sbase = sm0 + (s) * STAGE; \
    size_t g0 = (size_t)r0i * 128 + (ci) * BK + c0i * 8; \
    size_t g1 = (size_t)r1i * 128 + (ci) * BK + c1i * 8; \
    cp16(sbase + so0,              gA  + g0); \
    cp16(sbase + so1,              gA  + g1); \
    cp16(sbase + TILE_B + so0,     gBh + g0); \
    cp16(sbase + TILE_B + so1,     gBh + g1); \
    cp16(sbase + 2 * TILE_B + so0, gBl + g0); \
    cp16(sbase + 2 * TILE_B + so1, gBl + g1); \
} while (0)

    LOAD_CHUNK2(0, 0);
    cp_commit();

    for (int ci = 0; ci < 4; ++ci) {
        if (ci + 1 < 4) { LOAD_CHUNK2(ci + 1, (ci + 1) & 1); cp_commit(); }
        if (ci + 1 < 4) cp_wait<1>(); else cp_wait<0>();
        __syncthreads();

        const uint32_t sb = sm0 + (ci & 1) * STAGE;
#pragma unroll
        for (int kk = 0; kk < 2; ++kk) {
            const uint32_t ko = kk * 32;
            uint32_t av[2][4], bf[4][4];
            ldsm4(av[0], sb + aO + ko);
            ldsm4(av[1], sb + aO + 16 * TSTRIDE + ko);
#pragma unroll
            for (int j = 0; j < 4; j++)
                ldsm4(bf[j], sb + TILE_B + bO + j * 16 * TSTRIDE + ko);
#pragma unroll
            for (int i = 0; i < 2; i++)
#pragma unroll
                for (int j = 0; j < 4; j++) {
                    mma16816(acc[i][2 * j],     av[i], bf[j][0], bf[j][1]);
                    mma16816(acc[i][2 * j + 1], av[i], bf[j][2], bf[j][3]);
                }
#pragma unroll
            for (int j = 0; j < 4; j++)
                ldsm4(bf[j], sb + 2 * TILE_B + bO + j * 16 * TSTRIDE + ko);
#pragma unroll
            for (int i = 0; i < 2; i++)
#pragma unroll
                for (int j = 0; j < 4; j++) {
                    mma16816(acc[i][2 * j],     av[i], bf[j][0], bf[j][1]);
                    mma16816(acc[i][2 * j + 1], av[i], bf[j][2], bf[j][3]);
                }
        }
        __syncthreads();
    }

    const int rr = lane >> 2, c2 = (lane & 3) * 2;
#pragma unroll
    for (int i = 0; i < 2; i++) {
        const int row0 = m0 + wm * 32 + i * 16 + rr;
#pragma unroll
        for (int j = 0; j < 8; j++) {
            const int col = n0 + wn * 64 + j * 8 + c2;
            const float b0 = bias[col], b1 = bias[col + 1];
            *(float2*)(C + (size_t)row0 * No + col)
                = make_float2(acc[i][j][0] + b0, acc[i][j][1] + b1);
            *(float2*)(C + (size_t)(row0 + 8) * No + col)
                = make_float2(acc[i][j][2] + b0, acc[i][j][3] + b1);
        }
    }
#undef LOAD_CHUNK2
}

// ---------------------------------------------------------------------------
// reduce SPLITK partials + epilogue; up to 3 outputs via grid.y.
// mode 0: relu(z); 1: relu(z+res); 3: z; 4: relu(z+res)*scale
// Optional fp16 single output Ch besides/instead of fp32 C.
// ---------------------------------------------------------------------------
struct RedOut {
    float* C;
    __half* Ch;
    const float* res;
    int mode;
};

__global__ __launch_bounds__(256) void reduce_ep(
    const float* __restrict__ P, const float* __restrict__ scale_p,
    RedOut o0, RedOut o1, RedOut o2)
{
    const int y = blockIdx.y;
    RedOut o = (y == 0) ? o0 : (y == 1) ? o1 : o2;

    int i = blockIdx.x * 256 + threadIdx.x;       // float4 index, 131072 per slot
    const float4* p = (const float4*)P + (size_t)y * SPLITK * 131072;
    float4 z = p[i];
#pragma unroll
    for (int s = 1; s < SPLITK; s++) {
        float4 a = p[i + (size_t)s * 131072];
        z.x += a.x; z.y += a.y; z.z += a.z; z.w += a.w;
    }
    if (o.mode == 1 || o.mode == 4) {
        float4 r = ((const float4*)o.res)[i];
        z.x += r.x; z.y += r.y; z.z += r.z; z.w += r.w;
    }
    if (o.mode != 3) {
        z.x = fmaxf(z.x, 0.0f); z.y = fmaxf(z.y, 0.0f);
        z.z = fmaxf(z.z, 0.0f); z.w = fmaxf(z.w, 0.0f);
    }
    if (o.mode == 4) {
        float s = *scale_p;
        z.x *= s; z.y *= s; z.z *= s; z.w *= s;
    }
    if (o.C) ((float4*)o.C)[i] = z;
    if (o.Ch) {
        union { __half b[4]; uint2 u; } H;
        H.b[0] = __float2half_rn(z.x); H.b[1] = __float2half_rn(z.y);
        H.b[2] = __float2half_rn(z.z); H.b[3] = __float2half_rn(z.w);
        ((uint2*)o.Ch)[i] = H.u;
    }
}

// ---------------------------------------------------------------------------
// G matrices: fp32 -> fp16 single. grid (16384, 2)
// ---------------------------------------------------------------------------
__global__ __launch_bounds__(256) void conv_g(
    const float* __restrict__ X0, __half* __restrict__ Y0,
    const float* __restrict__ X1, __half* __restrict__ Y1)
{
    const float* X = blockIdx.y ? X1 : X0;
    __half* Y = blockIdx.y ? Y1 : Y0;
    size_t i = (size_t)blockIdx.x * 256 + threadIdx.x;
    float4 v = ((const float4*)X)[i];
    union { __half b[4]; uint2 u; } H;
    H.b[0] = __float2half_rn(v.x); H.b[1] = __float2half_rn(v.y);
    H.b[2] = __float2half_rn(v.z); H.b[3] = __float2half_rn(v.w);
    ((uint2*)Y)[i] = H.u;
}

// qkv weights: fp32 -> fp16 hi/lo pair. grid (48, 2)
__global__ __launch_bounds__(256) void conv_w(
    const float* __restrict__ X0, __half* __restrict__ H0, __half* __restrict__ L0,
    const float* __restrict__ X1, __half* __restrict__ H1, __half* __restrict__ L1)
{
    const float* X = blockIdx.y ? X1 : X0;
    __half* Xh = blockIdx.y ? H1 : H0;
    __half* Xl = blockIdx.y ? L1 : L0;
    size_t i = (size_t)blockIdx.x * 256 + threadIdx.x;
    float4 v = ((const float4*)X)[i];
    union { __half b[4]; uint2 u; } H, L;
    split2h(v.x, H.b[0], L.b[0]); split2h(v.y, H.b[1], L.b[1]);
    split2h(v.z, H.b[2], L.b[2]); split2h(v.w, H.b[3], L.b[3]);
    ((uint2*)Xh)[i] = H.u;
    ((uint2*)Xl)[i] = L.u;
}

// ---------------------------------------------------------------------------
// Small NN GEMM (K=128) + FUSED transpose/split(fp16) epilogue:
// Z = A[4096,128] @ B[128,128] + bias;  Bt[ro+n][k] = split_h/l(Z[k][n])
// grid (128 k-tiles of 32, 2 n-halves of 64), block 128.
// ---------------------------------------------------------------------------
__global__ __launch_bounds__(128, 4) void gemm_smallT(
    const float* __restrict__ A,
    const float* __restrict__ B,
    const float* __restrict__ bias,
    __half* __restrict__ Bth, __half* __restrict__ Btl,
    int ro)
{
    __shared__ float As[32 * 33];
    __shared__ float Bs[32 * 64];
    __shared__ float Cs[64 * 33];   // [n][k_local]
    const int t = threadIdx.x;
    const int m0 = blockIdx.x * 32;
    const int n0 = blockIdx.y * 64;
    const int tr = t >> 4, tc = t & 15;
    const int am = t >> 2, ak = (t & 3) * 8;

    float acc[4][4];
#pragma unroll
    for (int r = 0; r < 4; r++)
#pragma unroll
        for (int c = 0; c < 4; c++) acc[r][c] = 0.0f;

    const float* Ap = A + (size_t)(m0 + am) * 128 + ak;
    float4 a0, a1, bb[4];

    a0 = *(const float4*)(Ap);
    a1 = *(const float4*)(Ap + 4);
#pragma unroll
    for (int j = 0; j < 4; j++) {
        int f = t + j * 128;
        bb[j] = *(const float4*)(B + (size_t)(f >> 4) * 128 + n0 + (f & 15) * 4);
    }
    As[(ak + 0) * 33 + am] = a0.x; As[(ak + 1) * 33 + am] = a0.y;
    As[(ak + 2) * 33 + am] = a0.z; As[(ak + 3) * 33 + am] = a0.w;
    As[(ak + 4) * 33 + am] = a1.x; As[(ak + 5) * 33 + am] = a1.y;
    As[(ak + 6) * 33 + am] = a1.z; As[(ak + 7) * 33 + am] = a1.w;
#pragma unroll
    for (int j = 0; j < 4; j++) {
        int f = t + j * 128;
        *(float4*)&Bs[(f >> 4) * 64 + (f & 15) * 4] = bb[j];
    }
    __syncthreads();

    for (int it = 1; it <= 4; ++it) {
        if (it < 4) {
            int k0 = it << 5;
            a0 = *(const float4*)(Ap + k0);
            a1 = *(const float4*)(Ap + k0 + 4);
#pragma unroll
            for (int j = 0; j < 4; j++) {
                int f = t + j * 128;
                bb[j] = *(const float4*)(B + (size_t)(k0 + (f >> 4)) * 128 + n0 + (f & 15) * 4);
            }
        }
#pragma unroll
        for (int k = 0; k < 32; ++k) {
            float av[4];
#pragma unroll
            for (int r = 0; r < 4; r++) av[r] = As[k * 33 + tr * 4 + r];
            float4 b0 = *(const float4*)&Bs[k * 64 + tc * 4];
            float bv[4] = {b0.x, b0.y, b0.z, b0.w};
#pragma unroll
            for (int r = 0; r < 4; r++)
#pragma unroll
                for (int c = 0; c < 4; c++) acc[r][c] += av[r] * bv[c];
        }
        __syncthreads();
        if (it < 4) {
            As[(ak + 0) * 33 + am] = a0.x; As[(ak + 1) * 33 + am] = a0.y;
            As[(ak + 2) * 33 + am] = a0.z; As[(ak + 3) * 33 + am] = a0.w;
            As[(ak + 4) * 33 + am] = a1.x; As[(ak + 5) * 33 + am] = a1.y;
            As[(ak + 6) * 33 + am] = a1.z; As[(ak + 7) * 33 + am] = a1.w;
#pragma unroll
            for (int j = 0; j < 4; j++) {
                int f = t + j * 128;
                *(float4*)&Bs[(f >> 4) * 64 + (f & 15) * 4] = bb[j];
            }
            __syncthreads();
        }
    }

    // stage transposed (+bias) into smem: Cs[n][k]
#pragma unroll
    for (int r = 0; r < 4; r++)
#pragma unroll
        for (int c = 0; c < 4; c++) {
            int n = tc * 4 + c;
            Cs[n * 33 + tr * 4 + r] = acc[r][c] + bias[n0 + n];
        }
    __syncthreads();

    // thread t: n = t>>1 (0..63), k-half = (t&1)*16 -> 16 values
    {
        const int n = t >> 1;
        const int kh = (t & 1) * 16;
        union { __half b[8]; uint4 u; } Hp, Lp;
        __half* oh = Bth + (size_t)(ro + n0 + n) * KTOT + m0 + kh;
        __half* ol = Btl + (size_t)(ro + n0 + n) * KTOT + m0 + kh;
#pragma unroll
        for (int g = 0; g < 2; g++) {
#pragma unroll
            for (int q = 0; q < 8; q++)
                split2h(Cs[n * 33 + kh + g * 8 + q], Hp.b[q], Lp.b[q]);
            *(uint4*)(oh + g * 8) = Hp.u;
            *(uint4*)(ol + g * 8) = Lp.u;
        }
    }
}

// ---------------------------------------------------------------------------
// NT GEMM (fp32 SIMT, kept for the small Wo projections):
// C[M, No] = A[M,128] @ W[No,128]^T + bias
// ---------------------------------------------------------------------------
__global__ __launch_bounds__(256) void gemm_nt(
    const float* __restrict__ A, const float* __restrict__ W,
    const float* __restrict__ bias, float* __restrict__ C,
    float* __restrict__ Cdup, int No)
{
    __shared__ float As[32 * 129];
    __shared__ float Ws[32 * 129];
    const int t = threadIdx.x;
    const int m0 = blockIdx.x * 32, n0 = blockIdx.y * 32;

    for (int i = t; i < 32 * 128; i += 256) {
        int r = i >> 7, k = i & 127;
        As[r * 129 + k] = A[(size_t)(m0 + r) * 128 + k];
        Ws[r * 129 + k] = W[(size_t)(n0 + r) * 128 + k];
    }
    __syncthreads();

    const int tr = t >> 4, tc = t & 15;
    const float* a0p = &As[(tr * 2) * 129];
    const float* a1p = &As[(tr * 2 + 1) * 129];
    const float* w0p = &Ws[(tc * 2) * 129];
    const float* w1p = &Ws[(tc * 2 + 1) * 129];

    float acc00 = 0, acc01 = 0, acc10 = 0, acc11 = 0;
#pragma unroll 16
    for (int k = 0; k < 128; k++) {
        float a0 = a0p[k], a1 = a1p[k], w0 = w0p[k], w1 = w1p[k];
        acc00 += a0 * w0; acc01 += a0 * w1;
        acc10 += a1 * w0; acc11 += a1 * w1;
    }
    int row0 = m0 + tr * 2, col0 = n0 + tc * 2;
    float v00 = acc00 + bias[col0], v01 = acc01 + bias[col0 + 1];
    float v10 = acc10 + bias[col0], v11 = acc11 + bias[col0 + 1];
    C[(size_t)row0 * No + col0]           = v00;
    C[(size_t)row0 * No + col0 + 1]       = v01;
    C[(size_t)(row0 + 1) * No + col0]     = v10;
    C[(size_t)(row0 + 1) * No + col0 + 1] = v11;
    if (Cdup) {
        Cdup[(size_t)row0 * No + col0]           = v00;
        Cdup[(size_t)row0 * No + col0 + 1]       = v01;
        Cdup[(size_t)(row0 + 1) * No + col0]     = v10;
        Cdup[(size_t)(row0 + 1) * No + col0 + 1] = v11;
    }
}

// ---------------------------------------------------------------------------
// Mixup, emitting fp16 single (consumed as A by hmma_nt128).
// ---------------------------------------------------------------------------
__global__ void mix_kernel(const float* __restrict__ a1, const float* __restrict__ a3,
                           const int* __restrict__ perm, const float* __restrict__ lam,
                           __half* __restrict__ m1h, __half* __restrict__ m3h)
{
    int i = blockIdx.x * blockDim.x + threadIdx.x;
    int row = i >> 5, q = i & 31;
    float l = lam[0], il = 1.0f - l;
    int pr = perm[row];
    union { __half b[4]; uint2 u; } H;

    float4 x = ((const float4*)a1)[row * 32 + q];
    float4 y = ((const float4*)a1)[pr * 32 + q];
    H.b[0] = __float2half_rn(l * x.x + il * y.x);
    H.b[1] = __float2half_rn(l * x.y + il * y.y);
    H.b[2] = __float2half_rn(l * x.z + il * y.z);
    H.b[3] = __float2half_rn(l * x.w + il * y.w);
    ((uint2*)m1h)[row * 32 + q] = H.u;

    x = ((const float4*)a3)[row * 32 + q];
    y = ((const float4*)a3)[pr * 32 + q];
    H.b[0] = __float2half_rn(l * x.x + il * y.x);
    H.b[1] = __float2half_rn(l * x.y + il * y.y);
    H.b[2] = __float2half_rn(l * x.z + il * y.z);
    H.b[3] = __float2half_rn(l * x.w + il * y.w);
    ((uint2*)m3h)[row * 32 + q] = H.u;
}

__global__ void attn_kernel(const float* __restrict__ qkv0, const float* __restrict__ qkv1,
                            float* __restrict__ om, int nh)
{
    int gt = blockIdx.x * blockDim.x + threadIdx.x;
    int node = gt >> 5;
    int lane = gt & 31;
    const float4* p0 = (const float4*)(qkv0 + (size_t)node * 384);
    const float4* p1 = (const float4*)(qkv1 + (size_t)node * 384);
    float4 q0 = p0[lane], k0 = p0[32 + lane], v0 = p0[64 + lane];
    float4 q1 = p1[lane], k1 = p1[32 + lane], v1 = p1[64 + lane];

    float p00 = q0.x * k0.x + q0.y * k0.y + q0.z * k0.z + q0.w * k0.w;
    float p01 = q0.x * k1.x + q0.y * k1.y + q0.z * k1.z + q0.w * k1.w;
    float p10 = q1.x * k0.x + q1.y * k0.y + q1.z * k0.z + q1.w * k0.w;
    float p11 = q1.x * k1.x + q1.y * k1.y + q1.z * k1.z + q1.w * k1.w;

    int hd = 128 / nh;
    int Wd = hd >> 2;
    for (int off = Wd >> 1; off; off >>= 1) {
        p00 += __shfl_xor_sync(0xffffffffu, p00, off);
        p01 += __shfl_xor_sync(0xffffffffu, p01, off);
        p10 += __shfl_xor_sync(0xffffffffu, p10, off);
        p11 += __shfl_xor_sync(0xffffffffu, p11, off);
    }
    float scl = rsqrtf((float)hd);
    float s00 = p00 * scl, s01 = p01 * scl, s10 = p10 * scl, s11 = p11 * scl;

    float mx0 = fmaxf(s00, s01);
    float e00 = expf(s00 - mx0), e01 = expf(s01 - mx0);
    float r0 = 1.0f / (e00 + e01);
    float mx1 = fmaxf(s10, s11);
    float e10 = expf(s10 - mx1), e11 = expf(s11 - mx1);
    float r1 = 1.0f / (e10 + e11);

    float c0 = 0.5f * (e00 * r0 + e10 * r1);
    float c1 = 0.5f * (e01 * r0 + e11 * r1);

    float4 o;
    o.x = c0 * v0.x + c1 * v1.x;
    o.y = c0 * v0.y + c1 * v1.y;
    o.z = c0 * v0.z + c1 * v1.z;
    o.w = c0 * v0.w + c1 * v1.w;
    ((float4*)(om + (size_t)node * 128))[lane] = o;
}

__global__ __launch_bounds__(256) void edge_kernel(
    const float* __restrict__ h3, const int* __restrict__ ei,
    const float* __restrict__ Wc, const float* __restrict__ bc,
    float* __restrict__ out)
{
    __shared__ float wcs[512];
    __shared__ float bcs[2];
    int t = threadIdx.x;
    for (int i = t; i < 512; i += 256) wcs[i] = Wc[i];
    if (t < 2) bcs[t] = bc[t];
    __syncthreads();

    int e = blockIdx.x * 256 + t;
    int i0 = ei[e], i1 = ei[N_EDGES + e];
    const float4* r0 = (const float4*)(h3 + (size_t)i0 * 128);
    const float4* r1 = (const float4*)(h3 + (size_t)i1 * 128);
    float acc0 = bcs[0], acc1 = bcs[1];
#pragma unroll 8
    for (int q = 0; q < 32; q++) {
        float4 f = r0[q];
        int d = q * 4;
        acc0 += f.x * wcs[2 * d] + f.y * wcs[2 * (d + 1)] + f.z * wcs[2 * (d + 2)] + f.w * wcs[2 * (d + 3)];
        acc1 += f.x * wcs[2 * d + 1] + f.y * wcs[2 * (d + 1) + 1] + f.z * wcs[2 * (d + 2) + 1] + f.w * wcs[2 * (d + 3) + 1];
    }
#pragma unroll 8
    for (int q = 0; q < 32; q++) {
        float4 f = r1[q];
        int d = 128 + q * 4;
        acc0 += f.x * wcs[2 * d] + f.y * wcs[2 * (d + 1)] + f.z * wcs[2 * (d + 2)] + f.w * wcs[2 * (d + 3)];
        acc1 += f.x * wcs[2 * d + 1] + f.y * wcs[2 * (d + 1) + 1] + f.z * wcs[2 * (d + 2) + 1] + f.w * wcs[2 * (d + 3) + 1];
    }
    out[(size_t)e * 2]     = acc0;
    out[(size_t)e * 2 + 1] = acc1;
}

// ---------------------------------------------------------------------------
extern "C" void kernel_launch(void* const* d_in, const int* in_sizes, int n_in,
                              void* d_out, int out_size)
{
    const float* x    = (const float*)d_in[0];
    const float* G1   = (const float*)d_in[1];
    const float* G3   = (const float*)d_in[2];
    const int*   ei   = (const int*)d_in[3];
    const int*   perm = (const int*)d_in[4];
    const float* lam  = (const float*)d_in[5];
    const float* beta = (const float*)d_in[6];
    const float* W1 = (const float*)d_in[7];   const float* b1 = (const float*)d_in[8];
    const float* W2 = (const float*)d_in[9];   const float* b2 = (const float*)d_in[10];
    const float* W3 = (const float*)d_in[11];  const float* b3 = (const float*)d_in[12];
    const float* W1h = (const float*)d_in[13]; const float* b1h = (const float*)d_in[14];
    const float* W3h = (const float*)d_in[15]; const float* b3h = (const float*)d_in[16];
    const float* W2m = (const float*)d_in[17]; const float* b2m = (const float*)d_in[18];
    const float* W3m = (const float*)d_in[19]; const float* b3m = (const float*)d_in[20];
    const float* Wqkv_mix = (const float*)d_in[21]; const float* bqkv_mix = (const float*)d_in[22];
    const float* Wo_mix   = (const float*)d_in[23]; const float* bo_mix   = (const float*)d_in[24];
    const float* Wqkv_fus = (const float*)d_in[25]; const float* bqkv_fus = (const float*)d_in[26];
    const float* Wo_fus   = (const float*)d_in[27]; const float* bo_fus   = (const float*)d_in[28];
    const float* Wc = (const float*)d_in[29];  const float* bc = (const float*)d_in[30];

    float *h1, *h2, *a1, *a3, *qkv0, *qkv1, *om, *hmix, *h2m, *h3;
    float* part;
    __half *G1h, *G3h, *Bth, *Btl, *fA, *fB, *fC, *whm, *wlm, *whf, *wlf;
    cudaGetSymbolAddress((void**)&h1, g_h1);
    cudaGetSymbolAddress((void**)&h2, g_h2);
    cudaGetSymbolAddress((void**)&a1, g_a1);
    cudaGetSymbolAddress((void**)&a3, g_a3);
    cudaGetSymbolAddress((void**)&qkv0, g_qkv0);
    cudaGetSymbolAddress((void**)&qkv1, g_qkv1);
    cudaGetSymbolAddress((void**)&om, g_om);
    cudaGetSymbolAddress((void**)&hmix, g_hmix);
    cudaGetSymbolAddress((void**)&h2m, g_h2m);
    cudaGetSymbolAddress((void**)&h3, g_h3);
    cudaGetSymbolAddress((void**)&part, g_part);
    cudaGetSymbolAddress((void**)&G1h, g_G1h);
    cudaGetSymbolAddress((void**)&G3h, g_G3h);
    cudaGetSymbolAddress((void**)&Bth, g_Bth);
    cudaGetSymbolAddress((void**)&Btl, g_Btl);
    cudaGetSymbolAddress((void**)&fA, g_fA);
    cudaGetSymbolAddress((void**)&fB, g_fB);
    cudaGetSymbolAddress((void**)&fC, g_fC);
    cudaGetSymbolAddress((void**)&whm, g_whm);
    cudaGetSymbolAddress((void**)&wlm, g_wlm);
    cudaGetSymbolAddress((void**)&whf, g_whf);
    cudaGetSymbolAddress((void**)&wlf, g_wlf);

    cudaFuncSetAttribute(gemm_mma, cudaFuncAttributeMaxDynamicSharedMemorySize, GEMM_SMEM);
    cudaFuncSetAttribute(hmma_nt128, cudaFuncAttributeMaxDynamicSharedMemorySize, NT_SMEM);

    float* out_edge = (float*)d_out;
    float* out_h3   = out_edge + (size_t)N_EDGES * 2;

    const RedOut RO_NONE = {nullptr, nullptr, nullptr, 3};

    // convert G matrices (fp16 single) and qkv weights (fp16 pair)
    conv_g<<<dim3(16384, 2), 256>>>(G1, G1h, G3, G3h);
    conv_w<<<dim3(48, 2), 256>>>(Wqkv_mix, whm, wlm, Wqkv_fus, whf, wlf);

    // ---- h1 = relu(G1 @ (x@W1+b1)) ----
    gemm_smallT<<<dim3(128, 2), 128>>>(x, W1, b1, Bth, Btl, 0);
    gemm_mma<<<dim3(32, SPLITK, 1), 256, GEMM_SMEM>>>(G1h, G3h, Bth, Btl, part);
    { RedOut o = {h1, nullptr, nullptr, 0};
      reduce_ep<<<dim3(512, 1), 256>>>(part, nullptr, o, RO_NONE, RO_NONE); }

    // ---- h2 = relu(G1 @ (h1@W2+b2) + h1) ----
    gemm_smallT<<<dim3(128, 2), 128>>>(h1, W2, b2, Bth, Btl, 0);
    gemm_mma<<<dim3(32, SPLITK, 1), 256, GEMM_SMEM>>>(G1h, G3h, Bth, Btl, part);
    { RedOut o = {h2, nullptr, h1, 1};
      reduce_ep<<<dim3(512, 1), 256>>>(part, nullptr, o, RO_NONE, RO_NONE); }

    // ---- merged pass: z0: G1@t3 (+h2, relu) -> h3c1(fp16 fA); z1: G1@u1h -> a1; z2: G3@u3h -> a3 ----
    gemm_smallT<<<dim3(128, 2), 128>>>(h2, W3, b3, Bth, Btl, 0);
    gemm_smallT<<<dim3(128, 2), 128>>>(h1, W1h, b1h, Bth, Btl, 128);
    gemm_smallT<<<dim3(128, 2), 128>>>(h1, W3h, b3h, Bth, Btl, 256);
    gemm_mma<<<dim3(32, SPLITK, 3), 256, GEMM_SMEM>>>(G1h, G3h, Bth, Btl, part);
    { RedOut o0 = {nullptr, fA, h2, 1};
      RedOut o1 = {a1, nullptr, nullptr, 3};
      RedOut o2 = {a3, nullptr, nullptr, 3};
      reduce_ep<<<dim3(512, 3), 256>>>(part, nullptr, o0, o1, o2); }

    // ---- mixup (fp16 out) + MHA mix (nh=2) on HMMA ----
    mix_kernel<<<512, 256>>>(a1, a3, perm, lam, fB, fC);
    hmma_nt128<<<dim3(32, 3, 2), 256, NT_SMEM>>>(fB, fC, whm, wlm,
                                                 bqkv_mix, qkv0, qkv1, 384);
    attn_kernel<<<512, 256>>>(qkv0, qkv1, om, 2);
    gemm_nt<<<dim3(128, 4), 256>>>(om, Wo_mix, bo_mix, hmix, nullptr, 128);

    // ---- h2m = relu(G1 @ (hmix@W2m+b2m) + hmix) ----
    gemm_smallT<<<dim3(128, 2), 128>>>(hmix, W2m, b2m, Bth, Btl, 0);
    gemm_mma<<<dim3(32, SPLITK, 1), 256, GEMM_SMEM>>>(G1h, G3h, Bth, Btl, part);
    { RedOut o = {h2m, nullptr, hmix, 1};
      reduce_ep<<<dim3(512, 1), 256>>>(part, nullptr, o, RO_NONE, RO_NONE); }

    // ---- h3c2 = relu(G1 @ (h2m@W3m+b3m) + h2m) * beta -> fp16 fB ----
    gemm_smallT<<<dim3(128, 2), 128>>>(h2m, W3m, b3m, Bth, Btl, 0);
    gemm_mma<<<dim3(32, SPLITK, 1), 256, GEMM_SMEM>>>(G1h, G3h, Bth, Btl, part);
    { RedOut o = {nullptr, fB, h2m, 4};
      reduce_ep<<<dim3(512, 1), 256>>>(part, beta, o, RO_NONE, RO_NONE); }

    // ---- MHA fus (nh=4) on HMMA ----
    hmma_nt128<<<dim3(32, 3, 2), 256, NT_SMEM>>>(fA, fB, whf, wlf,
                                                 bqkv_fus, qkv0, qkv1, 384);
    attn_kernel<<<512, 256>>>(qkv0, qkv1, om, 4);
    gemm_nt<<<dim3(128, 4), 256>>>(om, Wo_fus, bo_fus, h3, out_h3, 128);

    // ---- edge classifier ----
    edge_kernel<<<512, 256>>>(h3, ei, Wc, bc, out_edge);
}

// round 17
// speedup vs baseline: 7.2056x; 1.0269x over previous
#include <cuda_runtime.h>
#include <cuda_fp16.h>
#include <cstdint>

#define N_NODES 4096
#define HDIM    128
#define N_EDGES 131072
#define KTOT    4096
#define SPLITK  8
#define KCTA    (KTOT / SPLITK)     // 512
#define BK      32
#define NCH     (KCTA / BK)         // 16

// ---------------- scratch (static device arrays; no allocation) ----------------
__device__ float g_h1[N_NODES * 128];
__device__ float g_h2[N_NODES * 128];
__device__ float g_a1[N_NODES * 128];
__device__ float g_a3[N_NODES * 128];
__device__ float g_qkv0[N_NODES * 384];
__device__ float g_qkv1[N_NODES * 384];
__device__ float g_hmix[N_NODES * 128];
__device__ float g_h2m[N_NODES * 128];
__device__ float g_h3[N_NODES * 128];
// fp16 (single) propagation matrices
__device__ __half g_G1h[(size_t)KTOT * KTOT];
__device__ __half g_G3h[(size_t)KTOT * KTOT];
// transposed fp16 hi/lo split of RHS (up to 384 rows x 4096 cols)
__device__ __half g_Bth[384 * KTOT];
__device__ __half g_Btl[384 * KTOT];
// fp16 single A-operands for the K=128 HMMA kernels
__device__ __half g_fA[N_NODES * 128];
__device__ __half g_fB[N_NODES * 128];
__device__ __half g_fC[N_NODES * 128];
// fp16 hi/lo of qkv weights [384,128] and Wo weights [128,128]
__device__ __half g_whm[384 * 128];
__device__ __half g_wlm[384 * 128];
__device__ __half g_whf[384 * 128];
__device__ __half g_wlf[384 * 128];
__device__ __half g_wohm[128 * 128];
__device__ __half g_wolm[128 * 128];
__device__ __half g_wohf[128 * 128];
__device__ __half g_wolf[128 * 128];
// split-K partials [3][SPLITK][4096][128]
__device__ float g_part[(size_t)3 * SPLITK * N_NODES * 128];

// ============================ asm helpers =================================
__device__ __forceinline__ uint32_t smem_to_u32(const void* p) {
    uint32_t a;
    asm("{ .reg .u64 t; cvta.to.shared.u64 t, %1; cvt.u32.u64 %0, t; }" : "=r"(a) : "l"(p));
    return a;
}
__device__ __forceinline__ void cp16(uint32_t s, const void* g) {
    asm volatile("cp.async.cg.shared.global [%0], [%1], 16;" :: "r"(s), "l"(g));
}
__device__ __forceinline__ void cp_commit() {
    asm volatile("cp.async.commit_group;" ::: "memory");
}
template <int Ng>
__device__ __forceinline__ void cp_wait() {
    asm volatile("cp.async.wait_group %0;" :: "n"(Ng) : "memory");
}
__device__ __forceinline__ void ldsm4(uint32_t* r, uint32_t addr) {
    asm volatile("ldmatrix.sync.aligned.m8n8.x4.shared.b16 {%0,%1,%2,%3}, [%4];"
        : "=r"(r[0]), "=r"(r[1]), "=r"(r[2]), "=r"(r[3]) : "r"(addr));
}
__device__ __forceinline__ void mma16816(float* d, const uint32_t* a, uint32_t b0, uint32_t b1) {
    asm volatile(
        "mma.sync.aligned.m16n8k16.row.col.f32.f16.f16.f32 "
        "{%0,%1,%2,%3}, {%4,%5,%6,%7}, {%8,%9}, {%0,%1,%2,%3};"
        : "+f"(d[0]), "+f"(d[1]), "+f"(d[2]), "+f"(d[3])
        : "r"(a[0]), "r"(a[1]), "r"(a[2]), "r"(a[3]), "r"(b0), "r"(b1));
}
__device__ __forceinline__ void split2h(float v, __half& h, __half& l) {
    h = __float2half_rn(v);
    l = __float2half_rn(v - __half2float(h));
}

// ===========================================================================
// Big tensor-core GEMM via mma.sync (fp16 2-term), 3-stage pipeline.
// Part[z][ks][4096][128] = A@Bh^T + A@Bl^T over K range of ks.
// ===========================================================================
#define TSTRIDE 80
#define TILE_B  (128 * TSTRIDE)
#define STAGE   (3 * TILE_B)          // A | Bh | Bl (30720 B)
#define GEMM_SMEM (3 * STAGE)         // 92160 B
#define NT_SMEM   (2 * STAGE)         // 61440 B

__global__ __launch_bounds__(256, 2) void gemm_mma(
    const __half* __restrict__ A0, const __half* __restrict__ A1,
    const __half* __restrict__ Bh, const __half* __restrict__ Bl,
    float* __restrict__ Part)
{
    extern __shared__ char smraw[];
    const uint32_t sm0 = smem_to_u32(smraw);

    const int tid = threadIdx.x;
    const int lane = tid & 31, wid = tid >> 5;
    const int wm = wid >> 1, wn = wid & 1;
    const int m0 = blockIdx.x * 128;
    const int ks = blockIdx.y;
    const int z  = blockIdx.z;
    const int kb = ks * KCTA;

    const __half* gA  = ((z == 2) ? A1 : A0) + (size_t)m0 * KTOT + kb;
    const __half* gBh = Bh + (size_t)(z * 128) * KTOT + kb;
    const __half* gBl = Bl + (size_t)(z * 128) * KTOT + kb;

    const int r0i = tid >> 2, c0i = tid & 3;
    const int r1i = (tid + 256) >> 2, c1i = tid & 3;
    const uint32_t so0 = (uint32_t)r0i * TSTRIDE + c0i * 16;
    const uint32_t so1 = (uint32_t)r1i * TSTRIDE + c1i * 16;

    const uint32_t aO = (uint32_t)(wm * 32 + (lane & 15)) * TSTRIDE + (lane >> 4) * 16;
    const uint32_t bO = (uint32_t)(wn * 64 + (lane & 7) + ((lane >> 4) & 1) * 8) * TSTRIDE
                      + ((lane >> 3) & 1) * 16;

    float acc[2][8][4];
#pragma unroll
    for (int i = 0; i < 2; i++)
#pragma unroll
        for (int j = 0; j < 8; j++)
#pragma unroll
            for (int q = 0; q < 4; q++) acc[i][j][q] = 0.0f;

#define LOAD_CHUNK(ci, s) do { \
    uint32_t sbase = sm0 + (s) * STAGE; \
    size_t g0 = (size_t)r0i * KTOT + (ci) * BK + c0i * 8; \
    size_t g1 = (size_t)r1i * KTOT + (ci) * BK + c1i * 8; \
    cp16(sbase + so0,              gA  + g0); \
    cp16(sbase + so1,              gA  + g1); \
    cp16(sbase + TILE_B + so0,     gBh + g0); \
    cp16(sbase + TILE_B + so1,     gBh + g1); \
    cp16(sbase + 2 * TILE_B + so0, gBl + g0); \
    cp16(sbase + 2 * TILE_B + so1, gBl + g1); \
} while (0)

    LOAD_CHUNK(0, 0);
    cp_commit();
    LOAD_CHUNK(1, 1);
    cp_commit();

    int stage = 0, lstage = 2;
    for (int ci = 0; ci < NCH; ++ci) {
        cp_wait<1>();
        __syncthreads();

        if (ci + 2 < NCH) LOAD_CHUNK(ci + 2, lstage);
        cp_commit();

        const uint32_t sb = sm0 + stage * STAGE;
#pragma unroll
        for (int kk = 0; kk < 2; ++kk) {
            const uint32_t ko = kk * 32;
            uint32_t av[2][4], bf[4][4];
            ldsm4(av[0], sb + aO + ko);
            ldsm4(av[1], sb + aO + 16 * TSTRIDE + ko);
#pragma unroll
            for (int j = 0; j < 4; j++)
                ldsm4(bf[j], sb + TILE_B + bO + j * 16 * TSTRIDE + ko);
#pragma unroll
            for (int i = 0; i < 2; i++)
#pragma unroll
                for (int j = 0; j < 4; j++) {
                    mma16816(acc[i][2 * j],     av[i], bf[j][0], bf[j][1]);
                    mma16816(acc[i][2 * j + 1], av[i], bf[j][2], bf[j][3]);
                }
#pragma unroll
            for (int j = 0; j < 4; j++)
                ldsm4(bf[j], sb + 2 * TILE_B + bO + j * 16 * TSTRIDE + ko);
#pragma unroll
            for (int i = 0; i < 2; i++)
#pragma unroll
                for (int j = 0; j < 4; j++) {
                    mma16816(acc[i][2 * j],     av[i], bf[j][0], bf[j][1]);
                    mma16816(acc[i][2 * j + 1], av[i], bf[j][2], bf[j][3]);
                }
        }
        stage = (stage == 2) ? 0 : stage + 1;
        lstage = (lstage == 2) ? 0 : lstage + 1;
    }

    float* outp = Part + ((size_t)(z * SPLITK + ks) * N_NODES + m0) * 128;
    const int rr = lane >> 2, c2 = (lane & 3) * 2;
#pragma unroll
    for (int i = 0; i < 2; i++) {
        const int row0 = wm * 32 + i * 16 + rr;
#pragma unroll
        for (int j = 0; j < 8; j++) {
            const int col = wn * 64 + j * 8 + c2;
            *(float2*)(outp + (size_t)row0 * 128 + col)       = make_float2(acc[i][j][0], acc[i][j][1]);
            *(float2*)(outp + (size_t)(row0 + 8) * 128 + col) = make_float2(acc[i][j][2], acc[i][j][3]);
        }
    }
#undef LOAD_CHUNK
}

// ===========================================================================
// K=128 HMMA NT GEMM (fp16 2-term): C[4096, No] = A@W^T + bias.
// grid (32, No/128, nz). Optional duplicate write Cdup (z==0 only).
// ===========================================================================
__global__ __launch_bounds__(256, 2) void hmma_nt128(
    const __half* __restrict__ A0, const __half* __restrict__ A1,
    const __half* __restrict__ Wh, const __half* __restrict__ Wl,
    const float* __restrict__ bias,
    float* __restrict__ C0, float* __restrict__ C1,
    float* __restrict__ Cdup, int No)
{
    extern __shared__ char smraw[];
    const uint32_t sm0 = smem_to_u32(smraw);

    const int tid = threadIdx.x;
    const int lane = tid & 31, wid = tid >> 5;
    const int wm = wid >> 1, wn = wid & 1;
    const int m0 = blockIdx.x * 128;
    const int n0 = blockIdx.y * 128;
    const int z  = blockIdx.z;

    const __half* gA  = (z ? A1 : A0) + (size_t)m0 * 128;
    const __half* gBh = Wh + (size_t)n0 * 128;
    const __half* gBl = Wl + (size_t)n0 * 128;
    float* C = z ? C1 : C0;

    const int r0i = tid >> 2, c0i = tid & 3;
    const int r1i = (tid + 256) >> 2, c1i = tid & 3;
    const uint32_t so0 = (uint32_t)r0i * TSTRIDE + c0i * 16;
    const uint32_t so1 = (uint32_t)r1i * TSTRIDE + c1i * 16;

    const uint32_t aO = (uint32_t)(wm * 32 + (lane & 15)) * TSTRIDE + (lane >> 4) * 16;
    const uint32_t bO = (uint32_t)(wn * 64 + (lane & 7) + ((lane >> 4) & 1) * 8) * TSTRIDE
                      + ((lane >> 3) & 1) * 16;

    float acc[2][8][4];
#pragma unroll
    for (int i = 0; i < 2; i++)
#pragma unroll
        for (int j = 0; j < 8; j++)
#pragma unroll
            for (int q = 0; q < 4; q++) acc[i][j][q] = 0.0f;

#define LOAD_CHUNK2(ci, s) do { \
    uint32_t sbase = sm0 + (s) * STAGE; \
    size_t g0 = (size_t)r0i * 128 + (ci) * BK + c0i * 8; \
    size_t g1 = (size_t)r1i * 128 + (ci) * BK + c1i * 8; \
    cp16(sbase + so0,              gA  + g0); \
    cp16(sbase + so1,              gA  + g1); \
    cp16(sbase + TILE_B + so0,     gBh + g0); \
    cp16(sbase + TILE_B + so1,     gBh + g1); \
    cp16(sbase + 2 * TILE_B + so0, gBl + g0); \
    cp16(sbase + 2 * TILE_B + so1, gBl + g1); \
} while (0)

    LOAD_CHUNK2(0, 0);
    cp_commit();

    for (int ci = 0; ci < 4; ++ci) {
        if (ci + 1 < 4) { LOAD_CHUNK2(ci + 1, (ci + 1) & 1); cp_commit(); }
        if (ci + 1 < 4) cp_wait<1>(); else cp_wait<0>();
        __syncthreads();

        const uint32_t sb = sm0 + (ci & 1) * STAGE;
#pragma unroll
        for (int kk = 0; kk < 2; ++kk) {
            const uint32_t ko = kk * 32;
            uint32_t av[2][4], bf[4][4];
            ldsm4(av[0], sb + aO + ko);
            ldsm4(av[1], sb + aO + 16 * TSTRIDE + ko);
#pragma unroll
            for (int j = 0; j < 4; j++)
                ldsm4(bf[j], sb + TILE_B + bO + j * 16 * TSTRIDE + ko);
#pragma unroll
            for (int i = 0; i < 2; i++)
#pragma unroll
                for (int j = 0; j < 4; j++) {
                    mma16816(acc[i][2 * j],     av[i], bf[j][0], bf[j][1]);
                    mma16816(acc[i][2 * j + 1], av[i], bf[j][2], bf[j][3]);
                }
#pragma unroll
            for (int j = 0; j < 4; j++)
                ldsm4(bf[j], sb + 2 * TILE_B + bO + j * 16 * TSTRIDE + ko);
#pragma unroll
            for (int i = 0; i < 2; i++)
#pragma unroll
                for (int j = 0; j < 4; j++) {
                    mma16816(acc[i][2 * j],     av[i], bf[j][0], bf[j][1]);
                    mma16816(acc[i][2 * j + 1], av[i], bf[j][2], bf[j][3]);
                }
        }
        __syncthreads();
    }

    const int rr = lane >> 2, c2 = (lane & 3) * 2;
#pragma unroll
    for (int i = 0; i < 2; i++) {
        const int row0 = m0 + wm * 32 + i * 16 + rr;
#pragma unroll
        for (int j = 0; j < 8; j++) {
            const int col = n0 + wn * 64 + j * 8 + c2;
            const float b0 = bias[col], b1 = bias[col + 1];
            float2 v0 = make_float2(acc[i][j][0] + b0, acc[i][j][1] + b1);
            float2 v1 = make_float2(acc[i][j][2] + b0, acc[i][j][3] + b1);
            *(float2*)(C + (size_t)row0 * No + col)       = v0;
            *(float2*)(C + (size_t)(row0 + 8) * No + col) = v1;
            if (Cdup && z == 0) {
                *(float2*)(Cdup + (size_t)row0 * No + col)       = v0;
                *(float2*)(Cdup + (size_t)(row0 + 8) * No + col) = v1;
            }
        }
    }
#undef LOAD_CHUNK2
}

// ---------------------------------------------------------------------------
// FUSED: split-K reduce (mode 0/1) + feature GEMM (K=128) + transpose/split.
// Block b: rows r0=b*32 of Z = reduce(P)+epilogue; writes Cout fp32;
// then Z2 = Zrows @ W + bias; writes Bt[n][b*32+k] fp16 h/l.
// grid 128, block 256.
// ---------------------------------------------------------------------------
__global__ __launch_bounds__(256) void reduce_small(
    const float* __restrict__ P,
    const float* __restrict__ res, int mode,
    float* __restrict__ Cout,
    const float* __restrict__ W, const float* __restrict__ bias,
    __half* __restrict__ Bth, __half* __restrict__ Btl)
{
    __shared__ char buf[33280];
    float* Cs = (float*)buf;                 // [32][132] A tile (and later Cs2 [128][33])
    float* Bs = (float*)(buf + 16896);       // [32][128] W chunk

    const int t = threadIdx.x;
    const int b = blockIdx.x;

    // ---- reduce 8 slices for rows b*32..b*32+32 ----
    const float4* p = (const float4*)P;
#pragma unroll
    for (int j = 0; j < 4; ++j) {
        int idx = t + j * 256;                       // 0..1023 within tile
        size_t gi = (size_t)b * 1024 + idx;
        float4 z = p[gi];
#pragma unroll
        for (int s = 1; s < SPLITK; s++) {
            float4 a = p[gi + (size_t)s * 131072];
            z.x += a.x; z.y += a.y; z.z += a.z; z.w += a.w;
        }
        if (mode == 1) {
            float4 r = ((const float4*)res)[gi];
            z.x += r.x; z.y += r.y; z.z += r.z; z.w += r.w;
        }
        z.x = fmaxf(z.x, 0.0f); z.y = fmaxf(z.y, 0.0f);
        z.z = fmaxf(z.z, 0.0f); z.w = fmaxf(z.w, 0.0f);
        ((float4*)Cout)[gi] = z;
        int row = idx >> 5, c4 = idx & 31;
        float* cp = &Cs[row * 132 + c4 * 4];
        cp[0] = z.x; cp[1] = z.y; cp[2] = z.z; cp[3] = z.w;
    }
    __syncthreads();

    // ---- GEMM: Z2[32,128] = Cs[32,128] @ W[128,128] ----
    const int tr = t >> 5, tc = t & 31;      // rows tr*4.., cols tc*4..
    float acc[4][4];
#pragma unroll
    for (int r = 0; r < 4; r++)
#pragma unroll
        for (int c = 0; c < 4; c++) acc[r][c] = 0.0f;

    for (int k0 = 0; k0 < 128; k0 += 32) {
        // stage W chunk
#pragma unroll
        for (int j = 0; j < 4; ++j) {
            int f = t + j * 256;
            int kr = f >> 5, c4 = f & 31;
            *(float4*)&Bs[kr * 128 + c4 * 4] = *(const float4*)(W + (size_t)(k0 + kr) * 128 + c4 * 4);
        }
        __syncthreads();
#pragma unroll
        for (int k = 0; k < 32; ++k) {
            float av[4];
#pragma unroll
            for (int r = 0; r < 4; r++) av[r] = Cs[(tr * 4 + r) * 132 + k0 + k];
            float4 b4 = *(const float4*)&Bs[k * 128 + tc * 4];
            float bv[4] = {b4.x, b4.y, b4.z, b4.w};
#pragma unroll
            for (int r = 0; r < 4; r++)
#pragma unroll
                for (int c = 0; c < 4; c++) acc[r][c] += av[r] * bv[c];
        }
        __syncthreads();
    }

    // ---- transpose (+bias) into Cs2 (overlaps Cs; safe after barrier) ----
    float* Cs2 = (float*)buf;                // [128][33]
#pragma unroll
    for (int r = 0; r < 4; r++)
#pragma unroll
        for (int c = 0; c < 4; c++) {
            int n = tc * 4 + c;
            Cs2[n * 33 + tr * 4 + r] = acc[r][c] + bias[n];
        }
    __syncthreads();

    // ---- split + write: thread t -> n=t>>1, k-half=(t&1)*16 ----
    {
        const int n = t >> 1;
        const int kh = (t & 1) * 16;
        union { __half h[8]; uint4 u; } Hp, Lp;
        __half* oh = Bth + (size_t)n * KTOT + b * 32 + kh;
        __half* ol = Btl + (size_t)n * KTOT + b * 32 + kh;
#pragma unroll
        for (int g = 0; g < 2; g++) {
#pragma unroll
            for (int q = 0; q < 8; q++)
                split2h(Cs2[n * 33 + kh + g * 8 + q], Hp.h[q], Lp.h[q]);
            *(uint4*)(oh + g * 8) = Hp.u;
            *(uint4*)(ol + g * 8) = Lp.u;
        }
    }
}

// ---------------------------------------------------------------------------
// reduce SPLITK partials + epilogue; up to 3 outputs via grid.y.
// mode 1: relu(z+res); 3: z; 4: relu(z+res)*scale
// ---------------------------------------------------------------------------
struct RedOut {
    float* C;
    __half* Ch;
    const float* res;
    int mode;
};

__global__ __launch_bounds__(256) void reduce_ep(
    const float* __restrict__ P, const float* __restrict__ scale_p,
    RedOut o0, RedOut o1, RedOut o2)
{
    const int y = blockIdx.y;
    RedOut o = (y == 0) ? o0 : (y == 1) ? o1 : o2;

    int i = blockIdx.x * 256 + threadIdx.x;
    const float4* p = (const float4*)P + (size_t)y * SPLITK * 131072;
    float4 z = p[i];
#pragma unroll
    for (int s = 1; s < SPLITK; s++) {
        float4 a = p[i + (size_t)s * 131072];
        z.x += a.x; z.y += a.y; z.z += a.z; z.w += a.w;
    }
    if (o.mode == 1 || o.mode == 4) {
        float4 r = ((const float4*)o.res)[i];
        z.x += r.x; z.y += r.y; z.z += r.z; z.w += r.w;
    }
    if (o.mode != 3) {
        z.x = fmaxf(z.x, 0.0f); z.y = fmaxf(z.y, 0.0f);
        z.z = fmaxf(z.z, 0.0f); z.w = fmaxf(z.w, 0.0f);
    }
    if (o.mode == 4) {
        float s = *scale_p;
        z.x *= s; z.y *= s; z.z *= s; z.w *= s;
    }
    if (o.C) ((float4*)o.C)[i] = z;
    if (o.Ch) {
        union { __half b[4]; uint2 u; } H;
        H.b[0] = __float2half_rn(z.x); H.b[1] = __float2half_rn(z.y);
        H.b[2] = __float2half_rn(z.z); H.b[3] = __float2half_rn(z.w);
        ((uint2*)o.Ch)[i] = H.u;
    }
}

// ---------------------------------------------------------------------------
// G matrices: fp32 -> fp16 single. grid (16384, 2)
// ---------------------------------------------------------------------------
__global__ __launch_bounds__(256) void conv_g(
    const float* __restrict__ X0, __half* __restrict__ Y0,
    const float* __restrict__ X1, __half* __restrict__ Y1)
{
    const float* X = blockIdx.y ? X1 : X0;
    __half* Y = blockIdx.y ? Y1 : Y0;
    size_t i = (size_t)blockIdx.x * 256 + threadIdx.x;
    float4 v = ((const float4*)X)[i];
    union { __half b[4]; uint2 u; } H;
    H.b[0] = __float2half_rn(v.x); H.b[1] = __float2half_rn(v.y);
    H.b[2] = __float2half_rn(v.z); H.b[3] = __float2half_rn(v.w);
    ((uint2*)Y)[i] = H.u;
}

// 4 weight matrices: fp32 -> fp16 hi/lo. grid (48, 4), per-y element guard.
__global__ __launch_bounds__(256) void conv_w4(
    const float* __restrict__ X0, __half* __restrict__ H0, __half* __restrict__ L0,
    const float* __restrict__ X1, __half* __restrict__ H1, __half* __restrict__ L1,
    const float* __restrict__ X2, __half* __restrict__ H2, __half* __restrict__ L2,
    const float* __restrict__ X3, __half* __restrict__ H3, __half* __restrict__ L3)
{
    const int y = blockIdx.y;
    const float* X = (y == 0) ? X0 : (y == 1) ? X1 : (y == 2) ? X2 : X3;
    __half* Xh     = (y == 0) ? H0 : (y == 1) ? H1 : (y == 2) ? H2 : H3;
    __half* Xl     = (y == 0) ? L0 : (y == 1) ? L1 : (y == 2) ? L2 : L3;
    const int cnt  = (y < 2) ? 12288 : 4096;   // float4 counts
    int i = blockIdx.x * 256 + threadIdx.x;
    if (i >= cnt) return;
    float4 v = ((const float4*)X)[i];
    union { __half b[4]; uint2 u; } H, L;
    split2h(v.x, H.b[0], L.b[0]); split2h(v.y, H.b[1], L.b[1]);
    split2h(v.z, H.b[2], L.b[2]); split2h(v.w, H.b[3], L.b[3]);
    ((uint2*)Xh)[i] = H.u;
    ((uint2*)Xl)[i] = L.u;
}

// ---------------------------------------------------------------------------
// Standalone small GEMM (K=128) + transpose/split(fp16) epilogue.
// grid (128 k-tiles, 2 n-halves), block 128.
// ---------------------------------------------------------------------------
__global__ __launch_bounds__(128, 4) void gemm_smallT(
    const float* __restrict__ A,
    const float* __restrict__ B,
    const float* __restrict__ bias,
    __half* __restrict__ Bth, __half* __restrict__ Btl,
    int ro)
{
    __shared__ float As[32 * 33];
    __shared__ float Bs[32 * 64];
    __shared__ float Cs[64 * 33];
    const int t = threadIdx.x;
    const int m0 = blockIdx.x * 32;
    const int n0 = blockIdx.y * 64;
    const int tr = t >> 4, tc = t & 15;
    const int am = t >> 2, ak = (t & 3) * 8;

    float acc[4][4];
#pragma unroll
    for (int r = 0; r < 4; r++)
#pragma unroll
        for (int c = 0; c < 4; c++) acc[r][c] = 0.0f;

    const float* Ap = A + (size_t)(m0 + am) * 128 + ak;
    float4 a0, a1, bb[4];

    a0 = *(const float4*)(Ap);
    a1 = *(const float4*)(Ap + 4);
#pragma unroll
    for (int j = 0; j < 4; j++) {
        int f = t + j * 128;
        bb[j] = *(const float4*)(B + (size_t)(f >> 4) * 128 + n0 + (f & 15) * 4);
    }
    As[(ak + 0) * 33 + am] = a0.x; As[(ak + 1) * 33 + am] = a0.y;
    As[(ak + 2) * 33 + am] = a0.z; As[(ak + 3) * 33 + am] = a0.w;
    As[(ak + 4) * 33 + am] = a1.x; As[(ak + 5) * 33 + am] = a1.y;
    As[(ak + 6) * 33 + am] = a1.z; As[(ak + 7) * 33 + am] = a1.w;
#pragma unroll
    for (int j = 0; j < 4; j++) {
        int f = t + j * 128;
        *(float4*)&Bs[(f >> 4) * 64 + (f & 15) * 4] = bb[j];
    }
    __syncthreads();

    for (int it = 1; it <= 4; ++it) {
        if (it < 4) {
            int k0 = it << 5;
            a0 = *(const float4*)(Ap + k0);
            a1 = *(const float4*)(Ap + k0 + 4);
#pragma unroll
            for (int j = 0; j < 4; j++) {
                int f = t + j * 128;
                bb[j] = *(const float4*)(B + (size_t)(k0 + (f >> 4)) * 128 + n0 + (f & 15) * 4);
            }
        }
#pragma unroll
        for (int k = 0; k < 32; ++k) {
            float av[4];
#pragma unroll
            for (int r = 0; r < 4; r++) av[r] = As[k * 33 + tr * 4 + r];
            float4 b0 = *(const float4*)&Bs[k * 64 + tc * 4];
            float bv[4] = {b0.x, b0.y, b0.z, b0.w};
#pragma unroll
            for (int r = 0; r < 4; r++)
#pragma unroll
                for (int c = 0; c < 4; c++) acc[r][c] += av[r] * bv[c];
        }
        __syncthreads();
        if (it < 4) {
            As[(ak + 0) * 33 + am] = a0.x; As[(ak + 1) * 33 + am] = a0.y;
            As[(ak + 2) * 33 + am] = a0.z; As[(ak + 3) * 33 + am] = a0.w;
            As[(ak + 4) * 33 + am] = a1.x; As[(ak + 5) * 33 + am] = a1.y;
            As[(ak + 6) * 33 + am] = a1.z; As[(ak + 7) * 33 + am] = a1.w;
#pragma unroll
            for (int j = 0; j < 4; j++) {
                int f = t + j * 128;
                *(float4*)&Bs[(f >> 4) * 64 + (f & 15) * 4] = bb[j];
            }
            __syncthreads();
        }
    }

#pragma unroll
    for (int r = 0; r < 4; r++)
#pragma unroll
        for (int c = 0; c < 4; c++) {
            int n = tc * 4 + c;
            Cs[n * 33 + tr * 4 + r] = acc[r][c] + bias[n0 + n];
        }
    __syncthreads();

    {
        const int n = t >> 1;
        const int kh = (t & 1) * 16;
        union { __half b[8]; uint4 u; } Hp, Lp;
        __half* oh = Bth + (size_t)(ro + n0 + n) * KTOT + m0 + kh;
        __half* ol = Btl + (size_t)(ro + n0 + n) * KTOT + m0 + kh;
#pragma unroll
        for (int g = 0; g < 2; g++) {
#pragma unroll
            for (int q = 0; q < 8; q++)
                split2h(Cs[n * 33 + kh + g * 8 + q], Hp.b[q], Lp.b[q]);
            *(uint4*)(oh + g * 8) = Hp.u;
            *(uint4*)(ol + g * 8) = Lp.u;
        }
    }
}

// ---------------------------------------------------------------------------
// Mixup, emitting fp16 single (consumed as A by hmma_nt128).
// ---------------------------------------------------------------------------
__global__ void mix_kernel(const float* __restrict__ a1, const float* __restrict__ a3,
                           const int* __restrict__ perm, const float* __restrict__ lam,
                           __half* __restrict__ m1h, __half* __restrict__ m3h)
{
    int i = blockIdx.x * blockDim.x + threadIdx.x;
    int row = i >> 5, q = i & 31;
    float l = lam[0], il = 1.0f - l;
    int pr = perm[row];
    union { __half b[4]; uint2 u; } H;

    float4 x = ((const float4*)a1)[row * 32 + q];
    float4 y = ((const float4*)a1)[pr * 32 + q];
    H.b[0] = __float2half_rn(l * x.x + il * y.x);
    H.b[1] = __float2half_rn(l * x.y + il * y.y);
    H.b[2] = __float2half_rn(l * x.z + il * y.z);
    H.b[3] = __float2half_rn(l * x.w + il * y.w);
    ((uint2*)m1h)[row * 32 + q] = H.u;

    x = ((const float4*)a3)[row * 32 + q];
    y = ((const float4*)a3)[pr * 32 + q];
    H.b[0] = __float2half_rn(l * x.x + il * y.x);
    H.b[1] = __float2half_rn(l * x.y + il * y.y);
    H.b[2] = __float2half_rn(l * x.z + il * y.z);
    H.b[3] = __float2half_rn(l * x.w + il * y.w);
    ((uint2*)m3h)[row * 32 + q] = H.u;
}

// attention; emits om as fp16 single (A operand of the Wo HMMA)
__global__ void attn_kernel(const float* __restrict__ qkv0, const float* __restrict__ qkv1,
                            __half* __restrict__ om_h, int nh)
{
    int gt = blockIdx.x * blockDim.x + threadIdx.x;
    int node = gt >> 5;
    int lane = gt & 31;
    const float4* p0 = (const float4*)(qkv0 + (size_t)node * 384);
    const float4* p1 = (const float4*)(qkv1 + (size_t)node * 384);
    float4 q0 = p0[lane], k0 = p0[32 + lane], v0 = p0[64 + lane];
    float4 q1 = p1[lane], k1 = p1[32 + lane], v1 = p1[64 + lane];

    float p00 = q0.x * k0.x + q0.y * k0.y + q0.z * k0.z + q0.w * k0.w;
    float p01 = q0.x * k1.x + q0.y * k1.y + q0.z * k1.z + q0.w * k1.w;
    float p10 = q1.x * k0.x + q1.y * k0.y + q1.z * k0.z + q1.w * k0.w;
    float p11 = q1.x * k1.x + q1.y * k1.y + q1.z * k1.z + q1.w * k1.w;

    int hd = 128 / nh;
    int Wd = hd >> 2;
    for (int off = Wd >> 1; off; off >>= 1) {
        p00 += __shfl_xor_sync(0xffffffffu, p00, off);
        p01 += __shfl_xor_sync(0xffffffffu, p01, off);
        p10 += __shfl_xor_sync(0xffffffffu, p10, off);
        p11 += __shfl_xor_sync(0xffffffffu, p11, off);
    }
    float scl = rsqrtf((float)hd);
    float s00 = p00 * scl, s01 = p01 * scl, s10 = p10 * scl, s11 = p11 * scl;

    float mx0 = fmaxf(s00, s01);
    float e00 = expf(s00 - mx0), e01 = expf(s01 - mx0);
    float r0 = 1.0f / (e00 + e01);
    float mx1 = fmaxf(s10, s11);
    float e10 = expf(s10 - mx1), e11 = expf(s11 - mx1);
    float r1 = 1.0f / (e10 + e11);

    float c0 = 0.5f * (e00 * r0 + e10 * r1);
    float c1 = 0.5f * (e01 * r0 + e11 * r1);

    float ox = c0 * v0.x + c1 * v1.x;
    float oy = c0 * v0.y + c1 * v1.y;
    float oz = c0 * v0.z + c1 * v1.z;
    float ow = c0 * v0.w + c1 * v1.w;
    union { __half b[4]; uint2 u; } H;
    H.b[0] = __float2half_rn(ox); H.b[1] = __float2half_rn(oy);
    H.b[2] = __float2half_rn(oz); H.b[3] = __float2half_rn(ow);
    ((uint2*)(om_h + (size_t)node * 128))[lane] = H.u;
}

__global__ __launch_bounds__(256) void edge_kernel(
    const float* __restrict__ h3, const int* __restrict__ ei,
    const float* __restrict__ Wc, const float* __restrict__ bc,
    float* __restrict__ out)
{
    __shared__ float wcs[512];
    __shared__ float bcs[2];
    int t = threadIdx.x;
    for (int i = t; i < 512; i += 256) wcs[i] = Wc[i];
    if (t < 2) bcs[t] = bc[t];
    __syncthreads();

    int e = blockIdx.x * 256 + t;
    int i0 = ei[e], i1 = ei[N_EDGES + e];
    const float4* r0 = (const float4*)(h3 + (size_t)i0 * 128);
    const float4* r1 = (const float4*)(h3 + (size_t)i1 * 128);
    float acc0 = bcs[0], acc1 = bcs[1];
#pragma unroll 8
    for (int q = 0; q < 32; q++) {
        float4 f = r0[q];
        int d = q * 4;
        acc0 += f.x * wcs[2 * d] + f.y * wcs[2 * (d + 1)] + f.z * wcs[2 * (d + 2)] + f.w * wcs[2 * (d + 3)];
        acc1 += f.x * wcs[2 * d + 1] + f.y * wcs[2 * (d + 1) + 1] + f.z * wcs[2 * (d + 2) + 1] + f.w * wcs[2 * (d + 3) + 1];
    }
#pragma unroll 8
    for (int q = 0; q < 32; q++) {
        float4 f = r1[q];
        int d = 128 + q * 4;
        acc0 += f.x * wcs[2 * d] + f.y * wcs[2 * (d + 1)] + f.z * wcs[2 * (d + 2)] + f.w * wcs[2 * (d + 3)];
        acc1 += f.x * wcs[2 * d + 1] + f.y * wcs[2 * (d + 1) + 1] + f.z * wcs[2 * (d + 2) + 1] + f.w * wcs[2 * (d + 3) + 1];
    }
    out[(size_t)e * 2]     = acc0;
    out[(size_t)e * 2 + 1] = acc1;
}

// ---------------------------------------------------------------------------
extern "C" void kernel_launch(void* const* d_in, const int* in_sizes, int n_in,
                              void* d_out, int out_size)
{
    const float* x    = (const float*)d_in[0];
    const float* G1   = (const float*)d_in[1];
    const float* G3   = (const float*)d_in[2];
    const int*   ei   = (const int*)d_in[3];
    const int*   perm = (const int*)d_in[4];
    const float* lam  = (const float*)d_in[5];
    const float* beta = (const float*)d_in[6];
    const float* W1 = (const float*)d_in[7];   const float* b1 = (const float*)d_in[8];
    const float* W2 = (const float*)d_in[9];   const float* b2 = (const float*)d_in[10];
    const float* W3 = (const float*)d_in[11];  const float* b3 = (const float*)d_in[12];
    const float* W1h = (const float*)d_in[13]; const float* b1h = (const float*)d_in[14];
    const float* W3h = (const float*)d_in[15]; const float* b3h = (const float*)d_in[16];
    const float* W2m = (const float*)d_in[17]; const float* b2m = (const float*)d_in[18];
    const float* W3m = (const float*)d_in[19]; const float* b3m = (const float*)d_in[20];
    const float* Wqkv_mix = (const float*)d_in[21]; const float* bqkv_mix = (const float*)d_in[22];
    const float* Wo_mix   = (const float*)d_in[23]; const float* bo_mix   = (const float*)d_in[24];
    const float* Wqkv_fus = (const float*)d_in[25]; const float* bqkv_fus = (const float*)d_in[26];
    const float* Wo_fus   = (const float*)d_in[27]; const float* bo_fus   = (const float*)d_in[28];
    const float* Wc = (const float*)d_in[29];  const float* bc = (const float*)d_in[30];

    float *h1, *h2, *a1, *a3, *qkv0, *qkv1, *hmix, *h2m, *h3;
    float* part;
    __half *G1h, *G3h, *Bth, *Btl, *fA, *fB, *fC;
    __half *whm, *wlm, *whf, *wlf, *wohm, *wolm, *wohf, *wolf;
    cudaGetSymbolAddress((void**)&h1, g_h1);
    cudaGetSymbolAddress((void**)&h2, g_h2);
    cudaGetSymbolAddress((void**)&a1, g_a1);
    cudaGetSymbolAddress((void**)&a3, g_a3);
    cudaGetSymbolAddress((void**)&qkv0, g_qkv0);
    cudaGetSymbolAddress((void**)&qkv1, g_qkv1);
    cudaGetSymbolAddress((void**)&hmix, g_hmix);
    cudaGetSymbolAddress((void**)&h2m, g_h2m);
    cudaGetSymbolAddress((void**)&h3, g_h3);
    cudaGetSymbolAddress((void**)&part, g_part);
    cudaGetSymbolAddress((void**)&G1h, g_G1h);
    cudaGetSymbolAddress((void**)&G3h, g_G3h);
    cudaGetSymbolAddress((void**)&Bth, g_Bth);
    cudaGetSymbolAddress((void**)&Btl, g_Btl);
    cudaGetSymbolAddress((void**)&fA, g_fA);
    cudaGetSymbolAddress((void**)&fB, g_fB);
    cudaGetSymbolAddress((void**)&fC, g_fC);
    cudaGetSymbolAddress((void**)&whm, g_whm);
    cudaGetSymbolAddress((void**)&wlm, g_wlm);
    cudaGetSymbolAddress((void**)&whf, g_whf);
    cudaGetSymbolAddress((void**)&wlf, g_wlf);
    cudaGetSymbolAddress((void**)&wohm, g_wohm);
    cudaGetSymbolAddress((void**)&wolm, g_wolm);
    cudaGetSymbolAddress((void**)&wohf, g_wohf);
    cudaGetSymbolAddress((void**)&wolf, g_wolf);

    cudaFuncSetAttribute(gemm_mma, cudaFuncAttributeMaxDynamicSharedMemorySize, GEMM_SMEM);
    cudaFuncSetAttribute(hmma_nt128, cudaFuncAttributeMaxDynamicSharedMemorySize, NT_SMEM);

    float* out_edge = (float*)d_out;
    float* out_h3   = out_edge + (size_t)N_EDGES * 2;

    const RedOut RO_NONE = {nullptr, nullptr, nullptr, 3};

    // weight conversions
    conv_g<<<dim3(16384, 2), 256>>>(G1, G1h, G3, G3h);
    conv_w4<<<dim3(48, 4), 256>>>(Wqkv_mix, whm, wlm, Wqkv_fus, whf, wlf,
                                  Wo_mix, wohm, wolm, Wo_fus, wohf, wolf);

    // ---- h1 = relu(G1 @ (x@W1+b1)); fused: + t2 = h1@W2+b2 -> Bt ----
    gemm_smallT<<<dim3(128, 2), 128>>>(x, W1, b1, Bth, Btl, 0);
    gemm_mma<<<dim3(32, SPLITK, 1), 256, GEMM_SMEM>>>(G1h, G3h, Bth, Btl, part);
    reduce_small<<<128, 256>>>(part, nullptr, 0, h1, W2, b2, Bth, Btl);

    // ---- h2-pass; fused: h2 + t3 = h2@W3+b3 -> Bt rows 0..127 ----
    gemm_mma<<<dim3(32, SPLITK, 1), 256, GEMM_SMEM>>>(G1h, G3h, Bth, Btl, part);
    reduce_small<<<128, 256>>>(part, h1, 1, h2, W3, b3, Bth, Btl);

    // u1h, u3h from h1 -> Bt rows 128.. / 256..
    gemm_smallT<<<dim3(128, 2), 128>>>(h1, W1h, b1h, Bth, Btl, 128);
    gemm_smallT<<<dim3(128, 2), 128>>>(h1, W3h, b3h, Bth, Btl, 256);

    // ---- merged pass: z0 h3c1(fp16 fA), z1 a1, z2 a3 ----
    gemm_mma<<<dim3(32, SPLITK, 3), 256, GEMM_SMEM>>>(G1h, G3h, Bth, Btl, part);
    { RedOut o0 = {nullptr, fA, h2, 1};
      RedOut o1 = {a1, nullptr, nullptr, 3};
      RedOut o2 = {a3, nullptr, nullptr, 3};
      reduce_ep<<<dim3(512, 3), 256>>>(part, nullptr, o0, o1, o2); }

    // ---- mixup + MHA mix (nh=2), all HMMA ----
    mix_kernel<<<512, 256>>>(a1, a3, perm, lam, fB, fC);
    hmma_nt128<<<dim3(32, 3, 2), 256, NT_SMEM>>>(fB, fC, whm, wlm,
                                                 bqkv_mix, qkv0, qkv1, nullptr, 384);
    attn_kernel<<<512, 256>>>(qkv0, qkv1, fC, 2);
    hmma_nt128<<<dim3(32, 1, 1), 256, NT_SMEM>>>(fC, nullptr, wohm, wolm,
                                                 bo_mix, hmix, nullptr, nullptr, 128);

    // ---- h2m-pass; fused: h2m + t3m = h2m@W3m+b3m -> Bt ----
    gemm_smallT<<<dim3(128, 2), 128>>>(hmix, W2m, b2m, Bth, Btl, 0);
    gemm_mma<<<dim3(32, SPLITK, 1), 256, GEMM_SMEM>>>(G1h, G3h, Bth, Btl, part);
    reduce_small<<<128, 256>>>(part, hmix, 1, h2m, W3m, b3m, Bth, Btl);

    // ---- h3c2 = relu(G1@t3m + h2m)*beta -> fp16 fB ----
    gemm_mma<<<dim3(32, SPLITK, 1), 256, GEMM_SMEM>>>(G1h, G3h, Bth, Btl, part);
    { RedOut o = {nullptr, fB, h2m, 4};
      reduce_ep<<<dim3(512, 1), 256>>>(part, beta, o, RO_NONE, RO_NONE); }

    // ---- MHA fus (nh=4), all HMMA ----
    hmma_nt128<<<dim3(32, 3, 2), 256, NT_SMEM>>>(fA, fB, whf, wlf,
                                                 bqkv_fus, qkv0, qkv1, nullptr, 384);
    attn_kernel<<<512, 256>>>(qkv0, qkv1, fC, 4);
    hmma_nt128<<<dim3(32, 1, 1), 256, NT_SMEM>>>(fC, nullptr, wohf, wolf,
                                                 bo_fus, h3, nullptr, out_h3, 128);

    // ---- edge classifier ----
    edge_kernel<<<512, 256>>>(h3, ei, Wc, bc, out_edge);
}